// round 1
// baseline (speedup 1.0000x reference)
#include <cuda_runtime.h>
#include <math.h>

// ---------------------------------------------------------------------------
// S2ConvNet forward pass, sm_103a.
// Shapes: B=16, F1=32, F2=64, B0=32, B1=16, B2=8, M1=31, M2=15.
// Inputs (metadata order):
//  0 x[16,1,64,64] 1 w1r[1,32,16,31] 2 w1i 3 w2r[32,64,8,15,15] 4 w2i
//  5 conv3_w[10,1,8] 6 conv3_b[10] 7 bn_gamma[10] 8 bn_beta[10]
//  9 fc_w[10,570] 10 fc_b[10]   -> out[16,10] f32
// ---------------------------------------------------------------------------

#define PI_D 3.141592653589793238462643383279502884

// ------------------------- static device scratch ---------------------------
__device__ float  g_D1F[16 * 64 * 31];            // [l][j][m]
__device__ float  g_D1I[16 * 32 * 31 * 31];       // [l][j][m][n]
__device__ float  g_D2F[8 * 32 * 15 * 15];        // [l][j][m][k]
__device__ float  g_D2I0[8 * 15 * 15];            // [l][m][n]  (j=0 slice)
__device__ float2 g_xh[16 * 16 * 31];             // [b][l][m]
__device__ float2 g_xmn[16 * 32 * 32 * 225];      // [b][c][j][m][k]
__device__ float2 g_xh2[16 * 32 * 8 * 225];       // [b][c][l][m][k] (K=57600/b)
__device__ float2 g_H[64 * 32 * 8 * 225];         // [f][c][l][m][k]
__device__ float  g_partial[16 * 8 * 128];        // [ks][ft][tid]
__device__ float  g_feat[16 * 64];                // relu'd layer-2 output

// ------------------------- Wigner-d table math (fp64) ----------------------
__device__ __forceinline__ double lf_d(int n) { return lgamma((double)n + 1.0); }

__device__ double wig_d(int l, int m, int n, double beta) {
    int kmin = max(0, m - n);
    int kmax = min(l + m, l - n);
    if (kmax < kmin) return 0.0;
    double cb = cos(beta * 0.5), sb = sin(beta * 0.5);
    double lcb = log(cb), lsb = log(sb);
    double pref = 0.5 * (lf_d(l + m) + lf_d(l - m) + lf_d(l + n) + lf_d(l - n));
    int a0 = 2 * l + m - n - 2 * kmin;
    int b0 = n - m + 2 * kmin;
    double t = exp(pref - lf_d(kmin) - lf_d(l + m - kmin) - lf_d(l - n - kmin)
                   - lf_d(n - m + kmin) + (double)a0 * lcb + (double)b0 * lsb);
    if (kmin & 1) t = -t;
    double tansq = (sb * sb) / (cb * cb);
    double sum = t;
    for (int k = kmin; k < kmax; ++k) {
        t *= -((double)((l + m - k) * (l - n - k)) /
               (double)((k + 1) * (n - m + k + 1))) * tansq;
        sum += t;
    }
    return sum;
}

__device__ double quadw_d(int b, double beta) {
    double s = 0.0;
    for (int k = 0; k < b; ++k)
        s += sin((2.0 * k + 1.0) * beta) / (2.0 * k + 1.0);
    return (2.0 / (double)b) * sin(beta) * s;
}

// ------------------------- table kernels -----------------------------------
__global__ void t_d1f() {
    int idx = blockIdx.x * blockDim.x + threadIdx.x;
    if (idx >= 16 * 64 * 31) return;
    int l = idx / (64 * 31);
    int j = (idx / 31) % 64;
    int m = idx % 31;
    int mt = m - 15;
    float v = 0.f;
    if (abs(mt) <= l) {
        double beta = PI_D * (2.0 * j + 1.0) / 128.0;
        v = (float)(quadw_d(32, beta) * wig_d(l, mt, 0, beta));
    }
    g_D1F[idx] = v;
}

__global__ void t_d1i() {
    int idx = blockIdx.x * blockDim.x + threadIdx.x;
    if (idx >= 16 * 32 * 31 * 31) return;
    int l = idx / 30752;
    int j = (idx / 961) % 32;
    int m = (idx / 31) % 31;
    int n = idx % 31;
    int mt = m - 15, nt = n - 15;
    float v = 0.f;
    if (abs(mt) <= l && abs(nt) <= l) {
        double beta = PI_D * (2.0 * j + 1.0) / 64.0;
        v = (float)((2.0 * l + 1.0) * wig_d(l, mt, nt, beta));
    }
    g_D1I[idx] = v;
}

__global__ void t_d2f() {
    int idx = blockIdx.x * blockDim.x + threadIdx.x;
    if (idx >= 8 * 32 * 15 * 15) return;
    int l = idx / (32 * 225);
    int j = (idx / 225) % 32;
    int m = (idx / 15) % 15;
    int n = idx % 15;
    int mt = m - 7, nt = n - 7;
    float v = 0.f;
    if (abs(mt) <= l && abs(nt) <= l) {
        double beta = PI_D * (2.0 * j + 1.0) / 64.0;
        v = (float)(quadw_d(16, beta) * wig_d(l, mt, nt, beta));
    }
    g_D2F[idx] = v;
}

__global__ void t_d2i0() {
    int idx = blockIdx.x * blockDim.x + threadIdx.x;
    if (idx >= 8 * 15 * 15) return;
    int l = idx / 225;
    int m = (idx / 15) % 15;
    int n = idx % 15;
    int mt = m - 7, nt = n - 7;
    float v = 0.f;
    if (abs(mt) <= l && abs(nt) <= l) {
        double beta = PI_D / 32.0;   // beta2[0]
        v = (float)((2.0 * l + 1.0) * wig_d(l, mt, nt, beta));
    }
    g_D2I0[idx] = v;
}

// ------------------------- stage A: x -> xh --------------------------------
// block per (b, m): DFT over t (64), then contract j with D1F.
__global__ void k_xh(const float* __restrict__ x) {
    __shared__ float2 s_tw[64];
    __shared__ float2 s_xm[64];
    int b = blockIdx.x / 31;
    int m = blockIdx.x % 31;
    int mt = m - 15;
    int j = threadIdx.x;   // 64 threads

    float sj, cj;
    __sincosf((float)j * (6.2831853071795864769f / 64.f), &sj, &cj);
    s_tw[j] = make_float2(cj, sj);
    __syncthreads();

    const float* xr = x + (size_t)(b * 64 + j) * 64;
    float accx = 0.f, accy = 0.f;
#pragma unroll 8
    for (int t = 0; t < 64; ++t) {
        unsigned r = ((unsigned)(mt * t)) & 63u;
        float2 e = s_tw[r];
        float v = xr[t];
        accx += v * e.x;      // e^{-i theta}
        accy -= v * e.y;
    }
    s_xm[j] = make_float2(accx, accy);
    __syncthreads();

    if (j < 16) {
        int l = j;
        float ax = 0.f, ay = 0.f;
        const float* dp = g_D1F + (size_t)l * 64 * 31 + m;
#pragma unroll 8
        for (int jj = 0; jj < 64; ++jj) {
            float d = dp[jj * 31];
            float2 v = s_xm[jj];
            ax += d * v.x;
            ay += d * v.y;
        }
        g_xh[(b * 16 + l) * 31 + m] = make_float2(ax, ay);
    }
}

// ------------------------- stage B+C fused plane kernel --------------------
// block per (b, f, j): f[m,n] -> inv 2D transform -> relu -> fwd 2D subset
__global__ __launch_bounds__(256) void k_main(const float* __restrict__ w1r,
                                              const float* __restrict__ w1i) {
    __shared__ float2 s_xh[16 * 31];
    __shared__ float2 s_w1[16 * 31];
    __shared__ float2 s_f[31 * 31];
    __shared__ float2 s_g[31 * 32];
    __shared__ float  s_r[32 * 32];
    __shared__ float2 s_u[32 * 15];
    __shared__ float2 s_tw[32];

    int bx = blockIdx.x;
    int b = bx >> 10;
    int f = (bx >> 5) & 31;
    int j = bx & 31;
    int tid = threadIdx.x;

    if (tid < 32) {
        float s, c;
        __sincosf((float)tid * (6.2831853071795864769f / 32.f), &s, &c);
        s_tw[tid] = make_float2(c, s);
    }
    for (int i = tid; i < 496; i += 256) {
        s_xh[i] = g_xh[b * 496 + i];
        s_w1[i] = make_float2(w1r[f * 496 + i], w1i[f * 496 + i]);
    }
    __syncthreads();

    // step 1: f[m,n] = sum_l D1I[l,j,m,n] * xh[l,m] * conj(w1[l,n])
    for (int idx = tid; idx < 961; idx += 256) {
        int m = idx / 31, n = idx % 31;
        int l0 = max(abs(m - 15), abs(n - 15));
        float ax = 0.f, ay = 0.f;
        const float* dp = g_D1I + (size_t)j * 961 + m * 31 + n;
        for (int l = l0; l < 16; ++l) {
            float d = dp[(size_t)l * 30752];
            float2 a = s_xh[l * 31 + m];
            float2 w = s_w1[l * 31 + n];
            float tr = a.x * w.x + a.y * w.y;    // a * conj(w)
            float ti = a.y * w.x - a.x * w.y;
            ax += d * tr;
            ay += d * ti;
        }
        s_f[idx] = make_float2(ax, ay);
    }
    __syncthreads();

    // step 2: g[m,q] = sum_n f[m,n] e^{+2pi i n~ q / 32}
    for (int idx = tid; idx < 992; idx += 256) {
        int m = idx >> 5, q = idx & 31;
        float ax = 0.f, ay = 0.f;
#pragma unroll
        for (int n = 0; n < 31; ++n) {
            unsigned r = ((unsigned)((n - 15) * q)) & 31u;
            float2 e = s_tw[r];
            float2 fv = s_f[m * 31 + n];
            ax += fv.x * e.x - fv.y * e.y;
            ay += fv.x * e.y + fv.y * e.x;
        }
        s_g[m * 32 + q] = make_float2(ax, ay);
    }
    __syncthreads();

    // step 3: r[p,q] = relu(Re sum_m e^{+2pi i m~ p/32} g[m,q])
    {
        int idx = tid;
#pragma unroll
        for (int rep = 0; rep < 4; ++rep, idx += 256) {
            int p = idx >> 5, q = idx & 31;
            float s = 0.f;
#pragma unroll
            for (int m = 0; m < 31; ++m) {
                unsigned r = ((unsigned)((m - 15) * p)) & 31u;
                float2 e = s_tw[r];
                float2 g = s_g[m * 32 + q];
                s += e.x * g.x - e.y * g.y;
            }
            s_r[idx] = fmaxf(s, 0.f);
        }
    }
    __syncthreads();

    // step 4: u[p,n2] = sum_q r[p,q] e^{-2pi i n~ q/32}
    for (int idx = tid; idx < 480; idx += 256) {
        int p = idx / 15, n2 = idx % 15;
        int nt = n2 - 7;
        float ax = 0.f, ay = 0.f;
#pragma unroll
        for (int q = 0; q < 32; ++q) {
            unsigned r = ((unsigned)(nt * q)) & 31u;
            float2 e = s_tw[r];
            float v = s_r[p * 32 + q];
            ax += v * e.x;
            ay -= v * e.y;
        }
        s_u[p * 15 + n2] = make_float2(ax, ay);
    }
    __syncthreads();

    // step 5: xmn[m2,n2] = sum_p e^{-2pi i m~ p/32} u[p,n2]
    if (tid < 225) {
        int m2 = tid / 15, n2 = tid % 15;
        int mt = m2 - 7;
        float ax = 0.f, ay = 0.f;
#pragma unroll
        for (int p = 0; p < 32; ++p) {
            unsigned r = ((unsigned)(mt * p)) & 31u;
            float2 e = s_tw[r];   // use conj(e)
            float2 u = s_u[p * 15 + n2];
            ax += u.x * e.x + u.y * e.y;
            ay += u.y * e.x - u.x * e.y;
        }
        g_xmn[(size_t)bx * 225 + tid] = make_float2(ax, ay);
    }
}

// ------------------------- stage D: xh2 ------------------------------------
__global__ void k_xh2() {
    int idx = blockIdx.x * blockDim.x + threadIdx.x;  // 921600
    int b = idx / 57600;
    int c = (idx / 1800) % 32;
    int l = (idx / 225) % 8;
    int mk = idx % 225;
    int m = mk / 15, k = mk % 15;
    if (max(abs(m - 7), abs(k - 7)) > l) {
        g_xh2[idx] = make_float2(0.f, 0.f);
        return;
    }
    const float2* xp = g_xmn + (size_t)(b * 32 + c) * 32 * 225 + mk;
    const float* dp = g_D2F + (size_t)l * 32 * 225 + mk;
    float ax = 0.f, ay = 0.f;
#pragma unroll 8
    for (int j = 0; j < 32; ++j) {
        float d = dp[j * 225];
        float2 v = xp[(size_t)j * 225];
        ax += d * v.x;
        ay += d * v.y;
    }
    g_xh2[idx] = make_float2(ax, ay);
}

// ------------------------- H precontraction --------------------------------
// H[f,c,l,m,k] = (sum_n D2I0[l,m,n]*w2r[c,f,l,n,k], sum_n D2I0*w2i)
// so that Re(X * D2I0 * conj(w2)) == X.x*H.x + X.y*H.y
__global__ void k_H(const float* __restrict__ w2r, const float* __restrict__ w2i) {
    int idx = blockIdx.x * blockDim.x + threadIdx.x;  // 3686400
    int f = idx / (32 * 1800);
    int c = (idx / 1800) % 32;
    int l = (idx / 225) % 8;
    int m = (idx / 15) % 15;
    int k = idx % 15;
    if (abs(m - 7) > l) {
        g_H[idx] = make_float2(0.f, 0.f);
        return;
    }
    const float* dp = g_D2I0 + l * 225 + m * 15;
    size_t wbase = (size_t)((c * 64 + f) * 8 + l) * 225 + k;
    float ax = 0.f, ay = 0.f;
    for (int n = 7 - l; n <= 7 + l; ++n) {
        float d = dp[n];
        ax += d * w2r[wbase + n * 15];
        ay += d * w2i[wbase + n * 15];
    }
    g_H[idx] = make_float2(ax, ay);
}

// ------------------------- tiny GEMM out_feat ------------------------------
__global__ void k_dot() {
    int ks = blockIdx.x;      // 16 k-splits of 3600
    int ft = blockIdx.y;      // 8 f-tiles of 8
    int tid = threadIdx.x;    // 128
    int b = tid >> 3;
    int fl = tid & 7;
    int f = ft * 8 + fl;
    const float2* X = g_xh2 + (size_t)b * 57600 + ks * 3600;
    const float2* Hp = g_H + (size_t)f * 57600 + ks * 3600;
    float a0 = 0.f, a1 = 0.f, a2 = 0.f, a3 = 0.f;
#pragma unroll 4
    for (int kk = 0; kk < 3600; kk += 4) {
        float2 x0 = X[kk], h0 = Hp[kk];
        float2 x1 = X[kk + 1], h1 = Hp[kk + 1];
        float2 x2 = X[kk + 2], h2 = Hp[kk + 2];
        float2 x3 = X[kk + 3], h3 = Hp[kk + 3];
        a0 += x0.x * h0.x + x0.y * h0.y;
        a1 += x1.x * h1.x + x1.y * h1.y;
        a2 += x2.x * h2.x + x2.y * h2.y;
        a3 += x3.x * h3.x + x3.y * h3.y;
    }
    g_partial[(ks * 8 + ft) * 128 + tid] = (a0 + a1) + (a2 + a3);
}

__global__ void k_dotred() {
    int tid = threadIdx.x;    // 1024
    int b = tid >> 6;
    int f = tid & 63;
    int ft = f >> 3, fl = f & 7;
    float s = 0.f;
#pragma unroll
    for (int ks = 0; ks < 16; ++ks)
        s += g_partial[(ks * 8 + ft) * 128 + (b << 3) + fl];
    g_feat[b * 64 + f] = fmaxf(s, 0.f);
}

// ------------------------- head: conv1d + BN + FC --------------------------
__global__ void k_head(const float* __restrict__ w3, const float* __restrict__ b3,
                       const float* __restrict__ gam, const float* __restrict__ bet,
                       const float* __restrict__ fcw, const float* __restrict__ fcb,
                       float* __restrict__ out) {
    __shared__ float s_r3[16 * 570];
    __shared__ float s_mu[10], s_rstd[10];
    int tid = threadIdx.x;    // 256

    for (int idx = tid; idx < 9120; idx += 256) {
        int b = idx / 570;
        int r = idx % 570;
        int o = r / 57, t = r % 57;
        float s = b3[o];
#pragma unroll
        for (int k = 0; k < 8; ++k)
            s += w3[o * 8 + k] * g_feat[b * 64 + t + k];
        s_r3[idx] = fmaxf(s, 0.f);
    }
    __syncthreads();

    if (tid < 10) {
        int o = tid;
        float sum = 0.f;
        for (int b = 0; b < 16; ++b)
            for (int t = 0; t < 57; ++t)
                sum += s_r3[b * 570 + o * 57 + t];
        float mu = sum / 912.f;
        float v = 0.f;
        for (int b = 0; b < 16; ++b)
            for (int t = 0; t < 57; ++t) {
                float d = s_r3[b * 570 + o * 57 + t] - mu;
                v += d * d;
            }
        s_mu[o] = mu;
        s_rstd[o] = rsqrtf(v / 912.f + 1e-5f);
    }
    __syncthreads();

    for (int idx = tid; idx < 9120; idx += 256) {
        int o = (idx % 570) / 57;
        s_r3[idx] = gam[o] * (s_r3[idx] - s_mu[o]) * s_rstd[o] + bet[o];
    }
    __syncthreads();

    if (tid < 160) {
        int b = tid / 10, i = tid % 10;
        float s = fcb[i];
        const float* wr = fcw + i * 570;
        const float* xr = s_r3 + b * 570;
        for (int z = 0; z < 570; ++z) s += xr[z] * wr[z];
        out[b * 10 + i] = s;
    }
}

// ---------------------------------------------------------------------------
extern "C" void kernel_launch(void* const* d_in, const int* in_sizes, int n_in,
                              void* d_out, int out_size) {
    const float* x   = (const float*)d_in[0];
    const float* w1r = (const float*)d_in[1];
    const float* w1i = (const float*)d_in[2];
    const float* w2r = (const float*)d_in[3];
    const float* w2i = (const float*)d_in[4];
    const float* c3w = (const float*)d_in[5];
    const float* c3b = (const float*)d_in[6];
    const float* bng = (const float*)d_in[7];
    const float* bnb = (const float*)d_in[8];
    const float* fcw = (const float*)d_in[9];
    const float* fcb = (const float*)d_in[10];
    float* out = (float*)d_out;

    // Wigner tables (recomputed every call — module constants in the reference)
    t_d1f<<<(16 * 64 * 31 + 127) / 128, 128>>>();
    t_d1i<<<(16 * 32 * 31 * 31 + 127) / 128, 128>>>();
    t_d2f<<<(8 * 32 * 15 * 15 + 127) / 128, 128>>>();
    t_d2i0<<<(8 * 15 * 15 + 127) / 128, 128>>>();

    k_xh<<<16 * 31, 64>>>(x);
    k_main<<<16 * 32 * 32, 256>>>(w1r, w1i);
    k_xh2<<<921600 / 256, 256>>>();
    k_H<<<3686400 / 256, 256>>>(w2r, w2i);
    k_dot<<<dim3(16, 8), 128>>>();
    k_dotred<<<1, 1024>>>();
    k_head<<<1, 256>>>(c3w, c3b, bng, bnb, fcw, fcb, out);
}

// round 2
// speedup vs baseline: 1.5741x; 1.5741x over previous
#include <cuda_runtime.h>
#include <math.h>

// ---------------------------------------------------------------------------
// S2ConvNet forward pass, sm_103a.
// Shapes: B=16, F1=32, F2=64, B0=32, B1=16, B2=8, M1=31, M2=15.
// ---------------------------------------------------------------------------

#define PI_D 3.141592653589793238462643383279502884

// ------------------------- static device scratch ---------------------------
__device__ float  g_D1F[16 * 64 * 31];            // [l][j][m]
__device__ float  g_D1I[16 * 32 * 31 * 31];       // [l][j][m][n]
__device__ float  g_D2F[8 * 32 * 15 * 15];        // [l][j][m][k]
__device__ float  g_D2I0[8 * 15 * 15];            // [l][m][n]  (j=0 slice)
__device__ float2 g_xh[16 * 16 * 31];             // [b][l][m]
__device__ float2 g_xmn[16 * 32 * 32 * 225];      // [b][c][j][m][k]
__device__ float2 g_xh2[16 * 32 * 8 * 225];       // [b][c][l][m][k]
__device__ float2 g_H[64 * 32 * 8 * 225];         // [f][c][l][m][k]
__device__ float  g_partial[16 * 8 * 128];
__device__ float  g_feat[16 * 64];

// beta-grid precompute (setup kernel fills these)
__device__ double g_cb0[64], g_sb0[64], g_w0[64];   // B0 grid (64 betas), quad b=32
__device__ double g_cb1[32], g_sb1[32], g_w1[32];   // B1 grid (32 betas), quad b=16
__device__ double g_cb2[16], g_sb2[16];             // B2 grid (16 betas)

// factorials 0..31 (rounded-to-double; reference uses log-space, also inexact)
__device__ static const double c_F[32] = {
    1.0, 1.0, 2.0, 6.0, 24.0, 120.0, 720.0, 5040.0, 40320.0, 362880.0,
    3628800.0, 39916800.0, 479001600.0, 6227020800.0, 87178291200.0,
    1307674368000.0, 20922789888000.0, 355687428096000.0, 6402373705728000.0,
    121645100408832000.0, 2432902008176640000.0, 51090942171709440000.0,
    1124000727777607680000.0, 25852016738884976640000.0,
    620448401733239439360000.0, 15511210043330985984000000.0,
    403291461126605635584000000.0, 10888869450418352160768000000.0,
    304888344611713860501504000000.0, 8841761993739701954543616000000.0,
    265252859812191058636308480000000.0, 8222838654177922817725562880000000.0
};

__device__ __forceinline__ double ipow_d(double x, int e) {
    double r = 1.0;
    while (e) { if (e & 1) r *= x; x *= x; e >>= 1; }
    return r;
}

// Wigner-d via direct factorial products + term-ratio recurrence (no transcendentals)
__device__ double wig_fast(int l, int m, int n, double cb, double sb) {
    int kmin = max(0, m - n);
    int kmax = min(l + m, l - n);
    if (kmax < kmin) return 0.0;
    double t = sqrt(c_F[l + m] * c_F[l - m] * c_F[l + n] * c_F[l - n])
             / (c_F[kmin] * c_F[l + m - kmin] * c_F[l - n - kmin] * c_F[n - m + kmin]);
    t *= ipow_d(cb, 2 * l + m - n - 2 * kmin) * ipow_d(sb, n - m + 2 * kmin);
    if (kmin & 1) t = -t;
    double tansq = (sb * sb) / (cb * cb);
    double s = t;
    for (int k = kmin; k < kmax; ++k) {
        t *= -((double)((l + m - k) * (l - n - k)) /
               (double)((k + 1) * (n - m + k + 1))) * tansq;
        s += t;
    }
    return s;
}

// ------------------------- setup kernel (betas + quad weights) -------------
__global__ void t_setup() {
    int t = threadIdx.x;   // 64 threads
    if (t < 64) {
        double beta = PI_D * (2.0 * t + 1.0) / 128.0;
        g_cb0[t] = cos(beta * 0.5);
        g_sb0[t] = sin(beta * 0.5);
        double s = 0.0;
        for (int k = 0; k < 32; ++k)
            s += sin((2.0 * k + 1.0) * beta) / (2.0 * k + 1.0);
        g_w0[t] = (2.0 / 32.0) * sin(beta) * s;
    }
    if (t < 32) {
        double beta = PI_D * (2.0 * t + 1.0) / 64.0;
        g_cb1[t] = cos(beta * 0.5);
        g_sb1[t] = sin(beta * 0.5);
        double s = 0.0;
        for (int k = 0; k < 16; ++k)
            s += sin((2.0 * k + 1.0) * beta) / (2.0 * k + 1.0);
        g_w1[t] = (2.0 / 16.0) * sin(beta) * s;
    }
    if (t < 16) {
        double beta = PI_D * (2.0 * t + 1.0) / 32.0;
        g_cb2[t] = cos(beta * 0.5);
        g_sb2[t] = sin(beta * 0.5);
    }
}

// ------------------------- merged table kernel -----------------------------
// [0,31744): D1F | [31744,523776): D1I | [523776,581376): D2F | [581376,583176): D2I0
__global__ void t_tables() {
    int idx = blockIdx.x * blockDim.x + threadIdx.x;
    if (idx < 31744) {                       // D1F [l][j][m], j on B0 grid, n=0
        int l = idx / (64 * 31);
        int j = (idx / 31) % 64;
        int m = idx % 31;
        int mt = m - 15;
        float v = 0.f;
        if (abs(mt) <= l)
            v = (float)(g_w0[j] * wig_fast(l, mt, 0, g_cb0[j], g_sb0[j]));
        g_D1F[idx] = v;
        return;
    }
    idx -= 31744;
    if (idx < 492032) {                      // D1I [l][j][m][n], j on B1 grid
        int l = idx / 30752;
        int j = (idx / 961) % 32;
        int m = (idx / 31) % 31;
        int n = idx % 31;
        int mt = m - 15, nt = n - 15;
        float v = 0.f;
        if (abs(mt) <= l && abs(nt) <= l)
            v = (float)((2.0 * l + 1.0) * wig_fast(l, mt, nt, g_cb1[j], g_sb1[j]));
        g_D1I[idx] = v;
        return;
    }
    idx -= 492032;
    if (idx < 57600) {                       // D2F [l][j][m][n], j on B1 grid
        int l = idx / (32 * 225);
        int j = (idx / 225) % 32;
        int m = (idx / 15) % 15;
        int n = idx % 15;
        int mt = m - 7, nt = n - 7;
        float v = 0.f;
        if (abs(mt) <= l && abs(nt) <= l)
            v = (float)(g_w1[j] * wig_fast(l, mt, nt, g_cb1[j], g_sb1[j]));
        g_D2F[idx] = v;
        return;
    }
    idx -= 57600;
    if (idx < 1800) {                        // D2I0 [l][m][n], beta2[0]
        int l = idx / 225;
        int m = (idx / 15) % 15;
        int n = idx % 15;
        int mt = m - 7, nt = n - 7;
        float v = 0.f;
        if (abs(mt) <= l && abs(nt) <= l)
            v = (float)((2.0 * l + 1.0) * wig_fast(l, mt, nt, g_cb2[0], g_sb2[0]));
        g_D2I0[idx] = v;
    }
}

// ------------------------- stage A: x -> xh --------------------------------
__global__ void k_xh(const float* __restrict__ x) {
    __shared__ float2 s_tw[64];
    __shared__ float2 s_xm[64];
    int b = blockIdx.x / 31;
    int m = blockIdx.x % 31;
    int mt = m - 15;
    int j = threadIdx.x;   // 64 threads

    float sj, cj;
    __sincosf((float)j * (6.2831853071795864769f / 64.f), &sj, &cj);
    s_tw[j] = make_float2(cj, sj);
    __syncthreads();

    const float* xr = x + (size_t)(b * 64 + j) * 64;
    float accx = 0.f, accy = 0.f;
#pragma unroll 8
    for (int t = 0; t < 64; ++t) {
        unsigned r = ((unsigned)(mt * t)) & 63u;
        float2 e = s_tw[r];
        float v = xr[t];
        accx += v * e.x;
        accy -= v * e.y;
    }
    s_xm[j] = make_float2(accx, accy);
    __syncthreads();

    if (j < 16) {
        int l = j;
        float ax = 0.f, ay = 0.f;
        const float* dp = g_D1F + (size_t)l * 64 * 31 + m;
#pragma unroll 8
        for (int jj = 0; jj < 64; ++jj) {
            float d = dp[jj * 31];
            float2 v = s_xm[jj];
            ax += d * v.x;
            ay += d * v.y;
        }
        g_xh[(b * 16 + l) * 31 + m] = make_float2(ax, ay);
    }
}

// ------------------------- stage B+C fused plane kernel --------------------
__global__ __launch_bounds__(256) void k_main(const float* __restrict__ w1r,
                                              const float* __restrict__ w1i) {
    __shared__ float2 s_xh[16 * 31];
    __shared__ float2 s_w1[16 * 31];
    __shared__ float2 s_f[31 * 31];
    __shared__ float2 s_g[31 * 32];
    __shared__ float  s_r[32 * 32];
    __shared__ float2 s_u[32 * 15];
    __shared__ float2 s_tw[32];

    int bx = blockIdx.x;
    int b = bx >> 10;
    int f = (bx >> 5) & 31;
    int j = bx & 31;
    int tid = threadIdx.x;

    if (tid < 32) {
        float s, c;
        __sincosf((float)tid * (6.2831853071795864769f / 32.f), &s, &c);
        s_tw[tid] = make_float2(c, s);
    }
    for (int i = tid; i < 496; i += 256) {
        s_xh[i] = g_xh[b * 496 + i];
        s_w1[i] = make_float2(w1r[f * 496 + i], w1i[f * 496 + i]);
    }
    __syncthreads();

    // step 1: f[m,n] = sum_l D1I[l,j,m,n] * xh[l,m] * conj(w1[l,n])
    for (int idx = tid; idx < 961; idx += 256) {
        int m = idx / 31, n = idx % 31;
        int l0 = max(abs(m - 15), abs(n - 15));
        float ax = 0.f, ay = 0.f;
        const float* dp = g_D1I + (size_t)j * 961 + m * 31 + n;
        for (int l = l0; l < 16; ++l) {
            float d = dp[(size_t)l * 30752];
            float2 a = s_xh[l * 31 + m];
            float2 w = s_w1[l * 31 + n];
            float tr = a.x * w.x + a.y * w.y;
            float ti = a.y * w.x - a.x * w.y;
            ax += d * tr;
            ay += d * ti;
        }
        s_f[idx] = make_float2(ax, ay);
    }
    __syncthreads();

    // step 2: g[m,q] = sum_n f[m,n] e^{+2pi i n~ q / 32}
    for (int idx = tid; idx < 992; idx += 256) {
        int m = idx >> 5, q = idx & 31;
        float ax = 0.f, ay = 0.f;
#pragma unroll
        for (int n = 0; n < 31; ++n) {
            unsigned r = ((unsigned)((n - 15) * q)) & 31u;
            float2 e = s_tw[r];
            float2 fv = s_f[m * 31 + n];
            ax += fv.x * e.x - fv.y * e.y;
            ay += fv.x * e.y + fv.y * e.x;
        }
        s_g[m * 32 + q] = make_float2(ax, ay);
    }
    __syncthreads();

    // step 3: r[p,q] = relu(Re sum_m e^{+2pi i m~ p/32} g[m,q])
    {
        int idx = tid;
#pragma unroll
        for (int rep = 0; rep < 4; ++rep, idx += 256) {
            int p = idx >> 5, q = idx & 31;
            float s = 0.f;
#pragma unroll
            for (int m = 0; m < 31; ++m) {
                unsigned r = ((unsigned)((m - 15) * p)) & 31u;
                float2 e = s_tw[r];
                float2 g = s_g[m * 32 + q];
                s += e.x * g.x - e.y * g.y;
            }
            s_r[idx] = fmaxf(s, 0.f);
        }
    }
    __syncthreads();

    // step 4: u[p,n2] = sum_q r[p,q] e^{-2pi i n~ q/32}
    for (int idx = tid; idx < 480; idx += 256) {
        int p = idx / 15, n2 = idx % 15;
        int nt = n2 - 7;
        float ax = 0.f, ay = 0.f;
#pragma unroll
        for (int q = 0; q < 32; ++q) {
            unsigned r = ((unsigned)(nt * q)) & 31u;
            float2 e = s_tw[r];
            float v = s_r[p * 32 + q];
            ax += v * e.x;
            ay -= v * e.y;
        }
        s_u[p * 15 + n2] = make_float2(ax, ay);
    }
    __syncthreads();

    // step 5: xmn[m2,n2] = sum_p e^{-2pi i m~ p/32} u[p,n2]
    if (tid < 225) {
        int m2 = tid / 15, n2 = tid % 15;
        int mt = m2 - 7;
        float ax = 0.f, ay = 0.f;
#pragma unroll
        for (int p = 0; p < 32; ++p) {
            unsigned r = ((unsigned)(mt * p)) & 31u;
            float2 e = s_tw[r];
            float2 u = s_u[p * 15 + n2];
            ax += u.x * e.x + u.y * e.y;
            ay += u.y * e.x - u.x * e.y;
        }
        g_xmn[(size_t)bx * 225 + tid] = make_float2(ax, ay);
    }
}

// ------------------------- stage D: xh2 ------------------------------------
__global__ void k_xh2() {
    int idx = blockIdx.x * blockDim.x + threadIdx.x;  // 921600
    int b = idx / 57600;
    int c = (idx / 1800) % 32;
    int l = (idx / 225) % 8;
    int mk = idx % 225;
    int m = mk / 15, k = mk % 15;
    if (max(abs(m - 7), abs(k - 7)) > l) {
        g_xh2[idx] = make_float2(0.f, 0.f);
        return;
    }
    const float2* xp = g_xmn + (size_t)(b * 32 + c) * 32 * 225 + mk;
    const float* dp = g_D2F + (size_t)l * 32 * 225 + mk;
    float ax = 0.f, ay = 0.f;
#pragma unroll 8
    for (int j = 0; j < 32; ++j) {
        float d = dp[j * 225];
        float2 v = xp[(size_t)j * 225];
        ax += d * v.x;
        ay += d * v.y;
    }
    g_xh2[idx] = make_float2(ax, ay);
}

// ------------------------- H precontraction --------------------------------
__global__ void k_H(const float* __restrict__ w2r, const float* __restrict__ w2i) {
    int idx = blockIdx.x * blockDim.x + threadIdx.x;  // 3686400
    int f = idx / (32 * 1800);
    int c = (idx / 1800) % 32;
    int l = (idx / 225) % 8;
    int m = (idx / 15) % 15;
    int k = idx % 15;
    if (abs(m - 7) > l) {
        g_H[idx] = make_float2(0.f, 0.f);
        return;
    }
    const float* dp = g_D2I0 + l * 225 + m * 15;
    size_t wbase = (size_t)((c * 64 + f) * 8 + l) * 225 + k;
    float ax = 0.f, ay = 0.f;
    for (int n = 7 - l; n <= 7 + l; ++n) {
        float d = dp[n];
        ax += d * w2r[wbase + n * 15];
        ay += d * w2i[wbase + n * 15];
    }
    g_H[idx] = make_float2(ax, ay);
}

// ------------------------- tiny GEMM out_feat ------------------------------
__global__ void k_dot() {
    int ks = blockIdx.x;      // 16 k-splits of 3600
    int ft = blockIdx.y;      // 8 f-tiles of 8
    int tid = threadIdx.x;    // 128
    int b = tid >> 3;
    int fl = tid & 7;
    int f = ft * 8 + fl;
    const float2* X = g_xh2 + (size_t)b * 57600 + ks * 3600;
    const float2* Hp = g_H + (size_t)f * 57600 + ks * 3600;
    float a0 = 0.f, a1 = 0.f, a2 = 0.f, a3 = 0.f;
#pragma unroll 4
    for (int kk = 0; kk < 3600; kk += 4) {
        float2 x0 = X[kk], h0 = Hp[kk];
        float2 x1 = X[kk + 1], h1 = Hp[kk + 1];
        float2 x2 = X[kk + 2], h2 = Hp[kk + 2];
        float2 x3 = X[kk + 3], h3 = Hp[kk + 3];
        a0 += x0.x * h0.x + x0.y * h0.y;
        a1 += x1.x * h1.x + x1.y * h1.y;
        a2 += x2.x * h2.x + x2.y * h2.y;
        a3 += x3.x * h3.x + x3.y * h3.y;
    }
    g_partial[(ks * 8 + ft) * 128 + tid] = (a0 + a1) + (a2 + a3);
}

__global__ void k_dotred() {
    int tid = threadIdx.x;    // 1024
    int b = tid >> 6;
    int f = tid & 63;
    int ft = f >> 3, fl = f & 7;
    float s = 0.f;
#pragma unroll
    for (int ks = 0; ks < 16; ++ks)
        s += g_partial[(ks * 8 + ft) * 128 + (b << 3) + fl];
    g_feat[b * 64 + f] = fmaxf(s, 0.f);
}

// ------------------------- head: conv1d + BN + FC --------------------------
__global__ void k_head(const float* __restrict__ w3, const float* __restrict__ b3,
                       const float* __restrict__ gam, const float* __restrict__ bet,
                       const float* __restrict__ fcw, const float* __restrict__ fcb,
                       float* __restrict__ out) {
    __shared__ float s_r3[16 * 570];
    __shared__ float s_mu[10], s_rstd[10];
    int tid = threadIdx.x;    // 256

    for (int idx = tid; idx < 9120; idx += 256) {
        int b = idx / 570;
        int r = idx % 570;
        int o = r / 57, t = r % 57;
        float s = b3[o];
#pragma unroll
        for (int k = 0; k < 8; ++k)
            s += w3[o * 8 + k] * g_feat[b * 64 + t + k];
        s_r3[idx] = fmaxf(s, 0.f);
    }
    __syncthreads();

    if (tid < 10) {
        int o = tid;
        float sum = 0.f;
        for (int b = 0; b < 16; ++b)
            for (int t = 0; t < 57; ++t)
                sum += s_r3[b * 570 + o * 57 + t];
        float mu = sum / 912.f;
        float v = 0.f;
        for (int b = 0; b < 16; ++b)
            for (int t = 0; t < 57; ++t) {
                float d = s_r3[b * 570 + o * 57 + t] - mu;
                v += d * d;
            }
        s_mu[o] = mu;
        s_rstd[o] = rsqrtf(v / 912.f + 1e-5f);
    }
    __syncthreads();

    for (int idx = tid; idx < 9120; idx += 256) {
        int o = (idx % 570) / 57;
        s_r3[idx] = gam[o] * (s_r3[idx] - s_mu[o]) * s_rstd[o] + bet[o];
    }
    __syncthreads();

    if (tid < 160) {
        int b = tid / 10, i = tid % 10;
        float s = fcb[i];
        const float* wr = fcw + i * 570;
        const float* xr = s_r3 + b * 570;
        for (int z = 0; z < 570; ++z) s += xr[z] * wr[z];
        out[b * 10 + i] = s;
    }
}

// ---------------------------------------------------------------------------
extern "C" void kernel_launch(void* const* d_in, const int* in_sizes, int n_in,
                              void* d_out, int out_size) {
    const float* x   = (const float*)d_in[0];
    const float* w1r = (const float*)d_in[1];
    const float* w1i = (const float*)d_in[2];
    const float* w2r = (const float*)d_in[3];
    const float* w2i = (const float*)d_in[4];
    const float* c3w = (const float*)d_in[5];
    const float* c3b = (const float*)d_in[6];
    const float* bng = (const float*)d_in[7];
    const float* bnb = (const float*)d_in[8];
    const float* fcw = (const float*)d_in[9];
    const float* fcb = (const float*)d_in[10];
    float* out = (float*)d_out;

    t_setup<<<1, 64>>>();
    t_tables<<<(583176 + 127) / 128, 128>>>();

    k_xh<<<16 * 31, 64>>>(x);
    k_main<<<16 * 32 * 32, 256>>>(w1r, w1i);
    k_xh2<<<921600 / 256, 256>>>();
    k_H<<<3686400 / 256, 256>>>(w2r, w2i);
    k_dot<<<dim3(16, 8), 128>>>();
    k_dotred<<<1, 1024>>>();
    k_head<<<1, 256>>>(c3w, c3b, bng, bnb, fcw, fcb, out);
}

// round 3
// speedup vs baseline: 2.3812x; 1.5127x over previous
#include <cuda_runtime.h>
#include <math.h>

// ---------------------------------------------------------------------------
// S2ConvNet forward pass, sm_103a.
// Shapes: B=16, F1=32, F2=64, B0=32, B1=16, B2=8, M1=31, M2=15.
// ---------------------------------------------------------------------------

#define PI_D 3.141592653589793238462643383279502884
#define TWOPI_32F 0.19634954084936207f   // 2*pi/32

// ------------------------- static device scratch ---------------------------
__device__ float  g_D1F[16 * 64 * 31];            // [l][j][m]
__device__ float  g_D1I[16 * 32 * 31 * 31];       // [l][j][m][n]
__device__ float  g_D2F[8 * 32 * 15 * 15];        // [l][j][m][k]
__device__ float  g_D2I0[8 * 15 * 15];            // [l][m][n]  (j=0 slice)
__device__ float2 g_xh[16 * 16 * 31];             // [b][l][m]
__device__ __align__(16) float2 g_xmn[16 * 32 * 32 * 225];  // [b][c][j][m][k]
__device__ __align__(16) float2 g_xh2[16 * 32 * 8 * 225];   // [b][c][l][m][k]
__device__ __align__(16) float2 g_H[64 * 32 * 8 * 225];     // [f][c][l][m][k]
__device__ float  g_partial[64 * 8 * 128];
__device__ float  g_feat[16 * 64];

// beta-grid precompute
__device__ double g_cb0[64], g_sb0[64], g_w0[64];
__device__ double g_cb1[32], g_sb1[32], g_w1[32];
__device__ double g_cb2[16], g_sb2[16];

__device__ static const double c_F[32] = {
    1.0, 1.0, 2.0, 6.0, 24.0, 120.0, 720.0, 5040.0, 40320.0, 362880.0,
    3628800.0, 39916800.0, 479001600.0, 6227020800.0, 87178291200.0,
    1307674368000.0, 20922789888000.0, 355687428096000.0, 6402373705728000.0,
    121645100408832000.0, 2432902008176640000.0, 51090942171709440000.0,
    1124000727777607680000.0, 25852016738884976640000.0,
    620448401733239439360000.0, 15511210043330985984000000.0,
    403291461126605635584000000.0, 10888869450418352160768000000.0,
    304888344611713860501504000000.0, 8841761993739701954543616000000.0,
    265252859812191058636308480000000.0, 8222838654177922817725562880000000.0
};

__device__ __forceinline__ double ipow_d(double x, int e) {
    double r = 1.0;
    while (e) { if (e & 1) r *= x; x *= x; e >>= 1; }
    return r;
}

__device__ double wig_fast(int l, int m, int n, double cb, double sb) {
    int kmin = max(0, m - n);
    int kmax = min(l + m, l - n);
    if (kmax < kmin) return 0.0;
    double t = sqrt(c_F[l + m] * c_F[l - m] * c_F[l + n] * c_F[l - n])
             / (c_F[kmin] * c_F[l + m - kmin] * c_F[l - n - kmin] * c_F[n - m + kmin]);
    t *= ipow_d(cb, 2 * l + m - n - 2 * kmin) * ipow_d(sb, n - m + 2 * kmin);
    if (kmin & 1) t = -t;
    double tansq = (sb * sb) / (cb * cb);
    double s = t;
    for (int k = kmin; k < kmax; ++k) {
        t *= -((double)((l + m - k) * (l - n - k)) /
               (double)((k + 1) * (n - m + k + 1))) * tansq;
        s += t;
    }
    return s;
}

// ------------------------- setup kernel ------------------------------------
__global__ void t_setup() {
    int t = threadIdx.x;   // 64
    if (t < 64) {
        double beta = PI_D * (2.0 * t + 1.0) / 128.0;
        g_cb0[t] = cos(beta * 0.5);
        g_sb0[t] = sin(beta * 0.5);
        double s = 0.0;
        for (int k = 0; k < 32; ++k)
            s += sin((2.0 * k + 1.0) * beta) / (2.0 * k + 1.0);
        g_w0[t] = (2.0 / 32.0) * sin(beta) * s;
    }
    if (t < 32) {
        double beta = PI_D * (2.0 * t + 1.0) / 64.0;
        g_cb1[t] = cos(beta * 0.5);
        g_sb1[t] = sin(beta * 0.5);
        double s = 0.0;
        for (int k = 0; k < 16; ++k)
            s += sin((2.0 * k + 1.0) * beta) / (2.0 * k + 1.0);
        g_w1[t] = (2.0 / 16.0) * sin(beta) * s;
    }
    if (t < 16) {
        double beta = PI_D * (2.0 * t + 1.0) / 32.0;
        g_cb2[t] = cos(beta * 0.5);
        g_sb2[t] = sin(beta * 0.5);
    }
}

// ------------------------- merged table kernel -----------------------------
__global__ void t_tables() {
    int idx = blockIdx.x * blockDim.x + threadIdx.x;
    if (idx < 31744) {
        int l = idx / (64 * 31);
        int j = (idx / 31) % 64;
        int m = idx % 31;
        int mt = m - 15;
        float v = 0.f;
        if (abs(mt) <= l)
            v = (float)(g_w0[j] * wig_fast(l, mt, 0, g_cb0[j], g_sb0[j]));
        g_D1F[idx] = v;
        return;
    }
    idx -= 31744;
    if (idx < 492032) {
        int l = idx / 30752;
        int j = (idx / 961) % 32;
        int m = (idx / 31) % 31;
        int n = idx % 31;
        int mt = m - 15, nt = n - 15;
        float v = 0.f;
        if (abs(mt) <= l && abs(nt) <= l)
            v = (float)((2.0 * l + 1.0) * wig_fast(l, mt, nt, g_cb1[j], g_sb1[j]));
        g_D1I[idx] = v;
        return;
    }
    idx -= 492032;
    if (idx < 57600) {
        int l = idx / (32 * 225);
        int j = (idx / 225) % 32;
        int m = (idx / 15) % 15;
        int n = idx % 15;
        int mt = m - 7, nt = n - 7;
        float v = 0.f;
        if (abs(mt) <= l && abs(nt) <= l)
            v = (float)(g_w1[j] * wig_fast(l, mt, nt, g_cb1[j], g_sb1[j]));
        g_D2F[idx] = v;
        return;
    }
    idx -= 57600;
    if (idx < 1800) {
        int l = idx / 225;
        int m = (idx / 15) % 15;
        int n = idx % 15;
        int mt = m - 7, nt = n - 7;
        float v = 0.f;
        if (abs(mt) <= l && abs(nt) <= l)
            v = (float)((2.0 * l + 1.0) * wig_fast(l, mt, nt, g_cb2[0], g_sb2[0]));
        g_D2I0[idx] = v;
    }
}

// ------------------------- stage A: x -> xh --------------------------------
__global__ void k_xh(const float* __restrict__ x) {
    __shared__ float2 s_tw[64];
    __shared__ float2 s_xm[64];
    int b = blockIdx.x / 31;
    int m = blockIdx.x % 31;
    int mt = m - 15;
    int j = threadIdx.x;   // 64

    float sj, cj;
    __sincosf((float)j * (6.2831853071795864769f / 64.f), &sj, &cj);
    s_tw[j] = make_float2(cj, sj);
    __syncthreads();

    const float* xr = x + (size_t)(b * 64 + j) * 64;
    float accx = 0.f, accy = 0.f;
#pragma unroll 8
    for (int t = 0; t < 64; ++t) {
        unsigned r = ((unsigned)(mt * t)) & 63u;
        float2 e = s_tw[r];
        float v = xr[t];
        accx += v * e.x;
        accy -= v * e.y;
    }
    s_xm[j] = make_float2(accx, accy);
    __syncthreads();

    if (j < 16) {
        int l = j;
        float ax = 0.f, ay = 0.f;
        const float* dp = g_D1F + (size_t)l * 64 * 31 + m;
#pragma unroll 8
        for (int jj = 0; jj < 64; ++jj) {
            float d = dp[jj * 31];
            float2 v = s_xm[jj];
            ax += d * v.x;
            ay += d * v.y;
        }
        g_xh[(b * 16 + l) * 31 + m] = make_float2(ax, ay);
    }
}

// ------------------------- stage B+C fused plane kernel --------------------
// LDS-minimized: 4-way output blocking (i^p rotations) + register twiddles.
__global__ __launch_bounds__(256, 4) void k_main(const float* __restrict__ w1r,
                                                 const float* __restrict__ w1i) {
    __shared__ float2 s_xh[16 * 31];
    __shared__ float2 s_w1[16 * 31];
    __shared__ float2 s_buf[992];       // f[961] OR r[1024 floats] + u[480]
    __shared__ float2 s_g[31 * 32];

    float2* s_f = s_buf;                           // [961]
    float*  s_r = (float*)s_buf;                   // [1024]
    float2* s_u = s_buf + 512;                     // [480]

    int bx = blockIdx.x;
    int b = bx >> 10;
    int f = (bx >> 5) & 31;
    int j = bx & 31;
    int tid = threadIdx.x;

    for (int i = tid; i < 496; i += 256) {
        s_xh[i] = g_xh[b * 496 + i];
        s_w1[i] = make_float2(w1r[f * 496 + i], w1i[f * 496 + i]);
    }
    __syncthreads();

    // step 1: f[m,n] = sum_l D1I[l,j,m,n] * xh[l,m] * conj(w1[l,n])
    for (int idx = tid; idx < 961; idx += 256) {
        int m = idx / 31, n = idx % 31;
        int l0 = max(abs(m - 15), abs(n - 15));
        float ax = 0.f, ay = 0.f;
        const float* dp = g_D1I + (size_t)j * 961 + m * 31 + n;
        for (int l = l0; l < 16; ++l) {
            float d = dp[(size_t)l * 30752];
            float2 a = s_xh[l * 31 + m];
            float2 w = s_w1[l * 31 + n];
            float tr = a.x * w.x + a.y * w.y;
            float ti = a.y * w.x - a.x * w.y;
            ax += d * tr;
            ay += d * ti;
        }
        s_f[idx] = make_float2(ax, ay);
    }
    __syncthreads();

    // step 2: g[m,q] = sum_n f[m,n] e^{+2pi i (n-15) q / 32}
    // thread (m,q0) computes q0, q0+8, q0+16, q0+24 via i^((n-15)%4) rotations.
    if (tid < 248) {
        int m = tid >> 3, q0 = tid & 7;
        float2 S, E;
        __sincosf((float)q0 * TWOPI_32F, &S.y, &S.x);
        {
            int a0 = ((unsigned)(-15 * q0)) & 31u;
            __sincosf((float)a0 * TWOPI_32F, &E.y, &E.x);
        }
        float a0x = 0.f, a0y = 0.f, a1x = 0.f, a1y = 0.f;
        float a2x = 0.f, a2y = 0.f, a3x = 0.f, a3y = 0.f;
        const float2* frow = s_f + m * 31;
        int n = 0;
#define S2_TERM(PP)                                                          \
        {                                                                    \
            float2 fv = frow[n];                                             \
            float tx = fv.x * E.x - fv.y * E.y;                              \
            float ty = fv.x * E.y + fv.y * E.x;                              \
            a0x += tx; a0y += ty;                                            \
            if (PP == 0) { a1x += tx; a1y += ty; a2x += tx; a2y += ty;       \
                           a3x += tx; a3y += ty; }                           \
            if (PP == 1) { a1x -= ty; a1y += tx; a2x -= tx; a2y -= ty;       \
                           a3x += ty; a3y -= tx; }                           \
            if (PP == 2) { a1x -= tx; a1y -= ty; a2x += tx; a2y += ty;       \
                           a3x -= tx; a3y -= ty; }                           \
            if (PP == 3) { a1x += ty; a1y -= tx; a2x -= tx; a2y -= ty;       \
                           a3x -= ty; a3y += tx; }                           \
            float ex = E.x * S.x - E.y * S.y;                                \
            E.y = E.x * S.y + E.y * S.x;                                     \
            E.x = ex;                                                        \
            ++n;                                                             \
        }
#pragma unroll
        for (int nb = 0; nb < 7; ++nb) {   // n = 0..27, (n-15)%4 = (n+1)&3
            S2_TERM(1) S2_TERM(2) S2_TERM(3) S2_TERM(0)
        }
        S2_TERM(1) S2_TERM(2) S2_TERM(3)   // n = 28,29,30
#undef S2_TERM
        s_g[m * 32 + q0]      = make_float2(a0x, a0y);
        s_g[m * 32 + q0 + 8]  = make_float2(a1x, a1y);
        s_g[m * 32 + q0 + 16] = make_float2(a2x, a2y);
        s_g[m * 32 + q0 + 24] = make_float2(a3x, a3y);
    }
    __syncthreads();

    // step 3: r[p,q] = relu(Re sum_m e^{+2pi i (m-15) p/32} g[m,q])
    // thread (p0,q) computes p0, p0+8, p0+16, p0+24.
    {
        int q = tid & 31, p0 = tid >> 5;   // p0 in 0..7
        float2 S, E;
        __sincosf((float)p0 * TWOPI_32F, &S.y, &S.x);
        {
            int a0 = ((unsigned)(-15 * p0)) & 31u;
            __sincosf((float)a0 * TWOPI_32F, &E.y, &E.x);
        }
        float a0s = 0.f, a1s = 0.f, a2s = 0.f, a3s = 0.f;
        const float2* gcol = s_g + q;
        int m = 0;
#define S3_TERM(PP)                                                          \
        {                                                                    \
            float2 gv = gcol[m * 32];                                        \
            float tx = gv.x * E.x - gv.y * E.y;                              \
            float ty = gv.x * E.y + gv.y * E.x;                              \
            a0s += tx;                                                       \
            if (PP == 0) { a1s += tx; a2s += tx; a3s += tx; }                \
            if (PP == 1) { a1s -= ty; a2s -= tx; a3s += ty; }                \
            if (PP == 2) { a1s -= tx; a2s += tx; a3s -= tx; }                \
            if (PP == 3) { a1s += ty; a2s -= tx; a3s -= ty; }                \
            float ex = E.x * S.x - E.y * S.y;                                \
            E.y = E.x * S.y + E.y * S.x;                                     \
            E.x = ex;                                                        \
            ++m;                                                             \
        }
#pragma unroll
        for (int mb = 0; mb < 7; ++mb) {
            S3_TERM(1) S3_TERM(2) S3_TERM(3) S3_TERM(0)
        }
        S3_TERM(1) S3_TERM(2) S3_TERM(3)
#undef S3_TERM
        __syncthreads();   // all reads of s_g / writes-after s_f done
        s_r[p0 * 32 + q]        = fmaxf(a0s, 0.f);
        s_r[(p0 + 8) * 32 + q]  = fmaxf(a1s, 0.f);
        s_r[(p0 + 16) * 32 + q] = fmaxf(a2s, 0.f);
        s_r[(p0 + 24) * 32 + q] = fmaxf(a3s, 0.f);
    }
    __syncthreads();

    // step 4: u[p,n2] = sum_q r[p,q] e^{-2pi i (n2-7) q/32}
#pragma unroll
    for (int rep = 0; rep < 2; ++rep) {
        int idx = tid + rep * 256;
        if (idx < 480) {
            int p = idx / 15, n2 = idx % 15;
            int nt = n2 - 7;
            float2 W = make_float2(1.f, 0.f), S4;
            {
                float ss, cc;
                __sincosf((float)nt * TWOPI_32F, &ss, &cc);
                S4 = make_float2(cc, -ss);
            }
            float ax = 0.f, ay = 0.f;
            const float* rrow = s_r + p * 32;
#pragma unroll
            for (int q = 0; q < 32; ++q) {
                float v = rrow[q];
                ax += v * W.x;
                ay += v * W.y;
                float wx = W.x * S4.x - W.y * S4.y;
                W.y = W.x * S4.y + W.y * S4.x;
                W.x = wx;
            }
            s_u[p * 15 + n2] = make_float2(ax, ay);
        }
    }
    __syncthreads();

    // step 5: xmn[m2,n2] = sum_p u[p,n2] e^{-2pi i (m2-7) p/32}
    if (tid < 225) {
        int m2 = tid / 15, n2 = tid % 15;
        int mt = m2 - 7;
        float2 W = make_float2(1.f, 0.f), S5;
        {
            float ss, cc;
            __sincosf((float)mt * TWOPI_32F, &ss, &cc);
            S5 = make_float2(cc, -ss);
        }
        float ax = 0.f, ay = 0.f;
        const float2* ucol = s_u + n2;
#pragma unroll
        for (int p = 0; p < 32; ++p) {
            float2 u = ucol[p * 15];
            ax += u.x * W.x - u.y * W.y;
            ay += u.x * W.y + u.y * W.x;
            float wx = W.x * S5.x - W.y * S5.y;
            W.y = W.x * S5.y + W.y * S5.x;
            W.x = wx;
        }
        g_xmn[(size_t)bx * 225 + tid] = make_float2(ax, ay);
    }
}

// ------------------------- fused stage D (xh2) + H precontraction ----------
__global__ void k_fused(const float* __restrict__ w2r, const float* __restrict__ w2i) {
    int bidx = blockIdx.x;
    if (bidx < 3600) {
        // xh2 part
        int idx = bidx * 256 + threadIdx.x;   // < 921600
        int b = idx / 57600;
        int c = (idx / 1800) % 32;
        int l = (idx / 225) % 8;
        int mk = idx % 225;
        int m = mk / 15, k = mk % 15;
        if (max(abs(m - 7), abs(k - 7)) > l) {
            g_xh2[idx] = make_float2(0.f, 0.f);
            return;
        }
        const float2* xp = g_xmn + (size_t)(b * 32 + c) * 32 * 225 + mk;
        const float* dp = g_D2F + (size_t)l * 32 * 225 + mk;
        float ax = 0.f, ay = 0.f;
#pragma unroll 8
        for (int jj = 0; jj < 32; ++jj) {
            float d = dp[jj * 225];
            float2 v = xp[(size_t)jj * 225];
            ax += d * v.x;
            ay += d * v.y;
        }
        g_xh2[idx] = make_float2(ax, ay);
    } else {
        // H part
        int idx = (bidx - 3600) * 256 + threadIdx.x;   // < 3686400
        int f = idx / (32 * 1800);
        int c = (idx / 1800) % 32;
        int l = (idx / 225) % 8;
        int m = (idx / 15) % 15;
        int k = idx % 15;
        if (abs(m - 7) > l) {
            g_H[idx] = make_float2(0.f, 0.f);
            return;
        }
        const float* dp = g_D2I0 + l * 225 + m * 15;
        size_t wbase = (size_t)((c * 64 + f) * 8 + l) * 225 + k;
        float ax = 0.f, ay = 0.f;
        for (int n = 7 - l; n <= 7 + l; ++n) {
            float d = dp[n];
            ax += d * w2r[wbase + n * 15];
            ay += d * w2i[wbase + n * 15];
        }
        g_H[idx] = make_float2(ax, ay);
    }
}

// ------------------------- tiny GEMM out_feat ------------------------------
__global__ void k_dot() {
    int ks = blockIdx.x;      // 64 k-splits of 900 float2 (450 float4)
    int ft = blockIdx.y;      // 8 f-tiles of 8
    int tid = threadIdx.x;    // 128
    int b = tid >> 3;
    int fl = tid & 7;
    int f = ft * 8 + fl;
    const float4* X4 = (const float4*)(g_xh2 + (size_t)b * 57600 + ks * 900);
    const float4* H4 = (const float4*)(g_H + (size_t)f * 57600 + ks * 900);
    float a0 = 0.f, a1 = 0.f;
#pragma unroll 4
    for (int kk = 0; kk < 450; kk += 2) {
        float4 x0 = X4[kk], h0 = H4[kk];
        float4 x1 = X4[kk + 1], h1 = H4[kk + 1];
        a0 += x0.x * h0.x + x0.y * h0.y + x0.z * h0.z + x0.w * h0.w;
        a1 += x1.x * h1.x + x1.y * h1.y + x1.z * h1.z + x1.w * h1.w;
    }
    g_partial[(ks * 8 + ft) * 128 + tid] = a0 + a1;
}

__global__ void k_dotred() {
    int tid = threadIdx.x;    // 1024
    int b = tid >> 6;
    int f = tid & 63;
    int ft = f >> 3, fl = f & 7;
    float s = 0.f;
#pragma unroll
    for (int ks = 0; ks < 64; ++ks)
        s += g_partial[(ks * 8 + ft) * 128 + (b << 3) + fl];
    g_feat[b * 64 + f] = fmaxf(s, 0.f);
}

// ------------------------- head: conv1d + BN + FC --------------------------
__global__ void k_head(const float* __restrict__ w3, const float* __restrict__ b3,
                       const float* __restrict__ gam, const float* __restrict__ bet,
                       const float* __restrict__ fcw, const float* __restrict__ fcb,
                       float* __restrict__ out) {
    __shared__ float s_r3[16 * 570];
    __shared__ float s_mu[10], s_rstd[10];
    __shared__ float s_ps[160], s_ps2[160];
    int tid = threadIdx.x;    // 256

    for (int idx = tid; idx < 9120; idx += 256) {
        int b = idx / 570;
        int r = idx % 570;
        int o = r / 57, t = r % 57;
        float s = b3[o];
#pragma unroll
        for (int k = 0; k < 8; ++k)
            s += w3[o * 8 + k] * g_feat[b * 64 + t + k];
        s_r3[idx] = fmaxf(s, 0.f);
    }
    __syncthreads();

    if (tid < 160) {
        int o = tid >> 4, i = tid & 15;
        float s = 0.f, s2 = 0.f;
        for (int idx2 = i; idx2 < 912; idx2 += 16) {
            int b = idx2 / 57, t = idx2 % 57;
            float v = s_r3[b * 570 + o * 57 + t];
            s += v;
            s2 += v * v;
        }
        s_ps[tid] = s;
        s_ps2[tid] = s2;
    }
    __syncthreads();

    if (tid < 10) {
        float s = 0.f, s2 = 0.f;
#pragma unroll
        for (int i = 0; i < 16; ++i) {
            s += s_ps[tid * 16 + i];
            s2 += s_ps2[tid * 16 + i];
        }
        float mu = s / 912.f;
        float var = s2 / 912.f - mu * mu;
        s_mu[tid] = mu;
        s_rstd[tid] = rsqrtf(var + 1e-5f);
    }
    __syncthreads();

    for (int idx = tid; idx < 9120; idx += 256) {
        int o = (idx % 570) / 57;
        s_r3[idx] = gam[o] * (s_r3[idx] - s_mu[o]) * s_rstd[o] + bet[o];
    }
    __syncthreads();

    if (tid < 160) {
        int b = tid / 10, i = tid % 10;
        float s = fcb[i];
        const float* wr = fcw + i * 570;
        const float* xr = s_r3 + b * 570;
        for (int z = 0; z < 570; ++z) s += xr[z] * wr[z];
        out[b * 10 + i] = s;
    }
}

// ---------------------------------------------------------------------------
extern "C" void kernel_launch(void* const* d_in, const int* in_sizes, int n_in,
                              void* d_out, int out_size) {
    const float* x   = (const float*)d_in[0];
    const float* w1r = (const float*)d_in[1];
    const float* w1i = (const float*)d_in[2];
    const float* w2r = (const float*)d_in[3];
    const float* w2i = (const float*)d_in[4];
    const float* c3w = (const float*)d_in[5];
    const float* c3b = (const float*)d_in[6];
    const float* bng = (const float*)d_in[7];
    const float* bnb = (const float*)d_in[8];
    const float* fcw = (const float*)d_in[9];
    const float* fcb = (const float*)d_in[10];
    float* out = (float*)d_out;

    t_setup<<<1, 64>>>();
    t_tables<<<(583176 + 127) / 128, 128>>>();

    k_xh<<<16 * 31, 64>>>(x);
    k_main<<<16 * 32 * 32, 256>>>(w1r, w1i);
    k_fused<<<3600 + 14400, 256>>>(w2r, w2i);
    k_dot<<<dim3(64, 8), 128>>>();
    k_dotred<<<1, 1024>>>();
    k_head<<<1, 256>>>(c3w, c3b, bng, bnb, fcw, fcb, out);
}

// round 4
// speedup vs baseline: 3.0012x; 1.2604x over previous
#include <cuda_runtime.h>
#include <math.h>

// ---------------------------------------------------------------------------
// S2ConvNet forward pass, sm_103a.
// Shapes: B=16, F1=32, F2=64, B0=32, B1=16, B2=8, M1=31, M2=15.
// ---------------------------------------------------------------------------

#define PI_D 3.141592653589793238462643383279502884
#define TWOPI_32F 0.19634954084936207f   // 2*pi/32

// ------------------------- static device scratch ---------------------------
__device__ float  g_D1F[16 * 64 * 31];                       // [l][j][m]
__device__ __align__(16) float g_D1I[16 * 32 * 31 * 32];     // [l][j][m][n] n padded to 32
__device__ float  g_D2F[8 * 32 * 15 * 15];                   // [l][j][m][k]
__device__ float  g_D2I0[8 * 15 * 15];                       // [l][m][n]
__device__ float2 g_xh[16 * 16 * 31];                        // [b][l][m]
__device__ __align__(16) float2 g_xmn[16 * 32 * 32 * 225];   // [b][c][j][m][k]
__device__ __align__(16) float2 g_xh2[16 * 32 * 8 * 225];    // [b][c][l][m][k]
__device__ __align__(16) float2 g_H[64 * 32 * 8 * 225];      // [f][c][l][m][k]
__device__ float  g_partial[64 * 8 * 128];
__device__ float  g_feat[16 * 64];

// beta-grid precompute (incl. tan^2(beta/2))
__device__ double g_cb0[64], g_sb0[64], g_w0[64], g_ts0[64];
__device__ double g_cb1[32], g_sb1[32], g_w1[32], g_ts1[32];
__device__ double g_cb2[16], g_sb2[16], g_ts2[16];

__device__ static const double c_F[32] = {
    1.0, 1.0, 2.0, 6.0, 24.0, 120.0, 720.0, 5040.0, 40320.0, 362880.0,
    3628800.0, 39916800.0, 479001600.0, 6227020800.0, 87178291200.0,
    1307674368000.0, 20922789888000.0, 355687428096000.0, 6402373705728000.0,
    121645100408832000.0, 2432902008176640000.0, 51090942171709440000.0,
    1124000727777607680000.0, 25852016738884976640000.0,
    620448401733239439360000.0, 15511210043330985984000000.0,
    403291461126605635584000000.0, 10888869450418352160768000000.0,
    304888344611713860501504000000.0, 8841761993739701954543616000000.0,
    265252859812191058636308480000000.0, 8222838654177922817725562880000000.0
};

// exact-rounded reciprocals 1/k (compile-time fp64 divisions)
__device__ static const double c_R[32] = {
    0.0, 1.0, 1.0/2.0, 1.0/3.0, 1.0/4.0, 1.0/5.0, 1.0/6.0, 1.0/7.0,
    1.0/8.0, 1.0/9.0, 1.0/10.0, 1.0/11.0, 1.0/12.0, 1.0/13.0, 1.0/14.0,
    1.0/15.0, 1.0/16.0, 1.0/17.0, 1.0/18.0, 1.0/19.0, 1.0/20.0, 1.0/21.0,
    1.0/22.0, 1.0/23.0, 1.0/24.0, 1.0/25.0, 1.0/26.0, 1.0/27.0, 1.0/28.0,
    1.0/29.0, 1.0/30.0, 1.0/31.0
};

__device__ __forceinline__ double ipow_d(double x, int e) {
    double r = 1.0;
    while (e) { if (e & 1) r *= x; x *= x; e >>= 1; }
    return r;
}

// Wigner-d via factorial products + division-free term-ratio recurrence
__device__ double wig_fast(int l, int m, int n, double cb, double sb, double ts) {
    int kmin = max(0, m - n);
    int kmax = min(l + m, l - n);
    if (kmax < kmin) return 0.0;
    double t = sqrt(c_F[l + m] * c_F[l - m] * c_F[l + n] * c_F[l - n])
             / (c_F[kmin] * c_F[l + m - kmin] * c_F[l - n - kmin] * c_F[n - m + kmin]);
    t *= ipow_d(cb, 2 * l + m - n - 2 * kmin) * ipow_d(sb, n - m + 2 * kmin);
    if (kmin & 1) t = -t;
    double s = t;
    for (int k = kmin; k < kmax; ++k) {
        t *= -((double)((l + m - k) * (l - n - k)) *
               c_R[k + 1] * c_R[n - m + k + 1]) * ts;
        s += t;
    }
    return s;
}

// ------------------------- setup kernel ------------------------------------
__global__ void t_setup() {
    int t = threadIdx.x;   // 64
    if (t < 64) {
        double beta = PI_D * (2.0 * t + 1.0) / 128.0;
        double sb, cb;
        sincos(beta * 0.5, &sb, &cb);
        g_cb0[t] = cb; g_sb0[t] = sb;
        g_ts0[t] = (sb * sb) / (cb * cb);
        double sinb = 2.0 * sb * cb;
        double c2 = 1.0 - 2.0 * sinb * sinb;       // cos(2*beta)
        double prev = -sinb, cur = sinb, s = 0.0;
#pragma unroll
        for (int k = 0; k < 32; ++k) {
            s += cur * (1.0 / (2.0 * k + 1.0));
            double nx = 2.0 * c2 * cur - prev;
            prev = cur; cur = nx;
        }
        g_w0[t] = (2.0 / 32.0) * sinb * s;
    }
    if (t < 32) {
        double beta = PI_D * (2.0 * t + 1.0) / 64.0;
        double sb, cb;
        sincos(beta * 0.5, &sb, &cb);
        g_cb1[t] = cb; g_sb1[t] = sb;
        g_ts1[t] = (sb * sb) / (cb * cb);
        double sinb = 2.0 * sb * cb;
        double c2 = 1.0 - 2.0 * sinb * sinb;
        double prev = -sinb, cur = sinb, s = 0.0;
#pragma unroll
        for (int k = 0; k < 16; ++k) {
            s += cur * (1.0 / (2.0 * k + 1.0));
            double nx = 2.0 * c2 * cur - prev;
            prev = cur; cur = nx;
        }
        g_w1[t] = (2.0 / 16.0) * sinb * s;
    }
    if (t < 16) {
        double beta = PI_D * (2.0 * t + 1.0) / 32.0;
        double sb, cb;
        sincos(beta * 0.5, &sb, &cb);
        g_cb2[t] = cb; g_sb2[t] = sb;
        g_ts2[t] = (sb * sb) / (cb * cb);
    }
}

// ------------------------- merged table kernel -----------------------------
// D1F 31744 | D1I 507904 (padded) | D2F 57600 | D2I0 1800  => 599048
__global__ void t_tables() {
    int idx = blockIdx.x * blockDim.x + threadIdx.x;
    if (idx < 31744) {
        int l = idx / (64 * 31);
        int j = (idx / 31) % 64;
        int m = idx % 31;
        int mt = m - 15;
        float v = 0.f;
        if (abs(mt) <= l)
            v = (float)(g_w0[j] * wig_fast(l, mt, 0, g_cb0[j], g_sb0[j], g_ts0[j]));
        g_D1F[idx] = v;
        return;
    }
    idx -= 31744;
    if (idx < 507904) {
        int l = idx / 31744;
        int r = idx % 31744;
        int j = r / 992;
        int m = (r / 32) % 31;
        int n = r % 32;
        int mt = m - 15, nt = n - 15;
        float v = 0.f;
        if (n < 31 && abs(mt) <= l && abs(nt) <= l)
            v = (float)((2.0 * l + 1.0) * wig_fast(l, mt, nt, g_cb1[j], g_sb1[j], g_ts1[j]));
        g_D1I[idx] = v;
        return;
    }
    idx -= 507904;
    if (idx < 57600) {
        int l = idx / (32 * 225);
        int j = (idx / 225) % 32;
        int m = (idx / 15) % 15;
        int n = idx % 15;
        int mt = m - 7, nt = n - 7;
        float v = 0.f;
        if (abs(mt) <= l && abs(nt) <= l)
            v = (float)(g_w1[j] * wig_fast(l, mt, nt, g_cb1[j], g_sb1[j], g_ts1[j]));
        g_D2F[idx] = v;
        return;
    }
    idx -= 57600;
    if (idx < 1800) {
        int l = idx / 225;
        int m = (idx / 15) % 15;
        int n = idx % 15;
        int mt = m - 7, nt = n - 7;
        float v = 0.f;
        if (abs(mt) <= l && abs(nt) <= l)
            v = (float)((2.0 * l + 1.0) * wig_fast(l, mt, nt, g_cb2[0], g_sb2[0], g_ts2[0]));
        g_D2I0[idx] = v;
    }
}

// ------------------------- stage A: x -> xh --------------------------------
__global__ void k_xh(const float* __restrict__ x) {
    __shared__ float2 s_tw[64];
    __shared__ float2 s_xm[64];
    int b = blockIdx.x / 31;
    int m = blockIdx.x % 31;
    int mt = m - 15;
    int j = threadIdx.x;   // 64

    float sj, cj;
    __sincosf((float)j * (6.2831853071795864769f / 64.f), &sj, &cj);
    s_tw[j] = make_float2(cj, sj);
    __syncthreads();

    const float* xr = x + (size_t)(b * 64 + j) * 64;
    float accx = 0.f, accy = 0.f;
#pragma unroll 8
    for (int t = 0; t < 64; ++t) {
        unsigned r = ((unsigned)(mt * t)) & 63u;
        float2 e = s_tw[r];
        float v = xr[t];
        accx += v * e.x;
        accy -= v * e.y;
    }
    s_xm[j] = make_float2(accx, accy);
    __syncthreads();

    if (j < 16) {
        int l = j;
        float ax = 0.f, ay = 0.f;
        const float* dp = g_D1F + (size_t)l * 64 * 31 + m;
#pragma unroll 8
        for (int jj = 0; jj < 64; ++jj) {
            float d = dp[jj * 31];
            float2 v = s_xm[jj];
            ax += d * v.x;
            ay += d * v.y;
        }
        g_xh[(b * 16 + l) * 31 + m] = make_float2(ax, ay);
    }
}

// ------------------------- stage B+C fused plane kernel --------------------
__global__ __launch_bounds__(256, 4) void k_main(const float* __restrict__ w1r,
                                                 const float* __restrict__ w1i) {
    __shared__ float2 s_xh[16 * 31];
    __shared__ __align__(16) float2 s_w1[16 * 32];   // n padded to 32
    __shared__ __align__(16) float2 s_buf[992];      // f[31][32] OR r[1024f]+u[480]
    __shared__ float2 s_g[31 * 32];

    float2* s_f = s_buf;                 // [m][n] stride 32
    float*  s_r = (float*)s_buf;         // [1024]
    float2* s_u = s_buf + 512;           // [480]

    int bx = blockIdx.x;
    int b = bx >> 10;
    int f = (bx >> 5) & 31;
    int j = bx & 31;
    int tid = threadIdx.x;

    for (int i = tid; i < 496; i += 256) {
        int l = i / 31, n = i % 31;
        s_xh[i] = g_xh[b * 496 + i];
        s_w1[l * 32 + n] = make_float2(w1r[f * 496 + i], w1i[f * 496 + i]);
    }
    if (tid < 16) s_w1[tid * 32 + 31] = make_float2(0.f, 0.f);
    __syncthreads();

    // step 1: f[m,n] = sum_l D1I[l,j,m,n] * xh[l,m] * conj(w1[l,n])
    // thread = (m, 4-n-group); vectorized LDS.128 / LDG.128.
    if (tid < 248) {
        int m = tid >> 3, ng = tid & 7, n0 = ng * 4;
        int am = abs(m - 15);
        int nhi = n0 + 3;
        int anmin = (nhi < 15) ? (15 - nhi) : ((n0 > 15) ? (n0 - 15) : 0);
        int l0 = max(am, anmin);
        float ax0 = 0.f, ay0 = 0.f, ax1 = 0.f, ay1 = 0.f;
        float ax2 = 0.f, ay2 = 0.f, ax3 = 0.f, ay3 = 0.f;
        const float4* dp4 = (const float4*)(g_D1I + (size_t)j * 992 + m * 32 + n0);
        for (int l = l0; l < 16; ++l) {
            float4 d = dp4[l * 7936];               // 31744 floats / 4
            float2 a = s_xh[l * 31 + m];
            float4 wA = *(const float4*)(s_w1 + l * 32 + n0);
            float4 wB = *(const float4*)(s_w1 + l * 32 + n0 + 2);
            float tr, ti;
            tr = a.x * wA.x + a.y * wA.y; ti = a.y * wA.x - a.x * wA.y;
            ax0 += d.x * tr; ay0 += d.x * ti;
            tr = a.x * wA.z + a.y * wA.w; ti = a.y * wA.z - a.x * wA.w;
            ax1 += d.y * tr; ay1 += d.y * ti;
            tr = a.x * wB.x + a.y * wB.y; ti = a.y * wB.x - a.x * wB.y;
            ax2 += d.z * tr; ay2 += d.z * ti;
            tr = a.x * wB.z + a.y * wB.w; ti = a.y * wB.z - a.x * wB.w;
            ax3 += d.w * tr; ay3 += d.w * ti;
        }
        *(float4*)(s_f + m * 32 + n0)     = make_float4(ax0, ay0, ax1, ay1);
        *(float4*)(s_f + m * 32 + n0 + 2) = make_float4(ax2, ay2, ax3, ay3);
    }
    __syncthreads();

    // step 2: g[m,q] = sum_n f[m,n] e^{+2pi i (n-15) q / 32}  (4-way q blocking)
    if (tid < 248) {
        int m = tid >> 3, q0 = tid & 7;
        float2 S, E;
        __sincosf((float)q0 * TWOPI_32F, &S.y, &S.x);
        {
            int a0 = ((unsigned)(-15 * q0)) & 31u;
            __sincosf((float)a0 * TWOPI_32F, &E.y, &E.x);
        }
        float a0x = 0.f, a0y = 0.f, a1x = 0.f, a1y = 0.f;
        float a2x = 0.f, a2y = 0.f, a3x = 0.f, a3y = 0.f;
        const float2* frow = s_f + m * 32;
        int n = 0;
#define S2_TERM(PP)                                                          \
        {                                                                    \
            float2 fv = frow[n];                                             \
            float tx = fv.x * E.x - fv.y * E.y;                              \
            float ty = fv.x * E.y + fv.y * E.x;                              \
            a0x += tx; a0y += ty;                                            \
            if (PP == 0) { a1x += tx; a1y += ty; a2x += tx; a2y += ty;       \
                           a3x += tx; a3y += ty; }                           \
            if (PP == 1) { a1x -= ty; a1y += tx; a2x -= tx; a2y -= ty;       \
                           a3x += ty; a3y -= tx; }                           \
            if (PP == 2) { a1x -= tx; a1y -= ty; a2x += tx; a2y += ty;       \
                           a3x -= tx; a3y -= ty; }                           \
            if (PP == 3) { a1x += ty; a1y -= tx; a2x -= tx; a2y -= ty;       \
                           a3x -= ty; a3y += tx; }                           \
            float ex = E.x * S.x - E.y * S.y;                                \
            E.y = E.x * S.y + E.y * S.x;                                     \
            E.x = ex;                                                        \
            ++n;                                                             \
        }
#pragma unroll
        for (int nb = 0; nb < 7; ++nb) {
            S2_TERM(1) S2_TERM(2) S2_TERM(3) S2_TERM(0)
        }
        S2_TERM(1) S2_TERM(2) S2_TERM(3)
#undef S2_TERM
        s_g[m * 32 + q0]      = make_float2(a0x, a0y);
        s_g[m * 32 + q0 + 8]  = make_float2(a1x, a1y);
        s_g[m * 32 + q0 + 16] = make_float2(a2x, a2y);
        s_g[m * 32 + q0 + 24] = make_float2(a3x, a3y);
    }
    __syncthreads();

    // step 3: r[p,q] = relu(Re sum_m e^{+2pi i (m-15) p/32} g[m,q])
    {
        int q = tid & 31, p0 = tid >> 5;
        float2 S, E;
        __sincosf((float)p0 * TWOPI_32F, &S.y, &S.x);
        {
            int a0 = ((unsigned)(-15 * p0)) & 31u;
            __sincosf((float)a0 * TWOPI_32F, &E.y, &E.x);
        }
        float a0s = 0.f, a1s = 0.f, a2s = 0.f, a3s = 0.f;
        const float2* gcol = s_g + q;
        int m = 0;
#define S3_TERM(PP)                                                          \
        {                                                                    \
            float2 gv = gcol[m * 32];                                        \
            float tx = gv.x * E.x - gv.y * E.y;                              \
            float ty = gv.x * E.y + gv.y * E.x;                              \
            a0s += tx;                                                       \
            if (PP == 0) { a1s += tx; a2s += tx; a3s += tx; }                \
            if (PP == 1) { a1s -= ty; a2s -= tx; a3s += ty; }                \
            if (PP == 2) { a1s -= tx; a2s += tx; a3s -= tx; }                \
            if (PP == 3) { a1s += ty; a2s -= tx; a3s -= ty; }                \
            float ex = E.x * S.x - E.y * S.y;                                \
            E.y = E.x * S.y + E.y * S.x;                                     \
            E.x = ex;                                                        \
            ++m;                                                             \
        }
#pragma unroll
        for (int mb = 0; mb < 7; ++mb) {
            S3_TERM(1) S3_TERM(2) S3_TERM(3) S3_TERM(0)
        }
        S3_TERM(1) S3_TERM(2) S3_TERM(3)
#undef S3_TERM
        __syncthreads();
        s_r[p0 * 32 + q]        = fmaxf(a0s, 0.f);
        s_r[(p0 + 8) * 32 + q]  = fmaxf(a1s, 0.f);
        s_r[(p0 + 16) * 32 + q] = fmaxf(a2s, 0.f);
        s_r[(p0 + 24) * 32 + q] = fmaxf(a3s, 0.f);
    }
    __syncthreads();

    // step 4: u[p,n2] = sum_q r[p,q] e^{-2pi i (n2-7) q/32}
#pragma unroll
    for (int rep = 0; rep < 2; ++rep) {
        int idx = tid + rep * 256;
        if (idx < 480) {
            int p = idx / 15, n2 = idx % 15;
            int nt = n2 - 7;
            float2 W = make_float2(1.f, 0.f), S4;
            {
                float ss, cc;
                __sincosf((float)nt * TWOPI_32F, &ss, &cc);
                S4 = make_float2(cc, -ss);
            }
            float ax = 0.f, ay = 0.f;
            const float* rrow = s_r + p * 32;
#pragma unroll
            for (int q = 0; q < 32; ++q) {
                float v = rrow[q];
                ax += v * W.x;
                ay += v * W.y;
                float wx = W.x * S4.x - W.y * S4.y;
                W.y = W.x * S4.y + W.y * S4.x;
                W.x = wx;
            }
            s_u[p * 15 + n2] = make_float2(ax, ay);
        }
    }
    __syncthreads();

    // step 5: xmn[m2,n2] = sum_p u[p,n2] e^{-2pi i (m2-7) p/32}
    if (tid < 225) {
        int m2 = tid / 15, n2 = tid % 15;
        int mt = m2 - 7;
        float2 W = make_float2(1.f, 0.f), S5;
        {
            float ss, cc;
            __sincosf((float)mt * TWOPI_32F, &ss, &cc);
            S5 = make_float2(cc, -ss);
        }
        float ax = 0.f, ay = 0.f;
        const float2* ucol = s_u + n2;
#pragma unroll
        for (int p = 0; p < 32; ++p) {
            float2 u = ucol[p * 15];
            ax += u.x * W.x - u.y * W.y;
            ay += u.x * W.y + u.y * W.x;
            float wx = W.x * S5.x - W.y * S5.y;
            W.y = W.x * S5.y + W.y * S5.x;
            W.x = wx;
        }
        g_xmn[(size_t)bx * 225 + tid] = make_float2(ax, ay);
    }
}

// ------------------------- fused stage D (xh2) + H precontraction ----------
__global__ void k_fused(const float* __restrict__ w2r, const float* __restrict__ w2i) {
    int bidx = blockIdx.x;
    if (bidx < 3600) {
        int idx = bidx * 256 + threadIdx.x;   // < 921600
        int b = idx / 57600;
        int c = (idx / 1800) % 32;
        int l = (idx / 225) % 8;
        int mk = idx % 225;
        int m = mk / 15, k = mk % 15;
        if (max(abs(m - 7), abs(k - 7)) > l) {
            g_xh2[idx] = make_float2(0.f, 0.f);
            return;
        }
        const float2* xp = g_xmn + (size_t)(b * 32 + c) * 32 * 225 + mk;
        const float* dp = g_D2F + (size_t)l * 32 * 225 + mk;
        float ax = 0.f, ay = 0.f;
#pragma unroll 8
        for (int jj = 0; jj < 32; ++jj) {
            float d = dp[jj * 225];
            float2 v = xp[(size_t)jj * 225];
            ax += d * v.x;
            ay += d * v.y;
        }
        g_xh2[idx] = make_float2(ax, ay);
    } else {
        int idx = (bidx - 3600) * 256 + threadIdx.x;   // < 3686400
        int f = idx / (32 * 1800);
        int c = (idx / 1800) % 32;
        int l = (idx / 225) % 8;
        int m = (idx / 15) % 15;
        int k = idx % 15;
        if (abs(m - 7) > l) {
            g_H[idx] = make_float2(0.f, 0.f);
            return;
        }
        const float* dp = g_D2I0 + l * 225 + m * 15;
        size_t wbase = (size_t)((c * 64 + f) * 8 + l) * 225 + k;
        float ax = 0.f, ay = 0.f;
        for (int n = 7 - l; n <= 7 + l; ++n) {
            float d = dp[n];
            ax += d * w2r[wbase + n * 15];
            ay += d * w2i[wbase + n * 15];
        }
        g_H[idx] = make_float2(ax, ay);
    }
}

// ------------------------- tiny GEMM out_feat ------------------------------
__global__ void k_dot() {
    int ks = blockIdx.x;      // 64 k-splits of 900 float2 (450 float4)
    int ft = blockIdx.y;      // 8 f-tiles of 8
    int tid = threadIdx.x;    // 128
    int b = tid >> 3;
    int fl = tid & 7;
    int f = ft * 8 + fl;
    const float4* X4 = (const float4*)(g_xh2 + (size_t)b * 57600 + ks * 900);
    const float4* H4 = (const float4*)(g_H + (size_t)f * 57600 + ks * 900);
    float a0 = 0.f, a1 = 0.f;
#pragma unroll 4
    for (int kk = 0; kk < 450; kk += 2) {
        float4 x0 = X4[kk], h0 = H4[kk];
        float4 x1 = X4[kk + 1], h1 = H4[kk + 1];
        a0 += x0.x * h0.x + x0.y * h0.y + x0.z * h0.z + x0.w * h0.w;
        a1 += x1.x * h1.x + x1.y * h1.y + x1.z * h1.z + x1.w * h1.w;
    }
    g_partial[(ks * 8 + ft) * 128 + tid] = a0 + a1;
}

__global__ void k_dotred() {
    int tid = threadIdx.x;    // 1024
    int b = tid >> 6;
    int f = tid & 63;
    int ft = f >> 3, fl = f & 7;
    float s = 0.f;
#pragma unroll
    for (int ks = 0; ks < 64; ++ks)
        s += g_partial[(ks * 8 + ft) * 128 + (b << 3) + fl];
    g_feat[b * 64 + f] = fmaxf(s, 0.f);
}

// ------------------------- head: conv1d + BN + FC --------------------------
__global__ void k_head(const float* __restrict__ w3, const float* __restrict__ b3,
                       const float* __restrict__ gam, const float* __restrict__ bet,
                       const float* __restrict__ fcw, const float* __restrict__ fcb,
                       float* __restrict__ out) {
    __shared__ float s_r3[16 * 570];
    __shared__ float s_mu[10], s_rstd[10];
    __shared__ float s_ps[160], s_ps2[160];
    int tid = threadIdx.x;    // 256

    for (int idx = tid; idx < 9120; idx += 256) {
        int b = idx / 570;
        int r = idx % 570;
        int o = r / 57, t = r % 57;
        float s = b3[o];
#pragma unroll
        for (int k = 0; k < 8; ++k)
            s += w3[o * 8 + k] * g_feat[b * 64 + t + k];
        s_r3[idx] = fmaxf(s, 0.f);
    }
    __syncthreads();

    if (tid < 160) {
        int o = tid >> 4, i = tid & 15;
        float s = 0.f, s2 = 0.f;
        for (int idx2 = i; idx2 < 912; idx2 += 16) {
            int b = idx2 / 57, t = idx2 % 57;
            float v = s_r3[b * 570 + o * 57 + t];
            s += v;
            s2 += v * v;
        }
        s_ps[tid] = s;
        s_ps2[tid] = s2;
    }
    __syncthreads();

    if (tid < 10) {
        float s = 0.f, s2 = 0.f;
#pragma unroll
        for (int i = 0; i < 16; ++i) {
            s += s_ps[tid * 16 + i];
            s2 += s_ps2[tid * 16 + i];
        }
        float mu = s / 912.f;
        float var = s2 / 912.f - mu * mu;
        s_mu[tid] = mu;
        s_rstd[tid] = rsqrtf(var + 1e-5f);
    }
    __syncthreads();

    for (int idx = tid; idx < 9120; idx += 256) {
        int o = (idx % 570) / 57;
        s_r3[idx] = gam[o] * (s_r3[idx] - s_mu[o]) * s_rstd[o] + bet[o];
    }
    __syncthreads();

    if (tid < 160) {
        int b = tid / 10, i = tid % 10;
        float s = fcb[i];
        const float* wr = fcw + i * 570;
        const float* xr = s_r3 + b * 570;
        for (int z = 0; z < 570; ++z) s += xr[z] * wr[z];
        out[b * 10 + i] = s;
    }
}

// ---------------------------------------------------------------------------
extern "C" void kernel_launch(void* const* d_in, const int* in_sizes, int n_in,
                              void* d_out, int out_size) {
    const float* x   = (const float*)d_in[0];
    const float* w1r = (const float*)d_in[1];
    const float* w1i = (const float*)d_in[2];
    const float* w2r = (const float*)d_in[3];
    const float* w2i = (const float*)d_in[4];
    const float* c3w = (const float*)d_in[5];
    const float* c3b = (const float*)d_in[6];
    const float* bng = (const float*)d_in[7];
    const float* bnb = (const float*)d_in[8];
    const float* fcw = (const float*)d_in[9];
    const float* fcb = (const float*)d_in[10];
    float* out = (float*)d_out;

    t_setup<<<1, 64>>>();
    t_tables<<<(599048 + 127) / 128, 128>>>();

    k_xh<<<16 * 31, 64>>>(x);
    k_main<<<16 * 32 * 32, 256>>>(w1r, w1i);
    k_fused<<<3600 + 14400, 256>>>(w2r, w2i);
    k_dot<<<dim3(64, 8), 128>>>();
    k_dotred<<<1, 1024>>>();
    k_head<<<1, 256>>>(c3w, c3b, bng, bnb, fcw, fcb, out);
}

// round 5
// speedup vs baseline: 3.1510x; 1.0499x over previous
#include <cuda_runtime.h>
#include <math.h>

// ---------------------------------------------------------------------------
// S2ConvNet forward pass, sm_103a.
// Shapes: B=16, F1=32, F2=64, B0=32, B1=16, B2=8, M1=31, M2=15.
// ---------------------------------------------------------------------------

#define PI_D 3.141592653589793238462643383279502884
#define TWOPI_32F 0.19634954084936207f   // 2*pi/32

// ------------------------- static device scratch ---------------------------
__device__ float  g_D1F[16 * 64 * 31];                       // [l][j][m]
__device__ __align__(16) float g_D1I[16 * 32 * 31 * 32];     // [l][j][m][n] n padded to 32
__device__ float  g_D2F[8 * 32 * 15 * 15];                   // [l][j][m][k]
__device__ float  g_D2I0[8 * 15 * 15];                       // [l][m][n]
__device__ float2 g_xh[16 * 16 * 31];                        // [b][l][m]
__device__ __align__(16) float2 g_xmn[16 * 32 * 32 * 225];   // [b][c][j][m][k]
__device__ __align__(16) float2 g_xh2[16 * 32 * 8 * 225];    // [b][c][l][m][k]
__device__ __align__(16) float2 g_H[64 * 32 * 8 * 225];      // [f][c][l][m][k]
__device__ float  g_partial[64 * 8 * 128];

// beta-grid precompute (incl. tan^2(beta/2))
__device__ double g_cb0[64], g_sb0[64], g_w0[64], g_ts0[64];
__device__ double g_cb1[32], g_sb1[32], g_w1[32], g_ts1[32];
__device__ double g_cb2[16], g_sb2[16], g_ts2[16];

__device__ static const double c_F[32] = {
    1.0, 1.0, 2.0, 6.0, 24.0, 120.0, 720.0, 5040.0, 40320.0, 362880.0,
    3628800.0, 39916800.0, 479001600.0, 6227020800.0, 87178291200.0,
    1307674368000.0, 20922789888000.0, 355687428096000.0, 6402373705728000.0,
    121645100408832000.0, 2432902008176640000.0, 51090942171709440000.0,
    1124000727777607680000.0, 25852016738884976640000.0,
    620448401733239439360000.0, 15511210043330985984000000.0,
    403291461126605635584000000.0, 10888869450418352160768000000.0,
    304888344611713860501504000000.0, 8841761993739701954543616000000.0,
    265252859812191058636308480000000.0, 8222838654177922817725562880000000.0
};

__device__ static const double c_R[32] = {
    0.0, 1.0, 1.0/2.0, 1.0/3.0, 1.0/4.0, 1.0/5.0, 1.0/6.0, 1.0/7.0,
    1.0/8.0, 1.0/9.0, 1.0/10.0, 1.0/11.0, 1.0/12.0, 1.0/13.0, 1.0/14.0,
    1.0/15.0, 1.0/16.0, 1.0/17.0, 1.0/18.0, 1.0/19.0, 1.0/20.0, 1.0/21.0,
    1.0/22.0, 1.0/23.0, 1.0/24.0, 1.0/25.0, 1.0/26.0, 1.0/27.0, 1.0/28.0,
    1.0/29.0, 1.0/30.0, 1.0/31.0
};

__device__ __forceinline__ double ipow_d(double x, int e) {
    double r = 1.0;
    while (e) { if (e & 1) r *= x; x *= x; e >>= 1; }
    return r;
}

__device__ double wig_fast(int l, int m, int n, double cb, double sb, double ts) {
    int kmin = max(0, m - n);
    int kmax = min(l + m, l - n);
    if (kmax < kmin) return 0.0;
    double t = sqrt(c_F[l + m] * c_F[l - m] * c_F[l + n] * c_F[l - n])
             / (c_F[kmin] * c_F[l + m - kmin] * c_F[l - n - kmin] * c_F[n - m + kmin]);
    t *= ipow_d(cb, 2 * l + m - n - 2 * kmin) * ipow_d(sb, n - m + 2 * kmin);
    if (kmin & 1) t = -t;
    double s = t;
    for (int k = kmin; k < kmax; ++k) {
        t *= -((double)((l + m - k) * (l - n - k)) *
               c_R[k + 1] * c_R[n - m + k + 1]) * ts;
        s += t;
    }
    return s;
}

// ------------------------- setup kernel ------------------------------------
__global__ void t_setup() {
    int t = threadIdx.x;   // 64
    if (t < 64) {
        double beta = PI_D * (2.0 * t + 1.0) / 128.0;
        double sb, cb;
        sincos(beta * 0.5, &sb, &cb);
        g_cb0[t] = cb; g_sb0[t] = sb;
        g_ts0[t] = (sb * sb) / (cb * cb);
        double sinb = 2.0 * sb * cb;
        double c2 = 1.0 - 2.0 * sinb * sinb;
        double prev = -sinb, cur = sinb, s = 0.0;
#pragma unroll
        for (int k = 0; k < 32; ++k) {
            s += cur * (1.0 / (2.0 * k + 1.0));
            double nx = 2.0 * c2 * cur - prev;
            prev = cur; cur = nx;
        }
        g_w0[t] = (2.0 / 32.0) * sinb * s;
    }
    if (t < 32) {
        double beta = PI_D * (2.0 * t + 1.0) / 64.0;
        double sb, cb;
        sincos(beta * 0.5, &sb, &cb);
        g_cb1[t] = cb; g_sb1[t] = sb;
        g_ts1[t] = (sb * sb) / (cb * cb);
        double sinb = 2.0 * sb * cb;
        double c2 = 1.0 - 2.0 * sinb * sinb;
        double prev = -sinb, cur = sinb, s = 0.0;
#pragma unroll
        for (int k = 0; k < 16; ++k) {
            s += cur * (1.0 / (2.0 * k + 1.0));
            double nx = 2.0 * c2 * cur - prev;
            prev = cur; cur = nx;
        }
        g_w1[t] = (2.0 / 16.0) * sinb * s;
    }
    if (t < 16) {
        double beta = PI_D * (2.0 * t + 1.0) / 32.0;
        double sb, cb;
        sincos(beta * 0.5, &sb, &cb);
        g_cb2[t] = cb; g_sb2[t] = sb;
        g_ts2[t] = (sb * sb) / (cb * cb);
    }
}

// ------------------------- merged table kernel -----------------------------
__global__ void t_tables() {
    int idx = blockIdx.x * blockDim.x + threadIdx.x;
    if (idx < 31744) {
        int l = idx / (64 * 31);
        int j = (idx / 31) % 64;
        int m = idx % 31;
        int mt = m - 15;
        float v = 0.f;
        if (abs(mt) <= l)
            v = (float)(g_w0[j] * wig_fast(l, mt, 0, g_cb0[j], g_sb0[j], g_ts0[j]));
        g_D1F[idx] = v;
        return;
    }
    idx -= 31744;
    if (idx < 507904) {
        int l = idx / 31744;
        int r = idx % 31744;
        int j = r / 992;
        int m = (r / 32) % 31;
        int n = r % 32;
        int mt = m - 15, nt = n - 15;
        float v = 0.f;
        if (n < 31 && abs(mt) <= l && abs(nt) <= l)
            v = (float)((2.0 * l + 1.0) * wig_fast(l, mt, nt, g_cb1[j], g_sb1[j], g_ts1[j]));
        g_D1I[idx] = v;
        return;
    }
    idx -= 507904;
    if (idx < 57600) {
        int l = idx / (32 * 225);
        int j = (idx / 225) % 32;
        int m = (idx / 15) % 15;
        int n = idx % 15;
        int mt = m - 7, nt = n - 7;
        float v = 0.f;
        if (abs(mt) <= l && abs(nt) <= l)
            v = (float)(g_w1[j] * wig_fast(l, mt, nt, g_cb1[j], g_sb1[j], g_ts1[j]));
        g_D2F[idx] = v;
        return;
    }
    idx -= 57600;
    if (idx < 1800) {
        int l = idx / 225;
        int m = (idx / 15) % 15;
        int n = idx % 15;
        int mt = m - 7, nt = n - 7;
        float v = 0.f;
        if (abs(mt) <= l && abs(nt) <= l)
            v = (float)((2.0 * l + 1.0) * wig_fast(l, mt, nt, g_cb2[0], g_sb2[0], g_ts2[0]));
        g_D2I0[idx] = v;
    }
}

// ------------------------- stage A: x -> xh --------------------------------
__global__ void k_xh(const float* __restrict__ x) {
    __shared__ float2 s_tw[64];
    __shared__ float2 s_xm[64];
    int b = blockIdx.x / 31;
    int m = blockIdx.x % 31;
    int mt = m - 15;
    int j = threadIdx.x;   // 64

    float sj, cj;
    __sincosf((float)j * (6.2831853071795864769f / 64.f), &sj, &cj);
    s_tw[j] = make_float2(cj, sj);
    __syncthreads();

    const float* xr = x + (size_t)(b * 64 + j) * 64;
    float accx = 0.f, accy = 0.f;
#pragma unroll 8
    for (int t = 0; t < 64; ++t) {
        unsigned r = ((unsigned)(mt * t)) & 63u;
        float2 e = s_tw[r];
        float v = xr[t];
        accx += v * e.x;
        accy -= v * e.y;
    }
    s_xm[j] = make_float2(accx, accy);
    __syncthreads();

    if (j < 16) {
        int l = j;
        float ax = 0.f, ay = 0.f;
        const float* dp = g_D1F + (size_t)l * 64 * 31 + m;
#pragma unroll 8
        for (int jj = 0; jj < 64; ++jj) {
            float d = dp[jj * 31];
            float2 v = s_xm[jj];
            ax += d * v.x;
            ay += d * v.y;
        }
        g_xh[(b * 16 + l) * 31 + m] = make_float2(ax, ay);
    }
}

// ------------------------- stage B+C fused plane kernel --------------------
__global__ __launch_bounds__(256, 4) void k_main(const float* __restrict__ w1r,
                                                 const float* __restrict__ w1i) {
    __shared__ float2 s_xh[16 * 31];
    __shared__ __align__(16) float2 s_w1[16 * 32];   // n padded to 32
    __shared__ __align__(16) float2 s_buf[992];      // f[31][32] OR r[32][33]f + u[256]
    __shared__ float2 s_g[31 * 32];

    float2* s_f = s_buf;                 // [m][n] stride 32
    float*  s_r = (float*)s_buf;         // [32][33] floats (stride 33, 4224 B)
    float2* s_u = s_buf + 528;           // [p][d] 32x8 = 256 float2 (2 KB)

    int bx = blockIdx.x;
    int b = bx >> 10;
    int f = (bx >> 5) & 31;
    int j = bx & 31;
    int tid = threadIdx.x;

    for (int i = tid; i < 496; i += 256) {
        int l = i / 31, n = i % 31;
        s_xh[i] = g_xh[b * 496 + i];
        s_w1[l * 32 + n] = make_float2(w1r[f * 496 + i], w1i[f * 496 + i]);
    }
    if (tid < 16) s_w1[tid * 32 + 31] = make_float2(0.f, 0.f);
    __syncthreads();

    // step 1: f[m,n] = sum_l D1I[l,j,m,n] * xh[l,m] * conj(w1[l,n])
    if (tid < 248) {
        int m = tid >> 3, ng = tid & 7, n0 = ng * 4;
        int am = abs(m - 15);
        int nhi = n0 + 3;
        int anmin = (nhi < 15) ? (15 - nhi) : ((n0 > 15) ? (n0 - 15) : 0);
        int l0 = max(am, anmin);
        float ax0 = 0.f, ay0 = 0.f, ax1 = 0.f, ay1 = 0.f;
        float ax2 = 0.f, ay2 = 0.f, ax3 = 0.f, ay3 = 0.f;
        const float4* dp4 = (const float4*)(g_D1I + (size_t)j * 992 + m * 32 + n0);
        for (int l = l0; l < 16; ++l) {
            float4 d = dp4[l * 7936];
            float2 a = s_xh[l * 31 + m];
            float4 wA = *(const float4*)(s_w1 + l * 32 + n0);
            float4 wB = *(const float4*)(s_w1 + l * 32 + n0 + 2);
            float tr, ti;
            tr = a.x * wA.x + a.y * wA.y; ti = a.y * wA.x - a.x * wA.y;
            ax0 += d.x * tr; ay0 += d.x * ti;
            tr = a.x * wA.z + a.y * wA.w; ti = a.y * wA.z - a.x * wA.w;
            ax1 += d.y * tr; ay1 += d.y * ti;
            tr = a.x * wB.x + a.y * wB.y; ti = a.y * wB.x - a.x * wB.y;
            ax2 += d.z * tr; ay2 += d.z * ti;
            tr = a.x * wB.z + a.y * wB.w; ti = a.y * wB.z - a.x * wB.w;
            ax3 += d.w * tr; ay3 += d.w * ti;
        }
        *(float4*)(s_f + m * 32 + n0)     = make_float4(ax0, ay0, ax1, ay1);
        *(float4*)(s_f + m * 32 + n0 + 2) = make_float4(ax2, ay2, ax3, ay3);
    }
    __syncthreads();

    // step 2: g[m,q] = sum_n f[m,n] e^{+2pi i (n-15) q / 32}  (4-way q blocking)
    if (tid < 248) {
        int m = tid >> 3, q0 = tid & 7;
        float2 S, E;
        __sincosf((float)q0 * TWOPI_32F, &S.y, &S.x);
        {
            int a0 = ((unsigned)(-15 * q0)) & 31u;
            __sincosf((float)a0 * TWOPI_32F, &E.y, &E.x);
        }
        float a0x = 0.f, a0y = 0.f, a1x = 0.f, a1y = 0.f;
        float a2x = 0.f, a2y = 0.f, a3x = 0.f, a3y = 0.f;
        const float2* frow = s_f + m * 32;
        int n = 0;
#define S2_TERM(PP)                                                          \
        {                                                                    \
            float2 fv = frow[n];                                             \
            float tx = fv.x * E.x - fv.y * E.y;                              \
            float ty = fv.x * E.y + fv.y * E.x;                              \
            a0x += tx; a0y += ty;                                            \
            if (PP == 0) { a1x += tx; a1y += ty; a2x += tx; a2y += ty;       \
                           a3x += tx; a3y += ty; }                           \
            if (PP == 1) { a1x -= ty; a1y += tx; a2x -= tx; a2y -= ty;       \
                           a3x += ty; a3y -= tx; }                           \
            if (PP == 2) { a1x -= tx; a1y -= ty; a2x += tx; a2y += ty;       \
                           a3x -= tx; a3y -= ty; }                           \
            if (PP == 3) { a1x += ty; a1y -= tx; a2x -= tx; a2y -= ty;       \
                           a3x -= ty; a3y += tx; }                           \
            float ex = E.x * S.x - E.y * S.y;                                \
            E.y = E.x * S.y + E.y * S.x;                                     \
            E.x = ex;                                                        \
            ++n;                                                             \
        }
#pragma unroll
        for (int nb = 0; nb < 7; ++nb) {
            S2_TERM(1) S2_TERM(2) S2_TERM(3) S2_TERM(0)
        }
        S2_TERM(1) S2_TERM(2) S2_TERM(3)
#undef S2_TERM
        s_g[m * 32 + q0]      = make_float2(a0x, a0y);
        s_g[m * 32 + q0 + 8]  = make_float2(a1x, a1y);
        s_g[m * 32 + q0 + 16] = make_float2(a2x, a2y);
        s_g[m * 32 + q0 + 24] = make_float2(a3x, a3y);
    }
    __syncthreads();

    // step 3: r[p,q] = relu(Re sum_m e^{+2pi i (m-15) p/32} g[m,q])
    {
        int q = tid & 31, p0 = tid >> 5;
        float2 S, E;
        __sincosf((float)p0 * TWOPI_32F, &S.y, &S.x);
        {
            int a0 = ((unsigned)(-15 * p0)) & 31u;
            __sincosf((float)a0 * TWOPI_32F, &E.y, &E.x);
        }
        float a0s = 0.f, a1s = 0.f, a2s = 0.f, a3s = 0.f;
        const float2* gcol = s_g + q;
        int m = 0;
#define S3_TERM(PP)                                                          \
        {                                                                    \
            float2 gv = gcol[m * 32];                                        \
            float tx = gv.x * E.x - gv.y * E.y;                              \
            float ty = gv.x * E.y + gv.y * E.x;                              \
            a0s += tx;                                                       \
            if (PP == 0) { a1s += tx; a2s += tx; a3s += tx; }                \
            if (PP == 1) { a1s -= ty; a2s -= tx; a3s += ty; }                \
            if (PP == 2) { a1s -= tx; a2s += tx; a3s -= tx; }                \
            if (PP == 3) { a1s += ty; a2s -= tx; a3s -= ty; }                \
            float ex = E.x * S.x - E.y * S.y;                                \
            E.y = E.x * S.y + E.y * S.x;                                     \
            E.x = ex;                                                        \
            ++m;                                                             \
        }
#pragma unroll
        for (int mb = 0; mb < 7; ++mb) {
            S3_TERM(1) S3_TERM(2) S3_TERM(3) S3_TERM(0)
        }
        S3_TERM(1) S3_TERM(2) S3_TERM(3)
#undef S3_TERM
        __syncthreads();   // step-2 reads of s_f (aliased by s_r) complete
        s_r[p0 * 33 + q]        = fmaxf(a0s, 0.f);
        s_r[(p0 + 8) * 33 + q]  = fmaxf(a1s, 0.f);
        s_r[(p0 + 16) * 33 + q] = fmaxf(a2s, 0.f);
        s_r[(p0 + 24) * 33 + q] = fmaxf(a3s, 0.f);
    }
    __syncthreads();

    // step 4 (Hermitian half): u[p,d] = sum_q r[p,q] e^{-2pi i d q/32}, d=0..7
    {
        int p = tid >> 3, d = tid & 7;
        float2 W = make_float2(1.f, 0.f), S4;
        {
            float ss, cc;
            __sincosf((float)d * TWOPI_32F, &ss, &cc);
            S4 = make_float2(cc, -ss);
        }
        float ax = 0.f, ay = 0.f;
        const float* rrow = s_r + p * 33;
#pragma unroll
        for (int q = 0; q < 32; ++q) {
            float v = rrow[q];
            ax += v * W.x;
            ay += v * W.y;
            float wx = W.x * S4.x - W.y * S4.y;
            W.y = W.x * S4.y + W.y * S4.x;
            W.x = wx;
        }
        s_u[p * 8 + d] = make_float2(ax, ay);
    }
    __syncthreads();

    // step 5 (Hermitian half): n2 = 7+d, all m2; mirror to (14-m2, 14-n2).
    if (tid < 120) {
        int m2 = tid >> 3, d = tid & 7;
        int n2 = 7 + d;
        int mt = m2 - 7;
        float2 W = make_float2(1.f, 0.f), S5;
        {
            float ss, cc;
            __sincosf((float)mt * TWOPI_32F, &ss, &cc);
            S5 = make_float2(cc, -ss);
        }
        float ax = 0.f, ay = 0.f;
        const float2* ucol = s_u + d;
#pragma unroll
        for (int p = 0; p < 32; ++p) {
            float2 u = ucol[p * 8];
            ax += u.x * W.x - u.y * W.y;
            ay += u.x * W.y + u.y * W.x;
            float wx = W.x * S5.x - W.y * S5.y;
            W.y = W.x * S5.y + W.y * S5.x;
            W.x = wx;
        }
        float2* outp = g_xmn + (size_t)bx * 225;
        outp[m2 * 15 + n2] = make_float2(ax, ay);
        if (d > 0)
            outp[(14 - m2) * 15 + (14 - n2)] = make_float2(ax, -ay);
    }
}

// ------------------------- fused stage D (xh2) + H precontraction ----------
__global__ void k_fused(const float* __restrict__ w2r, const float* __restrict__ w2i) {
    int bidx = blockIdx.x;
    if (bidx < 3600) {
        int idx = bidx * 256 + threadIdx.x;   // < 921600
        int b = idx / 57600;
        int c = (idx / 1800) % 32;
        int l = (idx / 225) % 8;
        int mk = idx % 225;
        int m = mk / 15, k = mk % 15;
        if (max(abs(m - 7), abs(k - 7)) > l) {
            g_xh2[idx] = make_float2(0.f, 0.f);
            return;
        }
        const float2* xp = g_xmn + (size_t)(b * 32 + c) * 32 * 225 + mk;
        const float* dp = g_D2F + (size_t)l * 32 * 225 + mk;
        float ax = 0.f, ay = 0.f;
#pragma unroll 8
        for (int jj = 0; jj < 32; ++jj) {
            float d = dp[jj * 225];
            float2 v = xp[(size_t)jj * 225];
            ax += d * v.x;
            ay += d * v.y;
        }
        g_xh2[idx] = make_float2(ax, ay);
    } else {
        int idx = (bidx - 3600) * 256 + threadIdx.x;   // < 3686400
        int f = idx / (32 * 1800);
        int c = (idx / 1800) % 32;
        int l = (idx / 225) % 8;
        int m = (idx / 15) % 15;
        int k = idx % 15;
        if (abs(m - 7) > l) {
            g_H[idx] = make_float2(0.f, 0.f);
            return;
        }
        const float* dp = g_D2I0 + l * 225 + m * 15;
        size_t wbase = (size_t)((c * 64 + f) * 8 + l) * 225 + k;
        float ax = 0.f, ay = 0.f;
        for (int n = 7 - l; n <= 7 + l; ++n) {
            float d = dp[n];
            ax += d * w2r[wbase + n * 15];
            ay += d * w2i[wbase + n * 15];
        }
        g_H[idx] = make_float2(ax, ay);
    }
}

// ------------------------- tiny GEMM out_feat ------------------------------
__global__ void k_dot() {
    int ks = blockIdx.x;      // 64 k-splits of 900 float2 (450 float4)
    int ft = blockIdx.y;      // 8 f-tiles of 8
    int tid = threadIdx.x;    // 128
    int b = tid >> 3;
    int fl = tid & 7;
    int f = ft * 8 + fl;
    const float4* X4 = (const float4*)(g_xh2 + (size_t)b * 57600 + ks * 900);
    const float4* H4 = (const float4*)(g_H + (size_t)f * 57600 + ks * 900);
    float a0 = 0.f, a1 = 0.f;
#pragma unroll 4
    for (int kk = 0; kk < 450; kk += 2) {
        float4 x0 = X4[kk], h0 = H4[kk];
        float4 x1 = X4[kk + 1], h1 = H4[kk + 1];
        a0 += x0.x * h0.x + x0.y * h0.y + x0.z * h0.z + x0.w * h0.w;
        a1 += x1.x * h1.x + x1.y * h1.y + x1.z * h1.z + x1.w * h1.w;
    }
    g_partial[(ks * 8 + ft) * 128 + tid] = a0 + a1;
}

// ------------------------- head: reduce + conv1d + BN + FC -----------------
__global__ void k_head(const float* __restrict__ w3, const float* __restrict__ b3,
                       const float* __restrict__ gam, const float* __restrict__ bet,
                       const float* __restrict__ fcw, const float* __restrict__ fcb,
                       float* __restrict__ out) {
    __shared__ float s_feat[16 * 64];
    __shared__ float s_r3[16 * 570];
    __shared__ float s_mu[10], s_rstd[10];
    __shared__ float s_ps[160], s_ps2[160];
    int tid = threadIdx.x;    // 256

    // fold former k_dotred: g_partial -> s_feat
    for (int idx = tid; idx < 1024; idx += 256) {
        int b = idx >> 6;
        int f = idx & 63;
        int ft = f >> 3, fl = f & 7;
        float s = 0.f;
#pragma unroll
        for (int ks = 0; ks < 64; ++ks)
            s += g_partial[(ks * 8 + ft) * 128 + (b << 3) + fl];
        s_feat[b * 64 + f] = fmaxf(s, 0.f);
    }
    __syncthreads();

    for (int idx = tid; idx < 9120; idx += 256) {
        int b = idx / 570;
        int r = idx % 570;
        int o = r / 57, t = r % 57;
        float s = b3[o];
#pragma unroll
        for (int k = 0; k < 8; ++k)
            s += w3[o * 8 + k] * s_feat[b * 64 + t + k];
        s_r3[idx] = fmaxf(s, 0.f);
    }
    __syncthreads();

    if (tid < 160) {
        int o = tid >> 4, i = tid & 15;
        float s = 0.f, s2 = 0.f;
        for (int idx2 = i; idx2 < 912; idx2 += 16) {
            int b = idx2 / 57, t = idx2 % 57;
            float v = s_r3[b * 570 + o * 57 + t];
            s += v;
            s2 += v * v;
        }
        s_ps[tid] = s;
        s_ps2[tid] = s2;
    }
    __syncthreads();

    if (tid < 10) {
        float s = 0.f, s2 = 0.f;
#pragma unroll
        for (int i = 0; i < 16; ++i) {
            s += s_ps[tid * 16 + i];
            s2 += s_ps2[tid * 16 + i];
        }
        float mu = s / 912.f;
        float var = s2 / 912.f - mu * mu;
        s_mu[tid] = mu;
        s_rstd[tid] = rsqrtf(var + 1e-5f);
    }
    __syncthreads();

    for (int idx = tid; idx < 9120; idx += 256) {
        int o = (idx % 570) / 57;
        s_r3[idx] = gam[o] * (s_r3[idx] - s_mu[o]) * s_rstd[o] + bet[o];
    }
    __syncthreads();

    if (tid < 160) {
        int b = tid / 10, i = tid % 10;
        float s = fcb[i];
        const float* wr = fcw + i * 570;
        const float* xr = s_r3 + b * 570;
        for (int z = 0; z < 570; ++z) s += xr[z] * wr[z];
        out[b * 10 + i] = s;
    }
}

// ---------------------------------------------------------------------------
extern "C" void kernel_launch(void* const* d_in, const int* in_sizes, int n_in,
                              void* d_out, int out_size) {
    const float* x   = (const float*)d_in[0];
    const float* w1r = (const float*)d_in[1];
    const float* w1i = (const float*)d_in[2];
    const float* w2r = (const float*)d_in[3];
    const float* w2i = (const float*)d_in[4];
    const float* c3w = (const float*)d_in[5];
    const float* c3b = (const float*)d_in[6];
    const float* bng = (const float*)d_in[7];
    const float* bnb = (const float*)d_in[8];
    const float* fcw = (const float*)d_in[9];
    const float* fcb = (const float*)d_in[10];
    float* out = (float*)d_out;

    t_setup<<<1, 64>>>();
    t_tables<<<(599048 + 127) / 128, 128>>>();

    k_xh<<<16 * 31, 64>>>(x);
    k_main<<<16 * 32 * 32, 256>>>(w1r, w1i);
    k_fused<<<3600 + 14400, 256>>>(w2r, w2i);
    k_dot<<<dim3(64, 8), 128>>>();
    k_head<<<1, 256>>>(c3w, c3b, bng, bnb, fcw, fcb, out);
}

// round 6
// speedup vs baseline: 3.5276x; 1.1195x over previous
#include <cuda_runtime.h>
#include <math.h>

// ---------------------------------------------------------------------------
// S2ConvNet forward pass, sm_103a.
// Shapes: B=16, F1=32, F2=64, B0=32, B1=16, B2=8, M1=31, M2=15.
// ---------------------------------------------------------------------------

#define PI_D 3.141592653589793238462643383279502884
#define TWOPI_32F 0.19634954084936207f   // 2*pi/32

// ------------------------- static device scratch ---------------------------
__device__ float  g_D1F[16 * 64 * 31];                       // [l][j][m]
__device__ __align__(16) float g_D1I[16 * 32 * 31 * 32];     // [l][j][m][n] n padded
__device__ float  g_D2F[8 * 32 * 15 * 15];                   // [l][j][m][k]
__device__ float  g_D2I0[8 * 15 * 15];                       // [l][m][n]
__device__ float2 g_xh[16 * 16 * 31];                        // [b][l][m]
__device__ __align__(16) float2 g_xmn[16 * 32 * 32 * 225];   // [b][c][j][m][k]
__device__ __align__(16) float2 g_G[16 * 32 * 1800];         // [b][c][l][n][k]
__device__ float  g_partial[32 * 8 * 128];

// beta-grid precompute (incl. tan^2(beta/2))
__device__ double g_cb0[64], g_sb0[64], g_w0[64], g_ts0[64];
__device__ double g_cb1[32], g_sb1[32], g_w1[32], g_ts1[32];
__device__ double g_cb2[16], g_sb2[16], g_ts2[16];

__device__ static const double c_F[32] = {
    1.0, 1.0, 2.0, 6.0, 24.0, 120.0, 720.0, 5040.0, 40320.0, 362880.0,
    3628800.0, 39916800.0, 479001600.0, 6227020800.0, 87178291200.0,
    1307674368000.0, 20922789888000.0, 355687428096000.0, 6402373705728000.0,
    121645100408832000.0, 2432902008176640000.0, 51090942171709440000.0,
    1124000727777607680000.0, 25852016738884976640000.0,
    620448401733239439360000.0, 15511210043330985984000000.0,
    403291461126605635584000000.0, 10888869450418352160768000000.0,
    304888344611713860501504000000.0, 8841761993739701954543616000000.0,
    265252859812191058636308480000000.0, 8222838654177922817725562880000000.0
};

__device__ static const double c_R[32] = {
    0.0, 1.0, 1.0/2.0, 1.0/3.0, 1.0/4.0, 1.0/5.0, 1.0/6.0, 1.0/7.0,
    1.0/8.0, 1.0/9.0, 1.0/10.0, 1.0/11.0, 1.0/12.0, 1.0/13.0, 1.0/14.0,
    1.0/15.0, 1.0/16.0, 1.0/17.0, 1.0/18.0, 1.0/19.0, 1.0/20.0, 1.0/21.0,
    1.0/22.0, 1.0/23.0, 1.0/24.0, 1.0/25.0, 1.0/26.0, 1.0/27.0, 1.0/28.0,
    1.0/29.0, 1.0/30.0, 1.0/31.0
};

__device__ __forceinline__ double ipow_d(double x, int e) {
    double r = 1.0;
    while (e) { if (e & 1) r *= x; x *= x; e >>= 1; }
    return r;
}

__device__ double wig_fast(int l, int m, int n, double cb, double sb, double ts) {
    int kmin = max(0, m - n);
    int kmax = min(l + m, l - n);
    if (kmax < kmin) return 0.0;
    double t = sqrt(c_F[l + m] * c_F[l - m] * c_F[l + n] * c_F[l - n])
             / (c_F[kmin] * c_F[l + m - kmin] * c_F[l - n - kmin] * c_F[n - m + kmin]);
    t *= ipow_d(cb, 2 * l + m - n - 2 * kmin) * ipow_d(sb, n - m + 2 * kmin);
    if (kmin & 1) t = -t;
    double s = t;
    for (int k = kmin; k < kmax; ++k) {
        t *= -((double)((l + m - k) * (l - n - k)) *
               c_R[k + 1] * c_R[n - m + k + 1]) * ts;
        s += t;
    }
    return s;
}

// ------------------------- setup kernel ------------------------------------
__global__ void t_setup() {
    int t = threadIdx.x;   // 64
    if (t < 64) {
        double beta = PI_D * (2.0 * t + 1.0) / 128.0;
        double sb, cb;
        sincos(beta * 0.5, &sb, &cb);
        g_cb0[t] = cb; g_sb0[t] = sb;
        g_ts0[t] = (sb * sb) / (cb * cb);
        double sinb = 2.0 * sb * cb;
        double c2 = 1.0 - 2.0 * sinb * sinb;
        double prev = -sinb, cur = sinb, s = 0.0;
#pragma unroll
        for (int k = 0; k < 32; ++k) {
            s += cur * (1.0 / (2.0 * k + 1.0));
            double nx = 2.0 * c2 * cur - prev;
            prev = cur; cur = nx;
        }
        g_w0[t] = (2.0 / 32.0) * sinb * s;
    }
    if (t < 32) {
        double beta = PI_D * (2.0 * t + 1.0) / 64.0;
        double sb, cb;
        sincos(beta * 0.5, &sb, &cb);
        g_cb1[t] = cb; g_sb1[t] = sb;
        g_ts1[t] = (sb * sb) / (cb * cb);
        double sinb = 2.0 * sb * cb;
        double c2 = 1.0 - 2.0 * sinb * sinb;
        double prev = -sinb, cur = sinb, s = 0.0;
#pragma unroll
        for (int k = 0; k < 16; ++k) {
            s += cur * (1.0 / (2.0 * k + 1.0));
            double nx = 2.0 * c2 * cur - prev;
            prev = cur; cur = nx;
        }
        g_w1[t] = (2.0 / 16.0) * sinb * s;
    }
    if (t < 16) {
        double beta = PI_D * (2.0 * t + 1.0) / 32.0;
        double sb, cb;
        sincos(beta * 0.5, &sb, &cb);
        g_cb2[t] = cb; g_sb2[t] = sb;
        g_ts2[t] = (sb * sb) / (cb * cb);
    }
}

// ------------------------- merged table kernel -----------------------------
__global__ void t_tables() {
    int idx = blockIdx.x * blockDim.x + threadIdx.x;
    if (idx < 31744) {
        int l = idx / (64 * 31);
        int j = (idx / 31) % 64;
        int m = idx % 31;
        int mt = m - 15;
        float v = 0.f;
        if (abs(mt) <= l)
            v = (float)(g_w0[j] * wig_fast(l, mt, 0, g_cb0[j], g_sb0[j], g_ts0[j]));
        g_D1F[idx] = v;
        return;
    }
    idx -= 31744;
    if (idx < 507904) {
        int l = idx / 31744;
        int r = idx % 31744;
        int j = r / 992;
        int m = (r / 32) % 31;
        int n = r % 32;
        int mt = m - 15, nt = n - 15;
        float v = 0.f;
        if (n < 31 && abs(mt) <= l && abs(nt) <= l)
            v = (float)((2.0 * l + 1.0) * wig_fast(l, mt, nt, g_cb1[j], g_sb1[j], g_ts1[j]));
        g_D1I[idx] = v;
        return;
    }
    idx -= 507904;
    if (idx < 57600) {
        int l = idx / (32 * 225);
        int j = (idx / 225) % 32;
        int m = (idx / 15) % 15;
        int n = idx % 15;
        int mt = m - 7, nt = n - 7;
        float v = 0.f;
        if (abs(mt) <= l && abs(nt) <= l)
            v = (float)(g_w1[j] * wig_fast(l, mt, nt, g_cb1[j], g_sb1[j], g_ts1[j]));
        g_D2F[idx] = v;
        return;
    }
    idx -= 57600;
    if (idx < 1800) {
        int l = idx / 225;
        int m = (idx / 15) % 15;
        int n = idx % 15;
        int mt = m - 7, nt = n - 7;
        float v = 0.f;
        if (abs(mt) <= l && abs(nt) <= l)
            v = (float)((2.0 * l + 1.0) * wig_fast(l, mt, nt, g_cb2[0], g_sb2[0], g_ts2[0]));
        g_D2I0[idx] = v;
    }
}

// ------------------------- stage A: x -> xh --------------------------------
__global__ void k_xh(const float* __restrict__ x) {
    __shared__ float2 s_tw[64];
    __shared__ float2 s_xm[64];
    int b = blockIdx.x / 31;
    int m = blockIdx.x % 31;
    int mt = m - 15;
    int j = threadIdx.x;   // 64

    float sj, cj;
    __sincosf((float)j * (6.2831853071795864769f / 64.f), &sj, &cj);
    s_tw[j] = make_float2(cj, sj);
    __syncthreads();

    const float* xr = x + (size_t)(b * 64 + j) * 64;
    float accx = 0.f, accy = 0.f;
#pragma unroll 8
    for (int t = 0; t < 64; ++t) {
        unsigned r = ((unsigned)(mt * t)) & 63u;
        float2 e = s_tw[r];
        float v = xr[t];
        accx += v * e.x;
        accy -= v * e.y;
    }
    s_xm[j] = make_float2(accx, accy);
    __syncthreads();

    if (j < 16) {
        int l = j;
        float ax = 0.f, ay = 0.f;
        const float* dp = g_D1F + (size_t)l * 64 * 31 + m;
#pragma unroll 8
        for (int jj = 0; jj < 64; ++jj) {
            float d = dp[jj * 31];
            float2 v = s_xm[jj];
            ax += d * v.x;
            ay += d * v.y;
        }
        g_xh[(b * 16 + l) * 31 + m] = make_float2(ax, ay);
    }
}

// ------------------------- stage B+C fused plane kernel --------------------
__global__ __launch_bounds__(256, 4) void k_main(const float* __restrict__ w1r,
                                                 const float* __restrict__ w1i) {
    __shared__ float2 s_xh[16 * 31];
    __shared__ __align__(16) float2 s_w1[16 * 32];     // n padded to 32
    __shared__ __align__(16) float2 s_buf[1056];       // f[31][34] OR r[32][33]f+u[256]
    __shared__ float2 s_g[31 * 32];

    float2* s_f = s_buf;                 // [m][n] stride 34 (272B rows, 16B aligned)
    float*  s_r = (float*)s_buf;         // [32][33] floats
    float2* s_u = s_buf + 528;           // [p][d] 32x8

    int bx = blockIdx.x;
    int b = bx >> 10;
    int f = (bx >> 5) & 31;
    int j = bx & 31;
    int tid = threadIdx.x;

    for (int i = tid; i < 496; i += 256) {
        int l = i / 31, n = i % 31;
        s_xh[i] = g_xh[b * 496 + i];
        s_w1[l * 32 + n] = make_float2(w1r[f * 496 + i], w1i[f * 496 + i]);
    }
    if (tid < 16) s_w1[tid * 32 + 31] = make_float2(0.f, 0.f);
    __syncthreads();

    // step 1: f[m,n] = sum_l D1I[l,j,m,n] * xh[l,m] * conj(w1[l,n])
    if (tid < 248) {
        int m = tid >> 3, ng = tid & 7, n0 = ng * 4;
        int am = abs(m - 15);
        int nhi = n0 + 3;
        int anmin = (nhi < 15) ? (15 - nhi) : ((n0 > 15) ? (n0 - 15) : 0);
        int l0 = max(am, anmin);
        float ax0 = 0.f, ay0 = 0.f, ax1 = 0.f, ay1 = 0.f;
        float ax2 = 0.f, ay2 = 0.f, ax3 = 0.f, ay3 = 0.f;
        const float4* dp4 = (const float4*)(g_D1I + (size_t)j * 992 + m * 32 + n0);
        for (int l = l0; l < 16; ++l) {
            float4 d = dp4[l * 7936];
            float2 a = s_xh[l * 31 + m];
            float4 wA = *(const float4*)(s_w1 + l * 32 + n0);
            float4 wB = *(const float4*)(s_w1 + l * 32 + n0 + 2);
            float tr, ti;
            tr = a.x * wA.x + a.y * wA.y; ti = a.y * wA.x - a.x * wA.y;
            ax0 += d.x * tr; ay0 += d.x * ti;
            tr = a.x * wA.z + a.y * wA.w; ti = a.y * wA.z - a.x * wA.w;
            ax1 += d.y * tr; ay1 += d.y * ti;
            tr = a.x * wB.x + a.y * wB.y; ti = a.y * wB.x - a.x * wB.y;
            ax2 += d.z * tr; ay2 += d.z * ti;
            tr = a.x * wB.z + a.y * wB.w; ti = a.y * wB.z - a.x * wB.w;
            ax3 += d.w * tr; ay3 += d.w * ti;
        }
        *(float4*)(s_f + m * 34 + n0)     = make_float4(ax0, ay0, ax1, ay1);
        *(float4*)(s_f + m * 34 + n0 + 2) = make_float4(ax2, ay2, ax3, ay3);
    }
    __syncthreads();

    // step 2: g[m,q] = sum_n f[m,n] e^{+2pi i (n-15) q / 32}
    // 4-way q blocking + float4 (2 complex) LDS reads.
    if (tid < 248) {
        int m = tid >> 3, q0 = tid & 7;
        float2 S, E;
        __sincosf((float)q0 * TWOPI_32F, &S.y, &S.x);
        {
            int a0 = ((unsigned)(-15 * q0)) & 31u;
            __sincosf((float)a0 * TWOPI_32F, &E.y, &E.x);
        }
        float a0x = 0.f, a0y = 0.f, a1x = 0.f, a1y = 0.f;
        float a2x = 0.f, a2y = 0.f, a3x = 0.f, a3y = 0.f;
        const float4* frow4 = (const float4*)(s_f + m * 34);
#define S2T(PP, FX, FY)                                                      \
        {                                                                    \
            float tx = (FX) * E.x - (FY) * E.y;                              \
            float ty = (FX) * E.y + (FY) * E.x;                              \
            a0x += tx; a0y += ty;                                            \
            if (PP == 0) { a1x += tx; a1y += ty; a2x += tx; a2y += ty;       \
                           a3x += tx; a3y += ty; }                           \
            if (PP == 1) { a1x -= ty; a1y += tx; a2x -= tx; a2y -= ty;       \
                           a3x += ty; a3y -= tx; }                           \
            if (PP == 2) { a1x -= tx; a1y -= ty; a2x += tx; a2y += ty;       \
                           a3x -= tx; a3y -= ty; }                           \
            if (PP == 3) { a1x += ty; a1y -= tx; a2x -= tx; a2y -= ty;       \
                           a3x -= ty; a3y += tx; }                           \
            float ex = E.x * S.x - E.y * S.y;                                \
            E.y = E.x * S.y + E.y * S.x;                                     \
            E.x = ex;                                                        \
        }
#pragma unroll
        for (int nb = 0; nb < 7; ++nb) {     // n = 4nb .. 4nb+3 : PP 1,2,3,0
            float4 A = frow4[2 * nb];
            float4 Bv = frow4[2 * nb + 1];
            S2T(1, A.x, A.y) S2T(2, A.z, A.w)
            S2T(3, Bv.x, Bv.y) S2T(0, Bv.z, Bv.w)
        }
        {
            float4 A = frow4[14];            // n = 28 (PP1), 29 (PP2)
            S2T(1, A.x, A.y) S2T(2, A.z, A.w)
            float2 t30 = s_f[m * 34 + 30];   // n = 30 (PP3)
            S2T(3, t30.x, t30.y)
        }
#undef S2T
        s_g[m * 32 + q0]      = make_float2(a0x, a0y);
        s_g[m * 32 + q0 + 8]  = make_float2(a1x, a1y);
        s_g[m * 32 + q0 + 16] = make_float2(a2x, a2y);
        s_g[m * 32 + q0 + 24] = make_float2(a3x, a3y);
    }
    __syncthreads();

    // step 3: r[p,q] = relu(Re sum_m e^{+2pi i (m-15) p/32} g[m,q])
    {
        int q = tid & 31, p0 = tid >> 5;
        float2 S, E;
        __sincosf((float)p0 * TWOPI_32F, &S.y, &S.x);
        {
            int a0 = ((unsigned)(-15 * p0)) & 31u;
            __sincosf((float)a0 * TWOPI_32F, &E.y, &E.x);
        }
        float a0s = 0.f, a1s = 0.f, a2s = 0.f, a3s = 0.f;
        const float2* gcol = s_g + q;
        int m = 0;
#define S3_TERM(PP)                                                          \
        {                                                                    \
            float2 gv = gcol[m * 32];                                        \
            float tx = gv.x * E.x - gv.y * E.y;                              \
            float ty = gv.x * E.y + gv.y * E.x;                              \
            a0s += tx;                                                       \
            if (PP == 0) { a1s += tx; a2s += tx; a3s += tx; }                \
            if (PP == 1) { a1s -= ty; a2s -= tx; a3s += ty; }                \
            if (PP == 2) { a1s -= tx; a2s += tx; a3s -= tx; }                \
            if (PP == 3) { a1s += ty; a2s -= tx; a3s -= ty; }                \
            float ex = E.x * S.x - E.y * S.y;                                \
            E.y = E.x * S.y + E.y * S.x;                                     \
            E.x = ex;                                                        \
            ++m;                                                             \
        }
#pragma unroll
        for (int mb = 0; mb < 7; ++mb) {
            S3_TERM(1) S3_TERM(2) S3_TERM(3) S3_TERM(0)
        }
        S3_TERM(1) S3_TERM(2) S3_TERM(3)
#undef S3_TERM
        __syncthreads();   // step-2 reads of s_f (aliased by s_r) complete
        s_r[p0 * 33 + q]        = fmaxf(a0s, 0.f);
        s_r[(p0 + 8) * 33 + q]  = fmaxf(a1s, 0.f);
        s_r[(p0 + 16) * 33 + q] = fmaxf(a2s, 0.f);
        s_r[(p0 + 24) * 33 + q] = fmaxf(a3s, 0.f);
    }
    __syncthreads();

    // step 4 (Hermitian half): u[p,d] = sum_q r[p,q] e^{-2pi i d q/32}, d=0..7
    {
        int p = tid >> 3, d = tid & 7;
        float2 W = make_float2(1.f, 0.f), S4;
        {
            float ss, cc;
            __sincosf((float)d * TWOPI_32F, &ss, &cc);
            S4 = make_float2(cc, -ss);
        }
        float ax = 0.f, ay = 0.f;
        const float* rrow = s_r + p * 33;
#pragma unroll
        for (int q = 0; q < 32; ++q) {
            float v = rrow[q];
            ax += v * W.x;
            ay += v * W.y;
            float wx = W.x * S4.x - W.y * S4.y;
            W.y = W.x * S4.y + W.y * S4.x;
            W.x = wx;
        }
        s_u[p * 8 + d] = make_float2(ax, ay);
    }
    __syncthreads();

    // step 5 (Hermitian half): n2 = 7+d, all m2; mirror to (14-m2, 14-n2).
    if (tid < 120) {
        int m2 = tid >> 3, d = tid & 7;
        int n2 = 7 + d;
        int mt = m2 - 7;
        float2 W = make_float2(1.f, 0.f), S5;
        {
            float ss, cc;
            __sincosf((float)mt * TWOPI_32F, &ss, &cc);
            S5 = make_float2(cc, -ss);
        }
        float ax = 0.f, ay = 0.f;
        const float2* ucol = s_u + d;
#pragma unroll
        for (int p = 0; p < 32; ++p) {
            float2 u = ucol[p * 8];
            ax += u.x * W.x - u.y * W.y;
            ay += u.x * W.y + u.y * W.x;
            float wx = W.x * S5.x - W.y * S5.y;
            W.y = W.x * S5.y + W.y * S5.x;
            W.x = wx;
        }
        float2* outp = g_xmn + (size_t)bx * 225;
        outp[m2 * 15 + n2] = make_float2(ax, ay);
        if (d > 0)
            outp[(14 - m2) * 15 + (14 - n2)] = make_float2(ax, -ay);
    }
}

// ------------------------- k_G: xmn -> xh2 -> G (per (b,c)) ----------------
// xh2[l,m,k] = sum_j D2F[l,j,m,k] * xmn[j,m,k]   (xmn in registers per thread)
// G[l,n,k]   = sum_m D2I0[l,m,n] * xh2[l,m,k]
__global__ __launch_bounds__(256) void k_G() {
    __shared__ float2 s_xh2[8 * 225];    // 14.4 KB
    __shared__ float  s_d2i0[1800];      // 7.2 KB
    int bc = blockIdx.x;    // b*32 + c
    int tid = threadIdx.x;  // 256 (225 active in phase 1)

    for (int i = tid; i < 1800; i += 256) s_d2i0[i] = g_D2I0[i];

    if (tid < 225) {
        int mk = tid;
        float2 acc[8];
#pragma unroll
        for (int l = 0; l < 8; ++l) acc[l] = make_float2(0.f, 0.f);
        const float2* xp = g_xmn + (size_t)bc * 7200 + mk;
        const float* dp = g_D2F + mk;
#pragma unroll 4
        for (int j = 0; j < 32; ++j) {
            float2 xv = xp[j * 225];
#pragma unroll
            for (int l = 0; l < 8; ++l) {
                float d = dp[l * 7200 + j * 225];
                acc[l].x += d * xv.x;
                acc[l].y += d * xv.y;
            }
        }
#pragma unroll
        for (int l = 0; l < 8; ++l) s_xh2[l * 225 + mk] = acc[l];
    }
    __syncthreads();

    float2* gout = g_G + (size_t)bc * 1800;
    for (int idx = tid; idx < 1800; idx += 256) {
        int l = idx / 225, nk = idx % 225;
        int n = nk / 15, k = nk % 15;
        float ax = 0.f, ay = 0.f;
        if (abs(n - 7) <= l) {
            const float* dp = s_d2i0 + l * 225 + n;       // stride 15 over m
            const float2* xp = s_xh2 + l * 225 + k;       // stride 15 over m
            for (int m = 7 - l; m <= 7 + l; ++m) {
                float d = dp[m * 15];
                float2 v = xp[m * 15];
                ax += d * v.x;
                ay += d * v.y;
            }
        }
        gout[idx] = make_float2(ax, ay);
    }
}

// ------------------------- k_dot: out_feat partials ------------------------
// partial[c][ft][b][fl] = sum over 1800 of G[b,c,e].x*w2r[c,f,e] + G.y*w2i
__global__ void k_dot(const float* __restrict__ w2r, const float* __restrict__ w2i) {
    int c  = blockIdx.x;      // 32
    int ft = blockIdx.y;      // 8
    int tid = threadIdx.x;    // 128
    int b = tid >> 3;
    int fl = tid & 7;
    int f = ft * 8 + fl;
    const float4* X4  = (const float4*)(g_G + ((size_t)b * 32 + c) * 1800);   // 900
    const float4* Wr4 = (const float4*)(w2r + ((size_t)c * 64 + f) * 1800);   // 450
    const float4* Wi4 = (const float4*)(w2i + ((size_t)c * 64 + f) * 1800);   // 450
    float a0 = 0.f, a1 = 0.f;
#pragma unroll 2
    for (int i = 0; i < 450; ++i) {
        float4 g0 = X4[2 * i], g1 = X4[2 * i + 1];
        float4 wr = Wr4[i], wi = Wi4[i];
        a0 += g0.x * wr.x + g0.y * wi.x + g0.z * wr.y + g0.w * wi.y;
        a1 += g1.x * wr.z + g1.y * wi.z + g1.z * wr.w + g1.w * wi.w;
    }
    g_partial[(c * 8 + ft) * 128 + tid] = a0 + a1;
}

// ------------------------- head: reduce + conv1d + BN + FC -----------------
__global__ void k_head(const float* __restrict__ w3, const float* __restrict__ b3,
                       const float* __restrict__ gam, const float* __restrict__ bet,
                       const float* __restrict__ fcw, const float* __restrict__ fcb,
                       float* __restrict__ out) {
    __shared__ float s_feat[16 * 64];
    __shared__ float s_r3[16 * 570];
    __shared__ float s_mu[10], s_rstd[10];
    __shared__ float s_ps[160], s_ps2[160];
    int tid = threadIdx.x;    // 256

    // reduce partials: g_partial[c][ft][b][fl] -> s_feat[b][f]
    for (int idx = tid; idx < 1024; idx += 256) {
        int b = idx >> 6;
        int f = idx & 63;
        int ft = f >> 3, fl = f & 7;
        float s = 0.f;
#pragma unroll
        for (int c = 0; c < 32; ++c)
            s += g_partial[(c * 8 + ft) * 128 + (b << 3) + fl];
        s_feat[b * 64 + f] = fmaxf(s, 0.f);
    }
    __syncthreads();

    for (int idx = tid; idx < 9120; idx += 256) {
        int b = idx / 570;
        int r = idx % 570;
        int o = r / 57, t = r % 57;
        float s = b3[o];
#pragma unroll
        for (int k = 0; k < 8; ++k)
            s += w3[o * 8 + k] * s_feat[b * 64 + t + k];
        s_r3[idx] = fmaxf(s, 0.f);
    }
    __syncthreads();

    if (tid < 160) {
        int o = tid >> 4, i = tid & 15;
        float s = 0.f, s2 = 0.f;
        for (int idx2 = i; idx2 < 912; idx2 += 16) {
            int b = idx2 / 57, t = idx2 % 57;
            float v = s_r3[b * 570 + o * 57 + t];
            s += v;
            s2 += v * v;
        }
        s_ps[tid] = s;
        s_ps2[tid] = s2;
    }
    __syncthreads();

    if (tid < 10) {
        float s = 0.f, s2 = 0.f;
#pragma unroll
        for (int i = 0; i < 16; ++i) {
            s += s_ps[tid * 16 + i];
            s2 += s_ps2[tid * 16 + i];
        }
        float mu = s / 912.f;
        float var = s2 / 912.f - mu * mu;
        s_mu[tid] = mu;
        s_rstd[tid] = rsqrtf(var + 1e-5f);
    }
    __syncthreads();

    for (int idx = tid; idx < 9120; idx += 256) {
        int o = (idx % 570) / 57;
        s_r3[idx] = gam[o] * (s_r3[idx] - s_mu[o]) * s_rstd[o] + bet[o];
    }
    __syncthreads();

    if (tid < 160) {
        int b = tid / 10, i = tid % 10;
        float s = fcb[i];
        const float* wr = fcw + i * 570;
        const float* xr = s_r3 + b * 570;
        for (int z = 0; z < 570; ++z) s += xr[z] * wr[z];
        out[b * 10 + i] = s;
    }
}

// ---------------------------------------------------------------------------
extern "C" void kernel_launch(void* const* d_in, const int* in_sizes, int n_in,
                              void* d_out, int out_size) {
    const float* x   = (const float*)d_in[0];
    const float* w1r = (const float*)d_in[1];
    const float* w1i = (const float*)d_in[2];
    const float* w2r = (const float*)d_in[3];
    const float* w2i = (const float*)d_in[4];
    const float* c3w = (const float*)d_in[5];
    const float* c3b = (const float*)d_in[6];
    const float* bng = (const float*)d_in[7];
    const float* bnb = (const float*)d_in[8];
    const float* fcw = (const float*)d_in[9];
    const float* fcb = (const float*)d_in[10];
    float* out = (float*)d_out;

    t_setup<<<1, 64>>>();
    t_tables<<<(599048 + 127) / 128, 128>>>();

    k_xh<<<16 * 31, 64>>>(x);
    k_main<<<16 * 32 * 32, 256>>>(w1r, w1i);
    k_G<<<512, 256>>>();
    k_dot<<<dim3(32, 8), 128>>>(w2r, w2i);
    k_head<<<1, 256>>>(c3w, c3b, bng, bnb, fcw, fcb, out);
}

// round 7
// speedup vs baseline: 3.9501x; 1.1198x over previous
#include <cuda_runtime.h>
#include <math.h>

// ---------------------------------------------------------------------------
// S2ConvNet forward pass, sm_103a.
// Shapes: B=16, F1=32, F2=64, B0=32, B1=16, B2=8, M1=31, M2=15.
// ---------------------------------------------------------------------------

#define PI_D 3.141592653589793238462643383279502884
#define TWOPI_32F 0.19634954084936207f   // 2*pi/32

// ------------------------- static device scratch ---------------------------
__device__ float  g_D1F[16 * 64 * 31];                       // [l][j][m]
__device__ __align__(16) float g_D1I[16 * 32 * 31 * 32];     // [l][j][m][n] n padded
__device__ float  g_D2F[8 * 32 * 15 * 15];                   // [l][j][m][k]
__device__ float  g_D2I0[8 * 15 * 15];                       // [l][m][n]
__device__ float2 g_xh[16 * 16 * 31];                        // [b][l][m]
__device__ __align__(16) float2 g_xmn[16 * 32 * 32 * 225];   // [b][c][j][m][k]
__device__ __align__(16) float2 g_G[16 * 32 * 1800];         // [b][c][l][n][k]
__device__ float  g_partial[32 * 8 * 128];

// beta-grid precompute (incl. tan^2(beta/2))
__device__ double g_cb0[64], g_sb0[64], g_w0[64], g_ts0[64];
__device__ double g_cb1[32], g_sb1[32], g_w1[32], g_ts1[32];
__device__ double g_cb2[16], g_sb2[16], g_ts2[16];

__device__ static const double c_F[32] = {
    1.0, 1.0, 2.0, 6.0, 24.0, 120.0, 720.0, 5040.0, 40320.0, 362880.0,
    3628800.0, 39916800.0, 479001600.0, 6227020800.0, 87178291200.0,
    1307674368000.0, 20922789888000.0, 355687428096000.0, 6402373705728000.0,
    121645100408832000.0, 2432902008176640000.0, 51090942171709440000.0,
    1124000727777607680000.0, 25852016738884976640000.0,
    620448401733239439360000.0, 15511210043330985984000000.0,
    403291461126605635584000000.0, 10888869450418352160768000000.0,
    304888344611713860501504000000.0, 8841761993739701954543616000000.0,
    265252859812191058636308480000000.0, 8222838654177922817725562880000000.0
};

__device__ static const double c_R[32] = {
    0.0, 1.0, 1.0/2.0, 1.0/3.0, 1.0/4.0, 1.0/5.0, 1.0/6.0, 1.0/7.0,
    1.0/8.0, 1.0/9.0, 1.0/10.0, 1.0/11.0, 1.0/12.0, 1.0/13.0, 1.0/14.0,
    1.0/15.0, 1.0/16.0, 1.0/17.0, 1.0/18.0, 1.0/19.0, 1.0/20.0, 1.0/21.0,
    1.0/22.0, 1.0/23.0, 1.0/24.0, 1.0/25.0, 1.0/26.0, 1.0/27.0, 1.0/28.0,
    1.0/29.0, 1.0/30.0, 1.0/31.0
};

__device__ __forceinline__ double ipow_d(double x, int e) {
    double r = 1.0;
    while (e) { if (e & 1) r *= x; x *= x; e >>= 1; }
    return r;
}

__device__ double wig_fast(int l, int m, int n, double cb, double sb, double ts) {
    int kmin = max(0, m - n);
    int kmax = min(l + m, l - n);
    if (kmax < kmin) return 0.0;
    double t = sqrt(c_F[l + m] * c_F[l - m] * c_F[l + n] * c_F[l - n])
             / (c_F[kmin] * c_F[l + m - kmin] * c_F[l - n - kmin] * c_F[n - m + kmin]);
    t *= ipow_d(cb, 2 * l + m - n - 2 * kmin) * ipow_d(sb, n - m + 2 * kmin);
    if (kmin & 1) t = -t;
    double s = t;
    for (int k = kmin; k < kmax; ++k) {
        t *= -((double)((l + m - k) * (l - n - k)) *
               c_R[k + 1] * c_R[n - m + k + 1]) * ts;
        s += t;
    }
    return s;
}

// ------------------------- setup kernel ------------------------------------
__global__ void t_setup() {
    int t = threadIdx.x;   // 64
    if (t < 64) {
        double beta = PI_D * (2.0 * t + 1.0) / 128.0;
        double sb, cb;
        sincos(beta * 0.5, &sb, &cb);
        g_cb0[t] = cb; g_sb0[t] = sb;
        g_ts0[t] = (sb * sb) / (cb * cb);
        double sinb = 2.0 * sb * cb;
        double c2 = 1.0 - 2.0 * sinb * sinb;
        double prev = -sinb, cur = sinb, s = 0.0;
#pragma unroll
        for (int k = 0; k < 32; ++k) {
            s += cur * (1.0 / (2.0 * k + 1.0));
            double nx = 2.0 * c2 * cur - prev;
            prev = cur; cur = nx;
        }
        g_w0[t] = (2.0 / 32.0) * sinb * s;
    }
    if (t < 32) {
        double beta = PI_D * (2.0 * t + 1.0) / 64.0;
        double sb, cb;
        sincos(beta * 0.5, &sb, &cb);
        g_cb1[t] = cb; g_sb1[t] = sb;
        g_ts1[t] = (sb * sb) / (cb * cb);
        double sinb = 2.0 * sb * cb;
        double c2 = 1.0 - 2.0 * sinb * sinb;
        double prev = -sinb, cur = sinb, s = 0.0;
#pragma unroll
        for (int k = 0; k < 16; ++k) {
            s += cur * (1.0 / (2.0 * k + 1.0));
            double nx = 2.0 * c2 * cur - prev;
            prev = cur; cur = nx;
        }
        g_w1[t] = (2.0 / 16.0) * sinb * s;
    }
    if (t < 16) {
        double beta = PI_D * (2.0 * t + 1.0) / 32.0;
        double sb, cb;
        sincos(beta * 0.5, &sb, &cb);
        g_cb2[t] = cb; g_sb2[t] = sb;
        g_ts2[t] = (sb * sb) / (cb * cb);
    }
}

// ------------------------- merged table kernel -----------------------------
__global__ void t_tables() {
    int idx = blockIdx.x * blockDim.x + threadIdx.x;
    if (idx < 31744) {
        int l = idx / (64 * 31);
        int j = (idx / 31) % 64;
        int m = idx % 31;
        int mt = m - 15;
        float v = 0.f;
        if (abs(mt) <= l)
            v = (float)(g_w0[j] * wig_fast(l, mt, 0, g_cb0[j], g_sb0[j], g_ts0[j]));
        g_D1F[idx] = v;
        return;
    }
    idx -= 31744;
    if (idx < 507904) {
        int l = idx / 31744;
        int r = idx % 31744;
        int j = r / 992;
        int m = (r / 32) % 31;
        int n = r % 32;
        int mt = m - 15, nt = n - 15;
        float v = 0.f;
        if (n < 31 && abs(mt) <= l && abs(nt) <= l)
            v = (float)((2.0 * l + 1.0) * wig_fast(l, mt, nt, g_cb1[j], g_sb1[j], g_ts1[j]));
        g_D1I[idx] = v;
        return;
    }
    idx -= 507904;
    if (idx < 57600) {
        int l = idx / (32 * 225);
        int j = (idx / 225) % 32;
        int m = (idx / 15) % 15;
        int n = idx % 15;
        int mt = m - 7, nt = n - 7;
        float v = 0.f;
        if (abs(mt) <= l && abs(nt) <= l)
            v = (float)(g_w1[j] * wig_fast(l, mt, nt, g_cb1[j], g_sb1[j], g_ts1[j]));
        g_D2F[idx] = v;
        return;
    }
    idx -= 57600;
    if (idx < 1800) {
        int l = idx / 225;
        int m = (idx / 15) % 15;
        int n = idx % 15;
        int mt = m - 7, nt = n - 7;
        float v = 0.f;
        if (abs(mt) <= l && abs(nt) <= l)
            v = (float)((2.0 * l + 1.0) * wig_fast(l, mt, nt, g_cb2[0], g_sb2[0], g_ts2[0]));
        g_D2I0[idx] = v;
    }
}

// ------------------------- stage A: x -> xh --------------------------------
__global__ void k_xh(const float* __restrict__ x) {
    __shared__ float2 s_tw[64];
    __shared__ float2 s_xm[64];
    int b = blockIdx.x / 31;
    int m = blockIdx.x % 31;
    int mt = m - 15;
    int j = threadIdx.x;   // 64

    float sj, cj;
    __sincosf((float)j * (6.2831853071795864769f / 64.f), &sj, &cj);
    s_tw[j] = make_float2(cj, sj);
    __syncthreads();

    const float* xr = x + (size_t)(b * 64 + j) * 64;
    float accx = 0.f, accy = 0.f;
#pragma unroll 8
    for (int t = 0; t < 64; ++t) {
        unsigned r = ((unsigned)(mt * t)) & 63u;
        float2 e = s_tw[r];
        float v = xr[t];
        accx += v * e.x;
        accy -= v * e.y;
    }
    s_xm[j] = make_float2(accx, accy);
    __syncthreads();

    if (j < 16) {
        int l = j;
        float ax = 0.f, ay = 0.f;
        const float* dp = g_D1F + (size_t)l * 64 * 31 + m;
#pragma unroll 8
        for (int jj = 0; jj < 64; ++jj) {
            float d = dp[jj * 31];
            float2 v = s_xm[jj];
            ax += d * v.x;
            ay += d * v.y;
        }
        g_xh[(b * 16 + l) * 31 + m] = make_float2(ax, ay);
    }
}

// ------------------------- stage B+C fused plane kernel --------------------
// Even/odd paired DFT stages: each stage sums ±index pairs with precomputed
// sum/diff arrays, halving twiddle work.
__global__ __launch_bounds__(256, 4) void k_main(const float* __restrict__ w1r,
                                                 const float* __restrict__ w1i) {
    __shared__ float2 s_xh[16 * 31];
    __shared__ __align__(16) float2 s_w1[16 * 32];     // n padded to 32
    __shared__ __align__(16) float2 s_buf[1056];       // f[31][34] OR r[32][33]f+u
    __shared__ float2 s_g[31 * 32];
    __shared__ __align__(16) float4 s_p4[31 * 16];     // pairing scratch (7.9KB)

    float2* s_f = s_buf;                 // [m][n] stride 34
    float*  s_r = (float*)s_buf;         // [32][33] floats
    float2* s_u = s_buf + 528;           // [p][d] 32x8
    float2* sp3 = (float2*)s_p4;         // [mt-1][q]  15x32
    float2* sp4 = (float2*)s_p4;         // [p][q-1]   32x15

    int bx = blockIdx.x;
    int b = bx >> 10;
    int f = (bx >> 5) & 31;
    int j = bx & 31;
    int tid = threadIdx.x;

    for (int i = tid; i < 496; i += 256) {
        int l = i / 31, n = i % 31;
        s_xh[i] = g_xh[b * 496 + i];
        s_w1[l * 32 + n] = make_float2(w1r[f * 496 + i], w1i[f * 496 + i]);
    }
    if (tid < 16) s_w1[tid * 32 + 31] = make_float2(0.f, 0.f);
    __syncthreads();

    // step 1: f[m,n] = sum_l D1I[l,j,m,n] * xh[l,m] * conj(w1[l,n])
    if (tid < 248) {
        int m = tid >> 3, ng = tid & 7, n0 = ng * 4;
        int am = abs(m - 15);
        int nhi = n0 + 3;
        int anmin = (nhi < 15) ? (15 - nhi) : ((n0 > 15) ? (n0 - 15) : 0);
        int l0 = max(am, anmin);
        float ax0 = 0.f, ay0 = 0.f, ax1 = 0.f, ay1 = 0.f;
        float ax2 = 0.f, ay2 = 0.f, ax3 = 0.f, ay3 = 0.f;
        const float4* dp4 = (const float4*)(g_D1I + (size_t)j * 992 + m * 32 + n0);
        for (int l = l0; l < 16; ++l) {
            float4 d = dp4[l * 7936];
            float2 a = s_xh[l * 31 + m];
            float4 wA = *(const float4*)(s_w1 + l * 32 + n0);
            float4 wB = *(const float4*)(s_w1 + l * 32 + n0 + 2);
            float tr, ti;
            tr = a.x * wA.x + a.y * wA.y; ti = a.y * wA.x - a.x * wA.y;
            ax0 += d.x * tr; ay0 += d.x * ti;
            tr = a.x * wA.z + a.y * wA.w; ti = a.y * wA.z - a.x * wA.w;
            ax1 += d.y * tr; ay1 += d.y * ti;
            tr = a.x * wB.x + a.y * wB.y; ti = a.y * wB.x - a.x * wB.y;
            ax2 += d.z * tr; ay2 += d.z * ti;
            tr = a.x * wB.z + a.y * wB.w; ti = a.y * wB.z - a.x * wB.w;
            ax3 += d.w * tr; ay3 += d.w * ti;
        }
        *(float4*)(s_f + m * 34 + n0)     = make_float4(ax0, ay0, ax1, ay1);
        *(float4*)(s_f + m * 34 + n0 + 2) = make_float4(ax2, ay2, ax3, ay3);
    }
    __syncthreads();

    // pass A: pair f over nt: s_p4[m][nt] = (Sx, Sy, Dx, Dy); nt=0 -> center
    for (int i = tid; i < 496; i += 256) {
        int m = i >> 4, nt = i & 15;
        float4 v;
        if (nt == 0) {
            float2 c = s_f[m * 34 + 15];
            v = make_float4(c.x, c.y, 0.f, 0.f);
        } else {
            float2 fp = s_f[m * 34 + 15 + nt];
            float2 fm = s_f[m * 34 + 15 - nt];
            v = make_float4(fp.x + fm.x, fp.y + fm.y, fp.x - fm.x, fp.y - fm.y);
        }
        s_p4[m * 16 + nt] = v;
    }
    __syncthreads();

    // step 2: g[m,q] = sum_nt pair-terms, 4-way q blocking (q0, +8, +16, +24)
    if (tid < 248) {
        int m = tid >> 3, q0 = tid & 7;
        float2 S, E;
        __sincosf((float)q0 * TWOPI_32F, &S.y, &S.x);
        E = S;     // nt = 1
        const float4* prow = s_p4 + m * 16;
        float4 c0 = prow[0];
        float a0x = c0.x, a0y = c0.y, a1x = c0.x, a1y = c0.y;
        float a2x = c0.x, a2y = c0.y, a3x = c0.x, a3y = c0.y;
        int nt = 1;
#define S2P(PP)                                                              \
        {                                                                    \
            float4 pr = prow[nt];                                            \
            float p1 = E.x * pr.x, p2 = E.y * pr.w;                          \
            float p3 = E.x * pr.y, p4 = E.y * pr.z;                          \
            float tx = p1 - p2, ty = p3 + p4;                                \
            a0x += tx; a0y += ty;                                            \
            if (PP == 0) { a1x += tx; a1y += ty; a2x += tx; a2y += ty;       \
                           a3x += tx; a3y += ty; }                           \
            if (PP == 2) { a1x -= tx; a1y -= ty; a2x += tx; a2y += ty;       \
                           a3x -= tx; a3y -= ty; }                           \
            if (PP == 1 || PP == 3) {                                        \
                float r1 = E.y * pr.x, r2 = E.x * pr.w;                      \
                float r3 = E.y * pr.y, r4 = E.x * pr.z;                      \
                float ux = r1 + r2, uy = r3 - r4;                            \
                if (PP == 1) { a1x -= ux; a1y -= uy; a2x -= tx; a2y -= ty;   \
                               a3x += ux; a3y += uy; }                       \
                if (PP == 3) { a1x += ux; a1y += uy; a2x -= tx; a2y -= ty;   \
                               a3x -= ux; a3y -= uy; }                       \
            }                                                                \
            float ex = E.x * S.x - E.y * S.y;                                \
            E.y = E.x * S.y + E.y * S.x;                                     \
            E.x = ex;                                                        \
            ++nt;                                                            \
        }
#pragma unroll
        for (int g4 = 0; g4 < 3; ++g4) {   // nt = 1..12
            S2P(1) S2P(2) S2P(3) S2P(0)
        }
        S2P(1) S2P(2) S2P(3)               // nt = 13,14,15
#undef S2P
        s_g[m * 32 + q0]      = make_float2(a0x, a0y);
        s_g[m * 32 + q0 + 8]  = make_float2(a1x, a1y);
        s_g[m * 32 + q0 + 16] = make_float2(a2x, a2y);
        s_g[m * 32 + q0 + 24] = make_float2(a3x, a3y);
    }
    __syncthreads();

    // pass B: pair g over mt: sp3[mt-1][q] = (P, Q)
    for (int i = tid; i < 480; i += 256) {
        int mt = 1 + (i >> 5), q = i & 31;
        float2 gp = s_g[(15 + mt) * 32 + q];
        float2 gm = s_g[(15 - mt) * 32 + q];
        sp3[(mt - 1) * 32 + q] = make_float2(gp.x + gm.x, gp.y - gm.y);
    }
    __syncthreads();

    // step 3: r[p,q] = relu(center + sum_mt (E.x*P - E.y*Q)), 4-way p blocking
    {
        int q = tid & 31, p0 = tid >> 5;
        float2 S, E;
        __sincosf((float)p0 * TWOPI_32F, &S.y, &S.x);
        E = S;     // mt = 1
        float c = s_g[15 * 32 + q].x;
        float a0 = c, a1 = c, a2 = c, a3 = c;
        const float2* pcol = sp3 + q;
        int mt = 1;
#define S3P(PP)                                                              \
        {                                                                    \
            float2 v = pcol[(mt - 1) * 32];                                  \
            float u1 = E.x * v.x, u2 = E.y * v.y;                            \
            float tx = u1 - u2;                                              \
            a0 += tx;                                                        \
            if (PP == 0) { a1 += tx; a2 += tx; a3 += tx; }                   \
            if (PP == 2) { a1 -= tx; a2 += tx; a3 -= tx; }                   \
            if (PP == 1 || PP == 3) {                                        \
                float v1 = E.y * v.x, v2 = E.x * v.y;                        \
                float ux = v1 + v2;                                          \
                if (PP == 1) { a1 -= ux; a2 -= tx; a3 += ux; }               \
                if (PP == 3) { a1 += ux; a2 -= tx; a3 -= ux; }               \
            }                                                                \
            float ex = E.x * S.x - E.y * S.y;                                \
            E.y = E.x * S.y + E.y * S.x;                                     \
            E.x = ex;                                                        \
            ++mt;                                                            \
        }
#pragma unroll
        for (int g4 = 0; g4 < 3; ++g4) {
            S3P(1) S3P(2) S3P(3) S3P(0)
        }
        S3P(1) S3P(2) S3P(3)
#undef S3P
        s_r[p0 * 33 + q]        = fmaxf(a0, 0.f);
        s_r[(p0 + 8) * 33 + q]  = fmaxf(a1, 0.f);
        s_r[(p0 + 16) * 33 + q] = fmaxf(a2, 0.f);
        s_r[(p0 + 24) * 33 + q] = fmaxf(a3, 0.f);
    }
    __syncthreads();

    // pass C: pair r over q: sp4[p][q-1] = (r_q + r_{32-q}, r_q - r_{32-q})
    for (int i = tid; i < 480; i += 256) {
        int p = i / 15, qm1 = i % 15;
        float a = s_r[p * 33 + qm1 + 1];
        float bb = s_r[p * 33 + 31 - qm1];
        sp4[p * 15 + qm1] = make_float2(a + bb, a - bb);
    }
    __syncthreads();

    // step 4: u[p,d] = r0 + (-1)^d r16 + sum_q (S*W.x, D*W.y), d = 0..7
    {
        int p = tid >> 3, d = tid & 7;
        float2 W1;
        __sincosf((float)d * TWOPI_32F, &W1.y, &W1.x);
        W1.y = -W1.y;
        float2 W = W1;
        float r0 = s_r[p * 33];
        float r16 = s_r[p * 33 + 16];
        float ax = r0 + ((d & 1) ? -r16 : r16);
        float ay = 0.f;
        const float2* sd = sp4 + p * 15;
#pragma unroll
        for (int q = 1; q <= 15; ++q) {
            float2 v = sd[q - 1];
            ax += v.x * W.x;
            ay += v.y * W.y;
            float wx = W.x * W1.x - W.y * W1.y;
            W.y = W.x * W1.y + W.y * W1.x;
            W.x = wx;
        }
        s_u[p * 8 + d] = make_float2(ax, ay);
    }
    __syncthreads();

    // step 5 (Hermitian half): n2 = 7+d, all m2; mirror to (14-m2, 14-n2)
    if (tid < 120) {
        int m2 = tid >> 3, d = tid & 7;
        int n2 = 7 + d;
        int mt = m2 - 7;
        float2 W = make_float2(1.f, 0.f), S5;
        {
            float ss, cc;
            __sincosf((float)mt * TWOPI_32F, &ss, &cc);
            S5 = make_float2(cc, -ss);
        }
        float ax = 0.f, ay = 0.f;
        const float2* ucol = s_u + d;
#pragma unroll
        for (int p = 0; p < 32; ++p) {
            float2 u = ucol[p * 8];
            ax += u.x * W.x - u.y * W.y;
            ay += u.x * W.y + u.y * W.x;
            float wx = W.x * S5.x - W.y * S5.y;
            W.y = W.x * S5.y + W.y * S5.x;
            W.x = wx;
        }
        float2* outp = g_xmn + (size_t)bx * 225;
        outp[m2 * 15 + n2] = make_float2(ax, ay);
        if (d > 0)
            outp[(14 - m2) * 15 + (14 - n2)] = make_float2(ax, -ay);
    }
}

// ------------------------- k_G: xmn -> xh2 -> G (per (b,c)) ----------------
__global__ __launch_bounds__(256) void k_G() {
    __shared__ float2 s_xh2[8 * 225];
    __shared__ float  s_d2i0[1800];
    int bc = blockIdx.x;    // b*32 + c
    int tid = threadIdx.x;  // 256

    for (int i = tid; i < 1800; i += 256) s_d2i0[i] = g_D2I0[i];

    if (tid < 225) {
        int mk = tid;
        float2 acc[8];
#pragma unroll
        for (int l = 0; l < 8; ++l) acc[l] = make_float2(0.f, 0.f);
        const float2* xp = g_xmn + (size_t)bc * 7200 + mk;
        const float* dp = g_D2F + mk;
#pragma unroll 4
        for (int j = 0; j < 32; ++j) {
            float2 xv = xp[j * 225];
#pragma unroll
            for (int l = 0; l < 8; ++l) {
                float d = dp[l * 7200 + j * 225];
                acc[l].x += d * xv.x;
                acc[l].y += d * xv.y;
            }
        }
#pragma unroll
        for (int l = 0; l < 8; ++l) s_xh2[l * 225 + mk] = acc[l];
    }
    __syncthreads();

    float2* gout = g_G + (size_t)bc * 1800;
    for (int idx = tid; idx < 1800; idx += 256) {
        int l = idx / 225, nk = idx % 225;
        int n = nk / 15, k = nk % 15;
        float ax = 0.f, ay = 0.f;
        if (abs(n - 7) <= l) {
            const float* dp = s_d2i0 + l * 225 + n;
            const float2* xp = s_xh2 + l * 225 + k;
            for (int m = 7 - l; m <= 7 + l; ++m) {
                float d = dp[m * 15];
                float2 v = xp[m * 15];
                ax += d * v.x;
                ay += d * v.y;
            }
        }
        gout[idx] = make_float2(ax, ay);
    }
}

// ------------------------- k_dot: out_feat partials ------------------------
__global__ void k_dot(const float* __restrict__ w2r, const float* __restrict__ w2i) {
    int c  = blockIdx.x;      // 32
    int ft = blockIdx.y;      // 8
    int tid = threadIdx.x;    // 128
    int b = tid >> 3;
    int fl = tid & 7;
    int f = ft * 8 + fl;
    const float4* X4  = (const float4*)(g_G + ((size_t)b * 32 + c) * 1800);
    const float4* Wr4 = (const float4*)(w2r + ((size_t)c * 64 + f) * 1800);
    const float4* Wi4 = (const float4*)(w2i + ((size_t)c * 64 + f) * 1800);
    float a0 = 0.f, a1 = 0.f;
#pragma unroll 2
    for (int i = 0; i < 450; ++i) {
        float4 g0 = X4[2 * i], g1 = X4[2 * i + 1];
        float4 wr = Wr4[i], wi = Wi4[i];
        a0 += g0.x * wr.x + g0.y * wi.x + g0.z * wr.y + g0.w * wi.y;
        a1 += g1.x * wr.z + g1.y * wi.z + g1.z * wr.w + g1.w * wi.w;
    }
    g_partial[(c * 8 + ft) * 128 + tid] = a0 + a1;
}

// ------------------------- head: reduce + conv1d + BN + FC -----------------
__global__ void k_head(const float* __restrict__ w3, const float* __restrict__ b3,
                       const float* __restrict__ gam, const float* __restrict__ bet,
                       const float* __restrict__ fcw, const float* __restrict__ fcb,
                       float* __restrict__ out) {
    __shared__ float s_feat[16 * 64];
    __shared__ float s_r3[16 * 570];
    __shared__ float s_mu[10], s_rstd[10];
    __shared__ float s_ps[160], s_ps2[160];
    int tid = threadIdx.x;    // 256

    for (int idx = tid; idx < 1024; idx += 256) {
        int b = idx >> 6;
        int f = idx & 63;
        int ft = f >> 3, fl = f & 7;
        float s = 0.f;
#pragma unroll
        for (int c = 0; c < 32; ++c)
            s += g_partial[(c * 8 + ft) * 128 + (b << 3) + fl];
        s_feat[b * 64 + f] = fmaxf(s, 0.f);
    }
    __syncthreads();

    for (int idx = tid; idx < 9120; idx += 256) {
        int b = idx / 570;
        int r = idx % 570;
        int o = r / 57, t = r % 57;
        float s = b3[o];
#pragma unroll
        for (int k = 0; k < 8; ++k)
            s += w3[o * 8 + k] * s_feat[b * 64 + t + k];
        s_r3[idx] = fmaxf(s, 0.f);
    }
    __syncthreads();

    if (tid < 160) {
        int o = tid >> 4, i = tid & 15;
        float s = 0.f, s2 = 0.f;
        for (int idx2 = i; idx2 < 912; idx2 += 16) {
            int b = idx2 / 57, t = idx2 % 57;
            float v = s_r3[b * 570 + o * 57 + t];
            s += v;
            s2 += v * v;
        }
        s_ps[tid] = s;
        s_ps2[tid] = s2;
    }
    __syncthreads();

    if (tid < 10) {
        float s = 0.f, s2 = 0.f;
#pragma unroll
        for (int i = 0; i < 16; ++i) {
            s += s_ps[tid * 16 + i];
            s2 += s_ps2[tid * 16 + i];
        }
        float mu = s / 912.f;
        float var = s2 / 912.f - mu * mu;
        s_mu[tid] = mu;
        s_rstd[tid] = rsqrtf(var + 1e-5f);
    }
    __syncthreads();

    for (int idx = tid; idx < 9120; idx += 256) {
        int o = (idx % 570) / 57;
        s_r3[idx] = gam[o] * (s_r3[idx] - s_mu[o]) * s_rstd[o] + bet[o];
    }
    __syncthreads();

    if (tid < 160) {
        int b = tid / 10, i = tid % 10;
        float s = fcb[i];
        const float* wr = fcw + i * 570;
        const float* xr = s_r3 + b * 570;
        for (int z = 0; z < 570; ++z) s += xr[z] * wr[z];
        out[b * 10 + i] = s;
    }
}

// ---------------------------------------------------------------------------
extern "C" void kernel_launch(void* const* d_in, const int* in_sizes, int n_in,
                              void* d_out, int out_size) {
    const float* x   = (const float*)d_in[0];
    const float* w1r = (const float*)d_in[1];
    const float* w1i = (const float*)d_in[2];
    const float* w2r = (const float*)d_in[3];
    const float* w2i = (const float*)d_in[4];
    const float* c3w = (const float*)d_in[5];
    const float* c3b = (const float*)d_in[6];
    const float* bng = (const float*)d_in[7];
    const float* bnb = (const float*)d_in[8];
    const float* fcw = (const float*)d_in[9];
    const float* fcb = (const float*)d_in[10];
    float* out = (float*)d_out;

    t_setup<<<1, 64>>>();
    t_tables<<<(599048 + 127) / 128, 128>>>();

    k_xh<<<16 * 31, 64>>>(x);
    k_main<<<16 * 32 * 32, 256>>>(w1r, w1i);
    k_G<<<512, 256>>>();
    k_dot<<<dim3(32, 8), 128>>>(w2r, w2i);
    k_head<<<1, 256>>>(c3w, c3b, bng, bnb, fcw, fcb, out);
}

// round 8
// speedup vs baseline: 4.1813x; 1.0585x over previous
#include <cuda_runtime.h>
#include <math.h>

// ---------------------------------------------------------------------------
// S2ConvNet forward pass, sm_103a.
// Shapes: B=16, F1=32, F2=64, B0=32, B1=16, B2=8, M1=31, M2=15.
// ---------------------------------------------------------------------------

#define PI_D 3.141592653589793238462643383279502884
#define TWOPI_32F 0.19634954084936207f   // 2*pi/32

// ------------------------- static device scratch ---------------------------
__device__ float  g_D1F[16 * 64 * 31];                       // [l][j][m]
__device__ __align__(16) float g_D1I[16 * 32 * 31 * 32];     // [l][j][m][n] n padded
__device__ float  g_D2F[8 * 32 * 15 * 15];                   // [l][j][m][k]
__device__ float  g_D2I0[8 * 15 * 15];                       // [l][m][n]
__device__ float2 g_xh[16 * 16 * 31];                        // [b][l][m]
__device__ __align__(16) float2 g_xmn[16 * 32 * 32 * 225];   // [b][c][j][m][k]
__device__ __align__(16) float2 g_G[16 * 32 * 1800];         // [b][c][l][n][k]
__device__ float  g_partial[32 * 8 * 128];

// beta-grid precompute (incl. tan^2(beta/2))
__device__ double g_cb0[64], g_sb0[64], g_w0[64], g_ts0[64];
__device__ double g_cb1[32], g_sb1[32], g_w1[32], g_ts1[32];
__device__ double g_cb2[16], g_sb2[16], g_ts2[16];

__device__ static const double c_F[32] = {
    1.0, 1.0, 2.0, 6.0, 24.0, 120.0, 720.0, 5040.0, 40320.0, 362880.0,
    3628800.0, 39916800.0, 479001600.0, 6227020800.0, 87178291200.0,
    1307674368000.0, 20922789888000.0, 355687428096000.0, 6402373705728000.0,
    121645100408832000.0, 2432902008176640000.0, 51090942171709440000.0,
    1124000727777607680000.0, 25852016738884976640000.0,
    620448401733239439360000.0, 15511210043330985984000000.0,
    403291461126605635584000000.0, 10888869450418352160768000000.0,
    304888344611713860501504000000.0, 8841761993739701954543616000000.0,
    265252859812191058636308480000000.0, 8222838654177922817725562880000000.0
};

__device__ static const double c_R[32] = {
    0.0, 1.0, 1.0/2.0, 1.0/3.0, 1.0/4.0, 1.0/5.0, 1.0/6.0, 1.0/7.0,
    1.0/8.0, 1.0/9.0, 1.0/10.0, 1.0/11.0, 1.0/12.0, 1.0/13.0, 1.0/14.0,
    1.0/15.0, 1.0/16.0, 1.0/17.0, 1.0/18.0, 1.0/19.0, 1.0/20.0, 1.0/21.0,
    1.0/22.0, 1.0/23.0, 1.0/24.0, 1.0/25.0, 1.0/26.0, 1.0/27.0, 1.0/28.0,
    1.0/29.0, 1.0/30.0, 1.0/31.0
};

__device__ __forceinline__ double ipow_d(double x, int e) {
    double r = 1.0;
    while (e) { if (e & 1) r *= x; x *= x; e >>= 1; }
    return r;
}

__device__ double wig_fast(int l, int m, int n, double cb, double sb, double ts) {
    int kmin = max(0, m - n);
    int kmax = min(l + m, l - n);
    if (kmax < kmin) return 0.0;
    double t = sqrt(c_F[l + m] * c_F[l - m] * c_F[l + n] * c_F[l - n])
             / (c_F[kmin] * c_F[l + m - kmin] * c_F[l - n - kmin] * c_F[n - m + kmin]);
    t *= ipow_d(cb, 2 * l + m - n - 2 * kmin) * ipow_d(sb, n - m + 2 * kmin);
    if (kmin & 1) t = -t;
    double s = t;
    for (int k = kmin; k < kmax; ++k) {
        t *= -((double)((l + m - k) * (l - n - k)) *
               c_R[k + 1] * c_R[n - m + k + 1]) * ts;
        s += t;
    }
    return s;
}

// ------------------------- setup kernel ------------------------------------
__global__ void t_setup() {
    int t = threadIdx.x;   // 64
    if (t < 64) {
        double beta = PI_D * (2.0 * t + 1.0) / 128.0;
        double sb, cb;
        sincos(beta * 0.5, &sb, &cb);
        g_cb0[t] = cb; g_sb0[t] = sb;
        g_ts0[t] = (sb * sb) / (cb * cb);
        double sinb = 2.0 * sb * cb;
        double c2 = 1.0 - 2.0 * sinb * sinb;
        double prev = -sinb, cur = sinb, s = 0.0;
#pragma unroll
        for (int k = 0; k < 32; ++k) {
            s += cur * (1.0 / (2.0 * k + 1.0));
            double nx = 2.0 * c2 * cur - prev;
            prev = cur; cur = nx;
        }
        g_w0[t] = (2.0 / 32.0) * sinb * s;
    }
    if (t < 32) {
        double beta = PI_D * (2.0 * t + 1.0) / 64.0;
        double sb, cb;
        sincos(beta * 0.5, &sb, &cb);
        g_cb1[t] = cb; g_sb1[t] = sb;
        g_ts1[t] = (sb * sb) / (cb * cb);
        double sinb = 2.0 * sb * cb;
        double c2 = 1.0 - 2.0 * sinb * sinb;
        double prev = -sinb, cur = sinb, s = 0.0;
#pragma unroll
        for (int k = 0; k < 16; ++k) {
            s += cur * (1.0 / (2.0 * k + 1.0));
            double nx = 2.0 * c2 * cur - prev;
            prev = cur; cur = nx;
        }
        g_w1[t] = (2.0 / 16.0) * sinb * s;
    }
    if (t < 16) {
        double beta = PI_D * (2.0 * t + 1.0) / 32.0;
        double sb, cb;
        sincos(beta * 0.5, &sb, &cb);
        g_cb2[t] = cb; g_sb2[t] = sb;
        g_ts2[t] = (sb * sb) / (cb * cb);
    }
}

// ------------------------- merged table kernel -----------------------------
__global__ void t_tables() {
    int idx = blockIdx.x * blockDim.x + threadIdx.x;
    if (idx < 31744) {
        int l = idx / (64 * 31);
        int j = (idx / 31) % 64;
        int m = idx % 31;
        int mt = m - 15;
        float v = 0.f;
        if (abs(mt) <= l)
            v = (float)(g_w0[j] * wig_fast(l, mt, 0, g_cb0[j], g_sb0[j], g_ts0[j]));
        g_D1F[idx] = v;
        return;
    }
    idx -= 31744;
    if (idx < 507904) {
        int l = idx / 31744;
        int r = idx % 31744;
        int j = r / 992;
        int m = (r / 32) % 31;
        int n = r % 32;
        int mt = m - 15, nt = n - 15;
        float v = 0.f;
        if (n < 31 && abs(mt) <= l && abs(nt) <= l)
            v = (float)((2.0 * l + 1.0) * wig_fast(l, mt, nt, g_cb1[j], g_sb1[j], g_ts1[j]));
        g_D1I[idx] = v;
        return;
    }
    idx -= 507904;
    if (idx < 57600) {
        int l = idx / (32 * 225);
        int j = (idx / 225) % 32;
        int m = (idx / 15) % 15;
        int n = idx % 15;
        int mt = m - 7, nt = n - 7;
        float v = 0.f;
        if (abs(mt) <= l && abs(nt) <= l)
            v = (float)(g_w1[j] * wig_fast(l, mt, nt, g_cb1[j], g_sb1[j], g_ts1[j]));
        g_D2F[idx] = v;
        return;
    }
    idx -= 57600;
    if (idx < 1800) {
        int l = idx / 225;
        int m = (idx / 15) % 15;
        int n = idx % 15;
        int mt = m - 7, nt = n - 7;
        float v = 0.f;
        if (abs(mt) <= l && abs(nt) <= l)
            v = (float)((2.0 * l + 1.0) * wig_fast(l, mt, nt, g_cb2[0], g_sb2[0], g_ts2[0]));
        g_D2I0[idx] = v;
    }
}

// ------------------------- stage A: x -> xh --------------------------------
__global__ void k_xh(const float* __restrict__ x) {
    __shared__ float2 s_tw[64];
    __shared__ float2 s_xm[64];
    int b = blockIdx.x / 31;
    int m = blockIdx.x % 31;
    int mt = m - 15;
    int j = threadIdx.x;   // 64

    float sj, cj;
    __sincosf((float)j * (6.2831853071795864769f / 64.f), &sj, &cj);
    s_tw[j] = make_float2(cj, sj);
    __syncthreads();

    const float* xr = x + (size_t)(b * 64 + j) * 64;
    float accx = 0.f, accy = 0.f;
#pragma unroll 8
    for (int t = 0; t < 64; ++t) {
        unsigned r = ((unsigned)(mt * t)) & 63u;
        float2 e = s_tw[r];
        float v = xr[t];
        accx += v * e.x;
        accy -= v * e.y;
    }
    s_xm[j] = make_float2(accx, accy);
    __syncthreads();

    if (j < 16) {
        int l = j;
        float ax = 0.f, ay = 0.f;
        const float* dp = g_D1F + (size_t)l * 64 * 31 + m;
#pragma unroll 8
        for (int jj = 0; jj < 64; ++jj) {
            float d = dp[jj * 31];
            float2 v = s_xm[jj];
            ax += d * v.x;
            ay += d * v.y;
        }
        g_xh[(b * 16 + l) * 31 + m] = make_float2(ax, ay);
    }
}

// ------------------------- stage B+C fused plane kernel --------------------
__global__ __launch_bounds__(256, 4) void k_main(const float* __restrict__ w1r,
                                                 const float* __restrict__ w1i) {
    __shared__ float2 s_xh[16 * 31];
    __shared__ __align__(16) float2 s_w1[16 * 32];     // n padded to 32
    __shared__ __align__(16) float2 s_buf[1056];       // f[31][34] THEN sp4+u
    __shared__ float2 s_g[31 * 32];
    __shared__ __align__(16) float4 s_p4[31 * 16];     // pairing scratch
    __shared__ float  s_r016[64];                      // r[p][0], r[p][16]

    float2* s_f = s_buf;                 // [m][n] stride 34 (phase 1)
    float2* sp4 = s_buf;                 // [p][qm1] stride 17 (phase 2, 544 f2)
    float2* s_u = s_buf + 560;           // [p][d] 32x8 (phase 2)
    float2* sp3 = (float2*)s_p4;         // [mt-1][q]  15x32

    int bx = blockIdx.x;
    int b = bx >> 10;
    int f = (bx >> 5) & 31;
    int j = bx & 31;
    int tid = threadIdx.x;

    for (int i = tid; i < 496; i += 256) {
        int l = i / 31, n = i % 31;
        s_xh[i] = g_xh[b * 496 + i];
        s_w1[l * 32 + n] = make_float2(w1r[f * 496 + i], w1i[f * 496 + i]);
    }
    if (tid < 16) s_w1[tid * 32 + 31] = make_float2(0.f, 0.f);
    __syncthreads();

    // step 1: f[m,n] = sum_l D1I[l,j,m,n] * xh[l,m] * conj(w1[l,n])
    if (tid < 248) {
        int m = tid >> 3, ng = tid & 7, n0 = ng * 4;
        int am = abs(m - 15);
        int nhi = n0 + 3;
        int anmin = (nhi < 15) ? (15 - nhi) : ((n0 > 15) ? (n0 - 15) : 0);
        int l0 = max(am, anmin);
        float ax0 = 0.f, ay0 = 0.f, ax1 = 0.f, ay1 = 0.f;
        float ax2 = 0.f, ay2 = 0.f, ax3 = 0.f, ay3 = 0.f;
        const float4* dp4 = (const float4*)(g_D1I + (size_t)j * 992 + m * 32 + n0);
        for (int l = l0; l < 16; ++l) {
            float4 d = dp4[l * 7936];
            float2 a = s_xh[l * 31 + m];
            float4 wA = *(const float4*)(s_w1 + l * 32 + n0);
            float4 wB = *(const float4*)(s_w1 + l * 32 + n0 + 2);
            float tr, ti;
            tr = a.x * wA.x + a.y * wA.y; ti = a.y * wA.x - a.x * wA.y;
            ax0 += d.x * tr; ay0 += d.x * ti;
            tr = a.x * wA.z + a.y * wA.w; ti = a.y * wA.z - a.x * wA.w;
            ax1 += d.y * tr; ay1 += d.y * ti;
            tr = a.x * wB.x + a.y * wB.y; ti = a.y * wB.x - a.x * wB.y;
            ax2 += d.z * tr; ay2 += d.z * ti;
            tr = a.x * wB.z + a.y * wB.w; ti = a.y * wB.z - a.x * wB.w;
            ax3 += d.w * tr; ay3 += d.w * ti;
        }
        *(float4*)(s_f + m * 34 + n0)     = make_float4(ax0, ay0, ax1, ay1);
        *(float4*)(s_f + m * 34 + n0 + 2) = make_float4(ax2, ay2, ax3, ay3);
    }
    __syncthreads();

    // pass A: pair f over nt: s_p4[m][nt] = (Sx, Sy, Dx, Dy); nt=0 -> center
    for (int i = tid; i < 496; i += 256) {
        int m = i >> 4, nt = i & 15;
        float4 v;
        if (nt == 0) {
            float2 c = s_f[m * 34 + 15];
            v = make_float4(c.x, c.y, 0.f, 0.f);
        } else {
            float2 fp = s_f[m * 34 + 15 + nt];
            float2 fm = s_f[m * 34 + 15 - nt];
            v = make_float4(fp.x + fm.x, fp.y + fm.y, fp.x - fm.x, fp.y - fm.y);
        }
        s_p4[m * 16 + nt] = v;
    }
    __syncthreads();

    // step 2: g[m,q] = sum_nt pair-terms, 4-way q blocking (q0, +8, +16, +24)
    if (tid < 248) {
        int m = tid >> 3, q0 = tid & 7;
        float2 S, E;
        __sincosf((float)q0 * TWOPI_32F, &S.y, &S.x);
        E = S;     // nt = 1
        const float4* prow = s_p4 + m * 16;
        float4 c0 = prow[0];
        float a0x = c0.x, a0y = c0.y, a1x = c0.x, a1y = c0.y;
        float a2x = c0.x, a2y = c0.y, a3x = c0.x, a3y = c0.y;
        int nt = 1;
#define S2P(PP)                                                              \
        {                                                                    \
            float4 pr = prow[nt];                                            \
            float p1 = E.x * pr.x, p2 = E.y * pr.w;                          \
            float p3 = E.x * pr.y, p4 = E.y * pr.z;                          \
            float tx = p1 - p2, ty = p3 + p4;                                \
            a0x += tx; a0y += ty;                                            \
            if (PP == 0) { a1x += tx; a1y += ty; a2x += tx; a2y += ty;       \
                           a3x += tx; a3y += ty; }                           \
            if (PP == 2) { a1x -= tx; a1y -= ty; a2x += tx; a2y += ty;       \
                           a3x -= tx; a3y -= ty; }                           \
            if (PP == 1 || PP == 3) {                                        \
                float r1 = E.y * pr.x, r2 = E.x * pr.w;                      \
                float r3 = E.y * pr.y, r4 = E.x * pr.z;                      \
                float ux = r1 + r2, uy = r3 - r4;                            \
                if (PP == 1) { a1x -= ux; a1y -= uy; a2x -= tx; a2y -= ty;   \
                               a3x += ux; a3y += uy; }                       \
                if (PP == 3) { a1x += ux; a1y += uy; a2x -= tx; a2y -= ty;   \
                               a3x -= ux; a3y -= uy; }                       \
            }                                                                \
            float ex = E.x * S.x - E.y * S.y;                                \
            E.y = E.x * S.y + E.y * S.x;                                     \
            E.x = ex;                                                        \
            ++nt;                                                            \
        }
#pragma unroll
        for (int g4 = 0; g4 < 3; ++g4) {   // nt = 1..12
            S2P(1) S2P(2) S2P(3) S2P(0)
        }
        S2P(1) S2P(2) S2P(3)               // nt = 13,14,15
#undef S2P
        s_g[m * 32 + q0]      = make_float2(a0x, a0y);
        s_g[m * 32 + q0 + 8]  = make_float2(a1x, a1y);
        s_g[m * 32 + q0 + 16] = make_float2(a2x, a2y);
        s_g[m * 32 + q0 + 24] = make_float2(a3x, a3y);
    }
    __syncthreads();

    // pass B: pair g over mt: sp3[mt-1][q] = (P, Q)
    for (int i = tid; i < 480; i += 256) {
        int mt = 1 + (i >> 5), q = i & 31;
        float2 gp = s_g[(15 + mt) * 32 + q];
        float2 gm = s_g[(15 - mt) * 32 + q];
        sp3[(mt - 1) * 32 + q] = make_float2(gp.x + gm.x, gp.y - gm.y);
    }
    __syncthreads();

    // step 3: r[p,q] = relu(center + sum_mt (E.x*P - E.y*Q)), 4-way p blocking
    // then in-warp pairing over q (pass C fused via shuffle).
    {
        int q = tid & 31, p0 = tid >> 5;
        float2 S, E;
        __sincosf((float)p0 * TWOPI_32F, &S.y, &S.x);
        E = S;     // mt = 1
        float c = s_g[15 * 32 + q].x;
        float a0 = c, a1 = c, a2 = c, a3 = c;
        const float2* pcol = sp3 + q;
        int mt = 1;
#define S3P(PP)                                                              \
        {                                                                    \
            float2 v = pcol[(mt - 1) * 32];                                  \
            float u1 = E.x * v.x, u2 = E.y * v.y;                            \
            float tx = u1 - u2;                                              \
            a0 += tx;                                                        \
            if (PP == 0) { a1 += tx; a2 += tx; a3 += tx; }                   \
            if (PP == 2) { a1 -= tx; a2 += tx; a3 -= tx; }                   \
            if (PP == 1 || PP == 3) {                                        \
                float v1 = E.y * v.x, v2 = E.x * v.y;                        \
                float ux = v1 + v2;                                          \
                if (PP == 1) { a1 -= ux; a2 -= tx; a3 += ux; }               \
                if (PP == 3) { a1 += ux; a2 -= tx; a3 -= ux; }               \
            }                                                                \
            float ex = E.x * S.x - E.y * S.y;                                \
            E.y = E.x * S.y + E.y * S.x;                                     \
            E.x = ex;                                                        \
            ++mt;                                                            \
        }
#pragma unroll
        for (int g4 = 0; g4 < 3; ++g4) {
            S3P(1) S3P(2) S3P(3) S3P(0)
        }
        S3P(1) S3P(2) S3P(3)
#undef S3P
        a0 = fmaxf(a0, 0.f);
        a1 = fmaxf(a1, 0.f);
        a2 = fmaxf(a2, 0.f);
        a3 = fmaxf(a3, 0.f);
        // partner lane (32-q)&31 holds r[p][32-q]
        int src = (32 - q) & 31;
        float b0 = __shfl_sync(0xffffffffu, a0, src);
        float b1 = __shfl_sync(0xffffffffu, a1, src);
        float b2 = __shfl_sync(0xffffffffu, a2, src);
        float b3 = __shfl_sync(0xffffffffu, a3, src);
        __syncthreads();   // sp3/s_g reads complete before s_buf reuse
        if (q >= 1 && q <= 15) {
            int qm1 = q - 1;
            sp4[p0 * 17 + qm1]        = make_float2(a0 + b0, a0 - b0);
            sp4[(p0 + 8) * 17 + qm1]  = make_float2(a1 + b1, a1 - b1);
            sp4[(p0 + 16) * 17 + qm1] = make_float2(a2 + b2, a2 - b2);
            sp4[(p0 + 24) * 17 + qm1] = make_float2(a3 + b3, a3 - b3);
        } else if (q == 0) {
            s_r016[p0]      = a0;
            s_r016[p0 + 8]  = a1;
            s_r016[p0 + 16] = a2;
            s_r016[p0 + 24] = a3;
        } else if (q == 16) {
            s_r016[32 + p0]      = a0;
            s_r016[32 + p0 + 8]  = a1;
            s_r016[32 + p0 + 16] = a2;
            s_r016[32 + p0 + 24] = a3;
        }
    }
    __syncthreads();

    // step 4: u[p,d] = r0 + (-1)^d r16 + sum_q (S*W.x, D*W.y), d = 0..7
    {
        int p = tid >> 3, d = tid & 7;
        float2 W1;
        __sincosf((float)d * TWOPI_32F, &W1.y, &W1.x);
        W1.y = -W1.y;
        float2 W = W1;
        float r0 = s_r016[p];
        float r16 = s_r016[32 + p];
        float ax = r0 + ((d & 1) ? -r16 : r16);
        float ay = 0.f;
        const float2* sd = sp4 + p * 17;
#pragma unroll
        for (int q = 1; q <= 15; ++q) {
            float2 v = sd[q - 1];
            ax += v.x * W.x;
            ay += v.y * W.y;
            float wx = W.x * W1.x - W.y * W1.y;
            W.y = W.x * W1.y + W.y * W1.x;
            W.x = wx;
        }
        s_u[p * 8 + d] = make_float2(ax, ay);
    }
    __syncthreads();

    // step 5 (Hermitian half): n2 = 7+d, all m2; mirror to (14-m2, 14-n2)
    if (tid < 120) {
        int m2 = tid >> 3, d = tid & 7;
        int n2 = 7 + d;
        int mt = m2 - 7;
        float2 W = make_float2(1.f, 0.f), S5;
        {
            float ss, cc;
            __sincosf((float)mt * TWOPI_32F, &ss, &cc);
            S5 = make_float2(cc, -ss);
        }
        float ax = 0.f, ay = 0.f;
        const float2* ucol = s_u + d;
#pragma unroll
        for (int p = 0; p < 32; ++p) {
            float2 u = ucol[p * 8];
            ax += u.x * W.x - u.y * W.y;
            ay += u.x * W.y + u.y * W.x;
            float wx = W.x * S5.x - W.y * S5.y;
            W.y = W.x * S5.y + W.y * S5.x;
            W.x = wx;
        }
        float2* outp = g_xmn + (size_t)bx * 225;
        outp[m2 * 15 + n2] = make_float2(ax, ay);
        if (d > 0)
            outp[(14 - m2) * 15 + (14 - n2)] = make_float2(ax, -ay);
    }
}

// ------------------------- k_G: xmn -> xh2 -> G (per (b,c)) ----------------
__global__ __launch_bounds__(256) void k_G() {
    __shared__ float2 s_xh2[8 * 225];
    __shared__ float  s_d2i0[1800];
    int bc = blockIdx.x;    // b*32 + c
    int tid = threadIdx.x;  // 256

    for (int i = tid; i < 1800; i += 256) s_d2i0[i] = g_D2I0[i];

    if (tid < 225) {
        int mk = tid;
        float2 acc[8];
#pragma unroll
        for (int l = 0; l < 8; ++l) acc[l] = make_float2(0.f, 0.f);
        const float2* xp = g_xmn + (size_t)bc * 7200 + mk;
        const float* dp = g_D2F + mk;
#pragma unroll 4
        for (int j = 0; j < 32; ++j) {
            float2 xv = xp[j * 225];
#pragma unroll
            for (int l = 0; l < 8; ++l) {
                float d = dp[l * 7200 + j * 225];
                acc[l].x += d * xv.x;
                acc[l].y += d * xv.y;
            }
        }
#pragma unroll
        for (int l = 0; l < 8; ++l) s_xh2[l * 225 + mk] = acc[l];
    }
    __syncthreads();

    float2* gout = g_G + (size_t)bc * 1800;
    for (int idx = tid; idx < 1800; idx += 256) {
        int l = idx / 225, nk = idx % 225;
        int n = nk / 15, k = nk % 15;
        float ax = 0.f, ay = 0.f;
        if (abs(n - 7) <= l) {
            const float* dp = s_d2i0 + l * 225 + n;
            const float2* xp = s_xh2 + l * 225 + k;
            for (int m = 7 - l; m <= 7 + l; ++m) {
                float d = dp[m * 15];
                float2 v = xp[m * 15];
                ax += d * v.x;
                ay += d * v.y;
            }
        }
        gout[idx] = make_float2(ax, ay);
    }
}

// ------------------------- k_dot: coalesced warp-per-(b,f) -----------------
// block = (c, ft); 8 warps; warp w covers b in {2w, 2w+1} x fl 0..7.
// Lanes stride the k-dim -> fully coalesced LDG.128; G chunk L1-reused 8x.
__global__ __launch_bounds__(256) void k_dot(const float* __restrict__ w2r,
                                             const float* __restrict__ w2i) {
    int c  = blockIdx.x;      // 32
    int ft = blockIdx.y;      // 8
    int tid = threadIdx.x;    // 256
    int w = tid >> 5;         // warp 0..7
    int lane = tid & 31;

    for (int fl = 0; fl < 8; ++fl) {
        int f = ft * 8 + fl;
        const float4* Wr4 = (const float4*)(w2r + ((size_t)c * 64 + f) * 1800);
        const float4* Wi4 = (const float4*)(w2i + ((size_t)c * 64 + f) * 1800);
#pragma unroll
        for (int b2 = 0; b2 < 2; ++b2) {
            int b = 2 * w + b2;
            const float4* X4 = (const float4*)(g_G + ((size_t)b * 32 + c) * 1800);
            float acc = 0.f;
            for (int i = lane; i < 450; i += 32) {
                float4 g0 = X4[2 * i], g1 = X4[2 * i + 1];
                float4 wr = Wr4[i], wi = Wi4[i];
                acc += g0.x * wr.x + g0.y * wi.x + g0.z * wr.y + g0.w * wi.y
                     + g1.x * wr.z + g1.y * wi.z + g1.z * wr.w + g1.w * wi.w;
            }
#pragma unroll
            for (int o = 16; o > 0; o >>= 1)
                acc += __shfl_xor_sync(0xffffffffu, acc, o);
            if (lane == 0)
                g_partial[(c * 8 + ft) * 128 + b * 8 + fl] = acc;
        }
    }
}

// ------------------------- head: reduce + conv1d + BN + FC -----------------
__global__ void k_head(const float* __restrict__ w3, const float* __restrict__ b3,
                       const float* __restrict__ gam, const float* __restrict__ bet,
                       const float* __restrict__ fcw, const float* __restrict__ fcb,
                       float* __restrict__ out) {
    __shared__ float s_feat[16 * 64];
    __shared__ float s_r3[16 * 570];
    __shared__ float s_mu[10], s_rstd[10];
    __shared__ float s_ps[160], s_ps2[160];
    int tid = threadIdx.x;    // 256

    for (int idx = tid; idx < 1024; idx += 256) {
        int b = idx >> 6;
        int f = idx & 63;
        int ft = f >> 3, fl = f & 7;
        float s = 0.f;
#pragma unroll
        for (int c = 0; c < 32; ++c)
            s += g_partial[(c * 8 + ft) * 128 + (b << 3) + fl];
        s_feat[b * 64 + f] = fmaxf(s, 0.f);
    }
    __syncthreads();

    for (int idx = tid; idx < 9120; idx += 256) {
        int b = idx / 570;
        int r = idx % 570;
        int o = r / 57, t = r % 57;
        float s = b3[o];
#pragma unroll
        for (int k = 0; k < 8; ++k)
            s += w3[o * 8 + k] * s_feat[b * 64 + t + k];
        s_r3[idx] = fmaxf(s, 0.f);
    }
    __syncthreads();

    if (tid < 160) {
        int o = tid >> 4, i = tid & 15;
        float s = 0.f, s2 = 0.f;
        for (int idx2 = i; idx2 < 912; idx2 += 16) {
            int b = idx2 / 57, t = idx2 % 57;
            float v = s_r3[b * 570 + o * 57 + t];
            s += v;
            s2 += v * v;
        }
        s_ps[tid] = s;
        s_ps2[tid] = s2;
    }
    __syncthreads();

    if (tid < 10) {
        float s = 0.f, s2 = 0.f;
#pragma unroll
        for (int i = 0; i < 16; ++i) {
            s += s_ps[tid * 16 + i];
            s2 += s_ps2[tid * 16 + i];
        }
        float mu = s / 912.f;
        float var = s2 / 912.f - mu * mu;
        s_mu[tid] = mu;
        s_rstd[tid] = rsqrtf(var + 1e-5f);
    }
    __syncthreads();

    for (int idx = tid; idx < 9120; idx += 256) {
        int o = (idx % 570) / 57;
        s_r3[idx] = gam[o] * (s_r3[idx] - s_mu[o]) * s_rstd[o] + bet[o];
    }
    __syncthreads();

    if (tid < 160) {
        int b = tid / 10, i = tid % 10;
        float s = fcb[i];
        const float* wr = fcw + i * 570;
        const float* xr = s_r3 + b * 570;
        for (int z = 0; z < 570; ++z) s += xr[z] * wr[z];
        out[b * 10 + i] = s;
    }
}

// ---------------------------------------------------------------------------
extern "C" void kernel_launch(void* const* d_in, const int* in_sizes, int n_in,
                              void* d_out, int out_size) {
    const float* x   = (const float*)d_in[0];
    const float* w1r = (const float*)d_in[1];
    const float* w1i = (const float*)d_in[2];
    const float* w2r = (const float*)d_in[3];
    const float* w2i = (const float*)d_in[4];
    const float* c3w = (const float*)d_in[5];
    const float* c3b = (const float*)d_in[6];
    const float* bng = (const float*)d_in[7];
    const float* bnb = (const float*)d_in[8];
    const float* fcw = (const float*)d_in[9];
    const float* fcb = (const float*)d_in[10];
    float* out = (float*)d_out;

    t_setup<<<1, 64>>>();
    t_tables<<<(599048 + 127) / 128, 128>>>();

    k_xh<<<16 * 31, 64>>>(x);
    k_main<<<16 * 32 * 32, 256>>>(w1r, w1i);
    k_G<<<512, 256>>>();
    k_dot<<<dim3(32, 8), 256>>>(w2r, w2i);
    k_head<<<1, 256>>>(c3w, c3b, bng, bnb, fcw, fcb, out);
}

// round 9
// speedup vs baseline: 4.3218x; 1.0336x over previous
#include <cuda_runtime.h>
#include <math.h>

// ---------------------------------------------------------------------------
// S2ConvNet forward pass, sm_103a.
// Shapes: B=16, F1=32, F2=64, B0=32, B1=16, B2=8, M1=31, M2=15.
// ---------------------------------------------------------------------------

#define PI_D 3.141592653589793238462643383279502884
#define TWOPI_32F 0.19634954084936207f   // 2*pi/32

// ------------------------- static device scratch ---------------------------
__device__ float  g_D1F[16 * 64 * 31];                       // [l][j][m]
__device__ __align__(16) float g_D1I[16 * 32 * 31 * 32];     // [l][j][m][n] n padded
__device__ float  g_D2F[8 * 32 * 15 * 15];                   // [l][j][m][k]
__device__ float  g_D2I0[8 * 15 * 15];                       // [l][m][n]
__device__ float2 g_xh[16 * 16 * 31];                        // [b][l][m]
__device__ __align__(16) float2 g_xmn[16 * 32 * 32 * 225];   // [b][c][j][m][k]
__device__ __align__(16) float2 g_G[16 * 32 * 1800];         // [b][c][l][n][k]
__device__ float  g_partial[32 * 8 * 128];

// beta-grid precompute (incl. tan^2(beta/2))
__device__ double g_cb0[64], g_sb0[64], g_w0[64], g_ts0[64];
__device__ double g_cb1[32], g_sb1[32], g_w1[32], g_ts1[32];
__device__ double g_cb2[16], g_sb2[16], g_ts2[16];

__device__ static const double c_F[32] = {
    1.0, 1.0, 2.0, 6.0, 24.0, 120.0, 720.0, 5040.0, 40320.0, 362880.0,
    3628800.0, 39916800.0, 479001600.0, 6227020800.0, 87178291200.0,
    1307674368000.0, 20922789888000.0, 355687428096000.0, 6402373705728000.0,
    121645100408832000.0, 2432902008176640000.0, 51090942171709440000.0,
    1124000727777607680000.0, 25852016738884976640000.0,
    620448401733239439360000.0, 15511210043330985984000000.0,
    403291461126605635584000000.0, 10888869450418352160768000000.0,
    304888344611713860501504000000.0, 8841761993739701954543616000000.0,
    265252859812191058636308480000000.0, 8222838654177922817725562880000000.0
};

__device__ static const double c_R[32] = {
    0.0, 1.0, 1.0/2.0, 1.0/3.0, 1.0/4.0, 1.0/5.0, 1.0/6.0, 1.0/7.0,
    1.0/8.0, 1.0/9.0, 1.0/10.0, 1.0/11.0, 1.0/12.0, 1.0/13.0, 1.0/14.0,
    1.0/15.0, 1.0/16.0, 1.0/17.0, 1.0/18.0, 1.0/19.0, 1.0/20.0, 1.0/21.0,
    1.0/22.0, 1.0/23.0, 1.0/24.0, 1.0/25.0, 1.0/26.0, 1.0/27.0, 1.0/28.0,
    1.0/29.0, 1.0/30.0, 1.0/31.0
};

__device__ __forceinline__ double ipow_d(double x, int e) {
    double r = 1.0;
    while (e) { if (e & 1) r *= x; x *= x; e >>= 1; }
    return r;
}

__device__ double wig_fast(int l, int m, int n, double cb, double sb, double ts) {
    int kmin = max(0, m - n);
    int kmax = min(l + m, l - n);
    if (kmax < kmin) return 0.0;
    double t = sqrt(c_F[l + m] * c_F[l - m] * c_F[l + n] * c_F[l - n])
             / (c_F[kmin] * c_F[l + m - kmin] * c_F[l - n - kmin] * c_F[n - m + kmin]);
    t *= ipow_d(cb, 2 * l + m - n - 2 * kmin) * ipow_d(sb, n - m + 2 * kmin);
    if (kmin & 1) t = -t;
    double s = t;
    for (int k = kmin; k < kmax; ++k) {
        t *= -((double)((l + m - k) * (l - n - k)) *
               c_R[k + 1] * c_R[n - m + k + 1]) * ts;
        s += t;
    }
    return s;
}

// ------------------------- setup kernel ------------------------------------
__global__ void t_setup() {
    int t = threadIdx.x;   // 64
    if (t < 64) {
        double beta = PI_D * (2.0 * t + 1.0) / 128.0;
        double sb, cb;
        sincos(beta * 0.5, &sb, &cb);
        g_cb0[t] = cb; g_sb0[t] = sb;
        g_ts0[t] = (sb * sb) / (cb * cb);
        double sinb = 2.0 * sb * cb;
        double c2 = 1.0 - 2.0 * sinb * sinb;
        double prev = -sinb, cur = sinb, s = 0.0;
#pragma unroll
        for (int k = 0; k < 32; ++k) {
            s += cur * (1.0 / (2.0 * k + 1.0));
            double nx = 2.0 * c2 * cur - prev;
            prev = cur; cur = nx;
        }
        g_w0[t] = (2.0 / 32.0) * sinb * s;
    }
    if (t < 32) {
        double beta = PI_D * (2.0 * t + 1.0) / 64.0;
        double sb, cb;
        sincos(beta * 0.5, &sb, &cb);
        g_cb1[t] = cb; g_sb1[t] = sb;
        g_ts1[t] = (sb * sb) / (cb * cb);
        double sinb = 2.0 * sb * cb;
        double c2 = 1.0 - 2.0 * sinb * sinb;
        double prev = -sinb, cur = sinb, s = 0.0;
#pragma unroll
        for (int k = 0; k < 16; ++k) {
            s += cur * (1.0 / (2.0 * k + 1.0));
            double nx = 2.0 * c2 * cur - prev;
            prev = cur; cur = nx;
        }
        g_w1[t] = (2.0 / 16.0) * sinb * s;
    }
    if (t < 16) {
        double beta = PI_D * (2.0 * t + 1.0) / 32.0;
        double sb, cb;
        sincos(beta * 0.5, &sb, &cb);
        g_cb2[t] = cb; g_sb2[t] = sb;
        g_ts2[t] = (sb * sb) / (cb * cb);
    }
}

// ------------------------- merged table kernel -----------------------------
// D1I uses 4-fold Wigner symmetry: only the canonical wedge nt >= |mt| is
// computed; mirrors (n,m), (-m,-n), (-n,-m) written with sign (-1)^{m-n}.
__global__ void t_tables() {
    int idx = blockIdx.x * blockDim.x + threadIdx.x;
    if (idx < 31744) {
        int l = idx / (64 * 31);
        int j = (idx / 31) % 64;
        int m = idx % 31;
        int mt = m - 15;
        float v = 0.f;
        if (abs(mt) <= l)
            v = (float)(g_w0[j] * wig_fast(l, mt, 0, g_cb0[j], g_sb0[j], g_ts0[j]));
        g_D1F[idx] = v;
        return;
    }
    idx -= 31744;
    if (idx < 507904) {
        int l = idx / 31744;
        int r = idx % 31744;
        int j = r / 992;
        int m = (r / 32) % 31;
        int n = r % 32;
        float* base = g_D1I + (size_t)l * 31744 + (size_t)j * 992;
        if (n == 31) { base[m * 32 + 31] = 0.f; return; }
        int mt = m - 15, nt = n - 15;
        if (abs(mt) > l || abs(nt) > l) { base[m * 32 + n] = 0.f; return; }
        if (nt < abs(mt)) return;   // non-canonical valid: written by partner
        float vf = (float)((2.0 * l + 1.0) *
                           wig_fast(l, mt, nt, g_cb1[j], g_sb1[j], g_ts1[j]));
        float sv = ((m - n) & 1) ? -vf : vf;
        base[m * 32 + n] = vf;
        base[n * 32 + m] = sv;
        base[(30 - m) * 32 + (30 - n)] = sv;
        base[(30 - n) * 32 + (30 - m)] = vf;
        return;
    }
    idx -= 507904;
    if (idx < 57600) {
        int l = idx / (32 * 225);
        int j = (idx / 225) % 32;
        int m = (idx / 15) % 15;
        int n = idx % 15;
        int mt = m - 7, nt = n - 7;
        float v = 0.f;
        if (abs(mt) <= l && abs(nt) <= l)
            v = (float)(g_w1[j] * wig_fast(l, mt, nt, g_cb1[j], g_sb1[j], g_ts1[j]));
        g_D2F[idx] = v;
        return;
    }
    idx -= 57600;
    if (idx < 1800) {
        int l = idx / 225;
        int m = (idx / 15) % 15;
        int n = idx % 15;
        int mt = m - 7, nt = n - 7;
        float v = 0.f;
        if (abs(mt) <= l && abs(nt) <= l)
            v = (float)((2.0 * l + 1.0) * wig_fast(l, mt, nt, g_cb2[0], g_sb2[0], g_ts2[0]));
        g_D2I0[idx] = v;
    }
}

// ------------------------- stage A: x -> xh --------------------------------
__global__ void k_xh(const float* __restrict__ x) {
    __shared__ float2 s_tw[64];
    __shared__ float2 s_xm[64];
    int b = blockIdx.x / 31;
    int m = blockIdx.x % 31;
    int mt = m - 15;
    int j = threadIdx.x;   // 64

    float sj, cj;
    __sincosf((float)j * (6.2831853071795864769f / 64.f), &sj, &cj);
    s_tw[j] = make_float2(cj, sj);
    __syncthreads();

    const float* xr = x + (size_t)(b * 64 + j) * 64;
    float accx = 0.f, accy = 0.f;
#pragma unroll 8
    for (int t = 0; t < 64; ++t) {
        unsigned r = ((unsigned)(mt * t)) & 63u;
        float2 e = s_tw[r];
        float v = xr[t];
        accx += v * e.x;
        accy -= v * e.y;
    }
    s_xm[j] = make_float2(accx, accy);
    __syncthreads();

    if (j < 16) {
        int l = j;
        float ax = 0.f, ay = 0.f;
        const float* dp = g_D1F + (size_t)l * 64 * 31 + m;
#pragma unroll 8
        for (int jj = 0; jj < 64; ++jj) {
            float d = dp[jj * 31];
            float2 v = s_xm[jj];
            ax += d * v.x;
            ay += d * v.y;
        }
        g_xh[(b * 16 + l) * 31 + m] = make_float2(ax, ay);
    }
}

// ------------------------- stage B+C fused plane kernel --------------------
__global__ __launch_bounds__(256, 4) void k_main(const float* __restrict__ w1r,
                                                 const float* __restrict__ w1i) {
    __shared__ float2 s_xh[16 * 31];
    __shared__ __align__(16) float2 s_w1[16 * 32];     // n padded to 32
    __shared__ __align__(16) float2 s_buf[1056];       // f[31][34] THEN sp4+u
    __shared__ float2 s_g[31 * 32];
    __shared__ __align__(16) float4 s_p4[31 * 16];     // pairing scratch
    __shared__ float  s_r016[64];                      // r[p][0], r[p][16]

    float2* s_f = s_buf;                 // [m][n] stride 34 (phase 1)
    float2* sp4 = s_buf;                 // [p][qm1] stride 17 (phase 2, 544 f2)
    float2* s_u = s_buf + 560;           // [p][d] 32x8 (phase 2)
    float2* sp3 = (float2*)s_p4;         // [mt-1][q]  15x32

    int bx = blockIdx.x;
    int b = bx >> 10;
    int f = (bx >> 5) & 31;
    int j = bx & 31;
    int tid = threadIdx.x;

    for (int i = tid; i < 496; i += 256) {
        int l = i / 31, n = i % 31;
        s_xh[i] = g_xh[b * 496 + i];
        s_w1[l * 32 + n] = make_float2(w1r[f * 496 + i], w1i[f * 496 + i]);
    }
    if (tid < 16) s_w1[tid * 32 + 31] = make_float2(0.f, 0.f);
    __syncthreads();

    // step 1: f[m,n] = sum_l D1I[l,j,m,n] * xh[l,m] * conj(w1[l,n])
    if (tid < 248) {
        int m = tid >> 3, ng = tid & 7, n0 = ng * 4;
        int am = abs(m - 15);
        int nhi = n0 + 3;
        int anmin = (nhi < 15) ? (15 - nhi) : ((n0 > 15) ? (n0 - 15) : 0);
        int l0 = max(am, anmin);
        float ax0 = 0.f, ay0 = 0.f, ax1 = 0.f, ay1 = 0.f;
        float ax2 = 0.f, ay2 = 0.f, ax3 = 0.f, ay3 = 0.f;
        const float4* dp4 = (const float4*)(g_D1I + (size_t)j * 992 + m * 32 + n0);
        for (int l = l0; l < 16; ++l) {
            float4 d = dp4[l * 7936];
            float2 a = s_xh[l * 31 + m];
            float4 wA = *(const float4*)(s_w1 + l * 32 + n0);
            float4 wB = *(const float4*)(s_w1 + l * 32 + n0 + 2);
            float tr, ti;
            tr = a.x * wA.x + a.y * wA.y; ti = a.y * wA.x - a.x * wA.y;
            ax0 += d.x * tr; ay0 += d.x * ti;
            tr = a.x * wA.z + a.y * wA.w; ti = a.y * wA.z - a.x * wA.w;
            ax1 += d.y * tr; ay1 += d.y * ti;
            tr = a.x * wB.x + a.y * wB.y; ti = a.y * wB.x - a.x * wB.y;
            ax2 += d.z * tr; ay2 += d.z * ti;
            tr = a.x * wB.z + a.y * wB.w; ti = a.y * wB.z - a.x * wB.w;
            ax3 += d.w * tr; ay3 += d.w * ti;
        }
        *(float4*)(s_f + m * 34 + n0)     = make_float4(ax0, ay0, ax1, ay1);
        *(float4*)(s_f + m * 34 + n0 + 2) = make_float4(ax2, ay2, ax3, ay3);
    }
    __syncthreads();

    // pass A: pair f over nt: s_p4[m][nt] = (Sx, Sy, Dx, Dy); nt=0 -> center
    for (int i = tid; i < 496; i += 256) {
        int m = i >> 4, nt = i & 15;
        float4 v;
        if (nt == 0) {
            float2 c = s_f[m * 34 + 15];
            v = make_float4(c.x, c.y, 0.f, 0.f);
        } else {
            float2 fp = s_f[m * 34 + 15 + nt];
            float2 fm = s_f[m * 34 + 15 - nt];
            v = make_float4(fp.x + fm.x, fp.y + fm.y, fp.x - fm.x, fp.y - fm.y);
        }
        s_p4[m * 16 + nt] = v;
    }
    __syncthreads();

    // step 2: g[m,q] = sum_nt pair-terms, 4-way q blocking (q0, +8, +16, +24)
    if (tid < 248) {
        int m = tid >> 3, q0 = tid & 7;
        float2 S, E;
        __sincosf((float)q0 * TWOPI_32F, &S.y, &S.x);
        E = S;     // nt = 1
        const float4* prow = s_p4 + m * 16;
        float4 c0 = prow[0];
        float a0x = c0.x, a0y = c0.y, a1x = c0.x, a1y = c0.y;
        float a2x = c0.x, a2y = c0.y, a3x = c0.x, a3y = c0.y;
        int nt = 1;
#define S2P(PP)                                                              \
        {                                                                    \
            float4 pr = prow[nt];                                            \
            float p1 = E.x * pr.x, p2 = E.y * pr.w;                          \
            float p3 = E.x * pr.y, p4 = E.y * pr.z;                          \
            float tx = p1 - p2, ty = p3 + p4;                                \
            a0x += tx; a0y += ty;                                            \
            if (PP == 0) { a1x += tx; a1y += ty; a2x += tx; a2y += ty;       \
                           a3x += tx; a3y += ty; }                           \
            if (PP == 2) { a1x -= tx; a1y -= ty; a2x += tx; a2y += ty;       \
                           a3x -= tx; a3y -= ty; }                           \
            if (PP == 1 || PP == 3) {                                        \
                float r1 = E.y * pr.x, r2 = E.x * pr.w;                      \
                float r3 = E.y * pr.y, r4 = E.x * pr.z;                      \
                float ux = r1 + r2, uy = r3 - r4;                            \
                if (PP == 1) { a1x -= ux; a1y -= uy; a2x -= tx; a2y -= ty;   \
                               a3x += ux; a3y += uy; }                       \
                if (PP == 3) { a1x += ux; a1y += uy; a2x -= tx; a2y -= ty;   \
                               a3x -= ux; a3y -= uy; }                       \
            }                                                                \
            float ex = E.x * S.x - E.y * S.y;                                \
            E.y = E.x * S.y + E.y * S.x;                                     \
            E.x = ex;                                                        \
            ++nt;                                                            \
        }
#pragma unroll
        for (int g4 = 0; g4 < 3; ++g4) {   // nt = 1..12
            S2P(1) S2P(2) S2P(3) S2P(0)
        }
        S2P(1) S2P(2) S2P(3)               // nt = 13,14,15
#undef S2P
        s_g[m * 32 + q0]      = make_float2(a0x, a0y);
        s_g[m * 32 + q0 + 8]  = make_float2(a1x, a1y);
        s_g[m * 32 + q0 + 16] = make_float2(a2x, a2y);
        s_g[m * 32 + q0 + 24] = make_float2(a3x, a3y);
    }
    __syncthreads();

    // pass B: pair g over mt: sp3[mt-1][q] = (P, Q)
    for (int i = tid; i < 480; i += 256) {
        int mt = 1 + (i >> 5), q = i & 31;
        float2 gp = s_g[(15 + mt) * 32 + q];
        float2 gm = s_g[(15 - mt) * 32 + q];
        sp3[(mt - 1) * 32 + q] = make_float2(gp.x + gm.x, gp.y - gm.y);
    }
    __syncthreads();

    // step 3: r[p,q] = relu(center + sum_mt (E.x*P - E.y*Q)), 4-way p blocking
    // then in-warp pairing over q (pass C fused via shuffle).
    {
        int q = tid & 31, p0 = tid >> 5;
        float2 S, E;
        __sincosf((float)p0 * TWOPI_32F, &S.y, &S.x);
        E = S;     // mt = 1
        float c = s_g[15 * 32 + q].x;
        float a0 = c, a1 = c, a2 = c, a3 = c;
        const float2* pcol = sp3 + q;
        int mt = 1;
#define S3P(PP)                                                              \
        {                                                                    \
            float2 v = pcol[(mt - 1) * 32];                                  \
            float u1 = E.x * v.x, u2 = E.y * v.y;                            \
            float tx = u1 - u2;                                              \
            a0 += tx;                                                        \
            if (PP == 0) { a1 += tx; a2 += tx; a3 += tx; }                   \
            if (PP == 2) { a1 -= tx; a2 += tx; a3 -= tx; }                   \
            if (PP == 1 || PP == 3) {                                        \
                float v1 = E.y * v.x, v2 = E.x * v.y;                        \
                float ux = v1 + v2;                                          \
                if (PP == 1) { a1 -= ux; a2 -= tx; a3 += ux; }               \
                if (PP == 3) { a1 += ux; a2 -= tx; a3 -= ux; }               \
            }                                                                \
            float ex = E.x * S.x - E.y * S.y;                                \
            E.y = E.x * S.y + E.y * S.x;                                     \
            E.x = ex;                                                        \
            ++mt;                                                            \
        }
#pragma unroll
        for (int g4 = 0; g4 < 3; ++g4) {
            S3P(1) S3P(2) S3P(3) S3P(0)
        }
        S3P(1) S3P(2) S3P(3)
#undef S3P
        a0 = fmaxf(a0, 0.f);
        a1 = fmaxf(a1, 0.f);
        a2 = fmaxf(a2, 0.f);
        a3 = fmaxf(a3, 0.f);
        // partner lane (32-q)&31 holds r[p][32-q]
        int src = (32 - q) & 31;
        float b0 = __shfl_sync(0xffffffffu, a0, src);
        float b1 = __shfl_sync(0xffffffffu, a1, src);
        float b2 = __shfl_sync(0xffffffffu, a2, src);
        float b3 = __shfl_sync(0xffffffffu, a3, src);
        __syncthreads();   // sp3/s_g reads complete before s_buf reuse
        if (q >= 1 && q <= 15) {
            int qm1 = q - 1;
            sp4[p0 * 17 + qm1]        = make_float2(a0 + b0, a0 - b0);
            sp4[(p0 + 8) * 17 + qm1]  = make_float2(a1 + b1, a1 - b1);
            sp4[(p0 + 16) * 17 + qm1] = make_float2(a2 + b2, a2 - b2);
            sp4[(p0 + 24) * 17 + qm1] = make_float2(a3 + b3, a3 - b3);
        } else if (q == 0) {
            s_r016[p0]      = a0;
            s_r016[p0 + 8]  = a1;
            s_r016[p0 + 16] = a2;
            s_r016[p0 + 24] = a3;
        } else if (q == 16) {
            s_r016[32 + p0]      = a0;
            s_r016[32 + p0 + 8]  = a1;
            s_r016[32 + p0 + 16] = a2;
            s_r016[32 + p0 + 24] = a3;
        }
    }
    __syncthreads();

    // step 4: u[p,d] = r0 + (-1)^d r16 + sum_q (S*W.x, D*W.y), d = 0..7
    {
        int p = tid >> 3, d = tid & 7;
        float2 W1;
        __sincosf((float)d * TWOPI_32F, &W1.y, &W1.x);
        W1.y = -W1.y;
        float2 W = W1;
        float r0 = s_r016[p];
        float r16 = s_r016[32 + p];
        float ax = r0 + ((d & 1) ? -r16 : r16);
        float ay = 0.f;
        const float2* sd = sp4 + p * 17;
#pragma unroll
        for (int q = 1; q <= 15; ++q) {
            float2 v = sd[q - 1];
            ax += v.x * W.x;
            ay += v.y * W.y;
            float wx = W.x * W1.x - W.y * W1.y;
            W.y = W.x * W1.y + W.y * W1.x;
            W.x = wx;
        }
        s_u[p * 8 + d] = make_float2(ax, ay);
    }
    __syncthreads();

    // step 5 (Hermitian half): n2 = 7+d, all m2; mirror to (14-m2, 14-n2)
    if (tid < 120) {
        int m2 = tid >> 3, d = tid & 7;
        int n2 = 7 + d;
        int mt = m2 - 7;
        float2 W = make_float2(1.f, 0.f), S5;
        {
            float ss, cc;
            __sincosf((float)mt * TWOPI_32F, &ss, &cc);
            S5 = make_float2(cc, -ss);
        }
        float ax = 0.f, ay = 0.f;
        const float2* ucol = s_u + d;
#pragma unroll
        for (int p = 0; p < 32; ++p) {
            float2 u = ucol[p * 8];
            ax += u.x * W.x - u.y * W.y;
            ay += u.x * W.y + u.y * W.x;
            float wx = W.x * S5.x - W.y * S5.y;
            W.y = W.x * S5.y + W.y * S5.x;
            W.x = wx;
        }
        float2* outp = g_xmn + (size_t)bx * 225;
        outp[m2 * 15 + n2] = make_float2(ax, ay);
        if (d > 0)
            outp[(14 - m2) * 15 + (14 - n2)] = make_float2(ax, -ay);
    }
}

// ------------------------- k_G: xmn -> xh2 -> G (per (b,c)) ----------------
// 512 threads; j-dim split across two 225-thread groups to halve the serial
// chain and double warp-level latency hiding.
__global__ __launch_bounds__(512) void k_G() {
    __shared__ float2 s_xh2[2 * 8 * 225];   // 28.8 KB
    __shared__ float  s_d2i0[1800];         // 7.2 KB
    int bc = blockIdx.x;    // b*32 + c
    int tid = threadIdx.x;  // 512

    for (int i = tid; i < 1800; i += 512) s_d2i0[i] = g_D2I0[i];

    if (tid < 450) {
        int jh = tid / 225, mk = tid % 225;
        float2 acc[8];
#pragma unroll
        for (int l = 0; l < 8; ++l) acc[l] = make_float2(0.f, 0.f);
        const float2* xp = g_xmn + (size_t)bc * 7200 + jh * 16 * 225 + mk;
        const float* dp = g_D2F + jh * 16 * 225 + mk;
#pragma unroll 4
        for (int j = 0; j < 16; ++j) {
            float2 xv = xp[j * 225];
#pragma unroll
            for (int l = 0; l < 8; ++l) {
                float d = dp[l * 7200 + j * 225];
                acc[l].x += d * xv.x;
                acc[l].y += d * xv.y;
            }
        }
#pragma unroll
        for (int l = 0; l < 8; ++l)
            s_xh2[jh * 1800 + l * 225 + mk] = acc[l];
    }
    __syncthreads();

    // combine j-halves
    for (int i = tid; i < 1800; i += 512) {
        float2 a = s_xh2[i], b = s_xh2[1800 + i];
        s_xh2[i] = make_float2(a.x + b.x, a.y + b.y);
    }
    __syncthreads();

    float2* gout = g_G + (size_t)bc * 1800;
    for (int idx = tid; idx < 1800; idx += 512) {
        int l = idx / 225, nk = idx % 225;
        int n = nk / 15, k = nk % 15;
        float ax = 0.f, ay = 0.f;
        if (abs(n - 7) <= l) {
            const float* dp = s_d2i0 + l * 225 + n;
            const float2* xp = s_xh2 + l * 225 + k;
            for (int m = 7 - l; m <= 7 + l; ++m) {
                float d = dp[m * 15];
                float2 v = xp[m * 15];
                ax += d * v.x;
                ay += d * v.y;
            }
        }
        gout[idx] = make_float2(ax, ay);
    }
}

// ------------------------- k_dot: coalesced warp-per-(b,f) -----------------
__global__ __launch_bounds__(256) void k_dot(const float* __restrict__ w2r,
                                             const float* __restrict__ w2i) {
    int c  = blockIdx.x;      // 32
    int ft = blockIdx.y;      // 8
    int tid = threadIdx.x;    // 256
    int w = tid >> 5;         // warp 0..7
    int lane = tid & 31;

    for (int fl = 0; fl < 8; ++fl) {
        int f = ft * 8 + fl;
        const float4* Wr4 = (const float4*)(w2r + ((size_t)c * 64 + f) * 1800);
        const float4* Wi4 = (const float4*)(w2i + ((size_t)c * 64 + f) * 1800);
#pragma unroll
        for (int b2 = 0; b2 < 2; ++b2) {
            int b = 2 * w + b2;
            const float4* X4 = (const float4*)(g_G + ((size_t)b * 32 + c) * 1800);
            float acc = 0.f;
            for (int i = lane; i < 450; i += 32) {
                float4 g0 = X4[2 * i], g1 = X4[2 * i + 1];
                float4 wr = Wr4[i], wi = Wi4[i];
                acc += g0.x * wr.x + g0.y * wi.x + g0.z * wr.y + g0.w * wi.y
                     + g1.x * wr.z + g1.y * wi.z + g1.z * wr.w + g1.w * wi.w;
            }
#pragma unroll
            for (int o = 16; o > 0; o >>= 1)
                acc += __shfl_xor_sync(0xffffffffu, acc, o);
            if (lane == 0)
                g_partial[(c * 8 + ft) * 128 + b * 8 + fl] = acc;
        }
    }
}

// ------------------------- head: reduce + conv1d + BN + FC -----------------
__global__ void k_head(const float* __restrict__ w3, const float* __restrict__ b3,
                       const float* __restrict__ gam, const float* __restrict__ bet,
                       const float* __restrict__ fcw, const float* __restrict__ fcb,
                       float* __restrict__ out) {
    __shared__ float s_feat[16 * 64];
    __shared__ float s_r3[16 * 570];
    __shared__ float s_mu[10], s_rstd[10];
    __shared__ float s_ps[160], s_ps2[160];
    int tid = threadIdx.x;    // 256

    for (int idx = tid; idx < 1024; idx += 256) {
        int b = idx >> 6;
        int f = idx & 63;
        int ft = f >> 3, fl = f & 7;
        float s = 0.f;
#pragma unroll
        for (int c = 0; c < 32; ++c)
            s += g_partial[(c * 8 + ft) * 128 + (b << 3) + fl];
        s_feat[b * 64 + f] = fmaxf(s, 0.f);
    }
    __syncthreads();

    for (int idx = tid; idx < 9120; idx += 256) {
        int b = idx / 570;
        int r = idx % 570;
        int o = r / 57, t = r % 57;
        float s = b3[o];
#pragma unroll
        for (int k = 0; k < 8; ++k)
            s += w3[o * 8 + k] * s_feat[b * 64 + t + k];
        s_r3[idx] = fmaxf(s, 0.f);
    }
    __syncthreads();

    if (tid < 160) {
        int o = tid >> 4, i = tid & 15;
        float s = 0.f, s2 = 0.f;
        for (int idx2 = i; idx2 < 912; idx2 += 16) {
            int b = idx2 / 57, t = idx2 % 57;
            float v = s_r3[b * 570 + o * 57 + t];
            s += v;
            s2 += v * v;
        }
        s_ps[tid] = s;
        s_ps2[tid] = s2;
    }
    __syncthreads();

    if (tid < 10) {
        float s = 0.f, s2 = 0.f;
#pragma unroll
        for (int i = 0; i < 16; ++i) {
            s += s_ps[tid * 16 + i];
            s2 += s_ps2[tid * 16 + i];
        }
        float mu = s / 912.f;
        float var = s2 / 912.f - mu * mu;
        s_mu[tid] = mu;
        s_rstd[tid] = rsqrtf(var + 1e-5f);
    }
    __syncthreads();

    for (int idx = tid; idx < 9120; idx += 256) {
        int o = (idx % 570) / 57;
        s_r3[idx] = gam[o] * (s_r3[idx] - s_mu[o]) * s_rstd[o] + bet[o];
    }
    __syncthreads();

    if (tid < 160) {
        int b = tid / 10, i = tid % 10;
        float s = fcb[i];
        const float* wr = fcw + i * 570;
        const float* xr = s_r3 + b * 570;
        for (int z = 0; z < 570; ++z) s += xr[z] * wr[z];
        out[b * 10 + i] = s;
    }
}

// ---------------------------------------------------------------------------
extern "C" void kernel_launch(void* const* d_in, const int* in_sizes, int n_in,
                              void* d_out, int out_size) {
    const float* x   = (const float*)d_in[0];
    const float* w1r = (const float*)d_in[1];
    const float* w1i = (const float*)d_in[2];
    const float* w2r = (const float*)d_in[3];
    const float* w2i = (const float*)d_in[4];
    const float* c3w = (const float*)d_in[5];
    const float* c3b = (const float*)d_in[6];
    const float* bng = (const float*)d_in[7];
    const float* bnb = (const float*)d_in[8];
    const float* fcw = (const float*)d_in[9];
    const float* fcb = (const float*)d_in[10];
    float* out = (float*)d_out;

    t_setup<<<1, 64>>>();
    t_tables<<<(599048 + 127) / 128, 128>>>();

    k_xh<<<16 * 31, 64>>>(x);
    k_main<<<16 * 32 * 32, 256>>>(w1r, w1i);
    k_G<<<512, 512>>>();
    k_dot<<<dim3(32, 8), 256>>>(w2r, w2i);
    k_head<<<1, 256>>>(c3w, c3b, bng, bnb, fcw, fcb, out);
}

// round 10
// speedup vs baseline: 4.6673x; 1.0799x over previous
#include <cuda_runtime.h>
#include <math.h>

// ---------------------------------------------------------------------------
// S2ConvNet forward pass, sm_103a.
// Shapes: B=16, F1=32, F2=64, B0=32, B1=16, B2=8, M1=31, M2=15.
// ---------------------------------------------------------------------------

#define PI_D 3.141592653589793238462643383279502884
#define TWOPI_32F 0.19634954084936207f   // 2*pi/32

// ------------------------- static device scratch ---------------------------
__device__ float  g_D1F[16 * 64 * 31];                       // [l][j][m]
__device__ __align__(16) float g_D1I[16 * 32 * 31 * 32];     // [l][j][m][n] n padded
__device__ float  g_D2F[8 * 32 * 15 * 15];                   // [l][j][m][k]
__device__ float  g_D2I0[8 * 15 * 15];                       // [l][m][n]
__device__ float2 g_xh[16 * 16 * 31];                        // [b][l][m]
__device__ __align__(16) float2 g_xmn[16 * 32 * 32 * 225];   // [b][c][j][m][k]
__device__ __align__(16) float2 g_G[16 * 32 * 1800];         // [b][c][l][n][k]
__device__ float  g_partial[32 * 8 * 128];

// beta-grid precompute (incl. tan^2(beta/2))
__device__ double g_cb0[64], g_sb0[64], g_w0[64], g_ts0[64];
__device__ double g_cb1[32], g_sb1[32], g_w1[32], g_ts1[32];
__device__ double g_cb2[16], g_sb2[16], g_ts2[16];

__device__ static const double c_F[32] = {
    1.0, 1.0, 2.0, 6.0, 24.0, 120.0, 720.0, 5040.0, 40320.0, 362880.0,
    3628800.0, 39916800.0, 479001600.0, 6227020800.0, 87178291200.0,
    1307674368000.0, 20922789888000.0, 355687428096000.0, 6402373705728000.0,
    121645100408832000.0, 2432902008176640000.0, 51090942171709440000.0,
    1124000727777607680000.0, 25852016738884976640000.0,
    620448401733239439360000.0, 15511210043330985984000000.0,
    403291461126605635584000000.0, 10888869450418352160768000000.0,
    304888344611713860501504000000.0, 8841761993739701954543616000000.0,
    265252859812191058636308480000000.0, 8222838654177922817725562880000000.0
};

__device__ static const double c_R[32] = {
    0.0, 1.0, 1.0/2.0, 1.0/3.0, 1.0/4.0, 1.0/5.0, 1.0/6.0, 1.0/7.0,
    1.0/8.0, 1.0/9.0, 1.0/10.0, 1.0/11.0, 1.0/12.0, 1.0/13.0, 1.0/14.0,
    1.0/15.0, 1.0/16.0, 1.0/17.0, 1.0/18.0, 1.0/19.0, 1.0/20.0, 1.0/21.0,
    1.0/22.0, 1.0/23.0, 1.0/24.0, 1.0/25.0, 1.0/26.0, 1.0/27.0, 1.0/28.0,
    1.0/29.0, 1.0/30.0, 1.0/31.0
};

__device__ __forceinline__ double ipow_d(double x, int e) {
    double r = 1.0;
    while (e) { if (e & 1) r *= x; x *= x; e >>= 1; }
    return r;
}

__device__ double wig_fast(int l, int m, int n, double cb, double sb, double ts) {
    int kmin = max(0, m - n);
    int kmax = min(l + m, l - n);
    if (kmax < kmin) return 0.0;
    double t = sqrt(c_F[l + m] * c_F[l - m] * c_F[l + n] * c_F[l - n])
             / (c_F[kmin] * c_F[l + m - kmin] * c_F[l - n - kmin] * c_F[n - m + kmin]);
    t *= ipow_d(cb, 2 * l + m - n - 2 * kmin) * ipow_d(sb, n - m + 2 * kmin);
    if (kmin & 1) t = -t;
    double s = t;
    for (int k = kmin; k < kmax; ++k) {
        t *= -((double)((l + m - k) * (l - n - k)) *
               c_R[k + 1] * c_R[n - m + k + 1]) * ts;
        s += t;
    }
    return s;
}

// ------------------------- setup kernel ------------------------------------
__global__ void t_setup() {
    int t = threadIdx.x;   // 64
    if (t < 64) {
        double beta = PI_D * (2.0 * t + 1.0) / 128.0;
        double sb, cb;
        sincos(beta * 0.5, &sb, &cb);
        g_cb0[t] = cb; g_sb0[t] = sb;
        g_ts0[t] = (sb * sb) / (cb * cb);
        double sinb = 2.0 * sb * cb;
        double c2 = 1.0 - 2.0 * sinb * sinb;
        double prev = -sinb, cur = sinb, s = 0.0;
#pragma unroll
        for (int k = 0; k < 32; ++k) {
            s += cur * (1.0 / (2.0 * k + 1.0));
            double nx = 2.0 * c2 * cur - prev;
            prev = cur; cur = nx;
        }
        g_w0[t] = (2.0 / 32.0) * sinb * s;
    }
    if (t < 32) {
        double beta = PI_D * (2.0 * t + 1.0) / 64.0;
        double sb, cb;
        sincos(beta * 0.5, &sb, &cb);
        g_cb1[t] = cb; g_sb1[t] = sb;
        g_ts1[t] = (sb * sb) / (cb * cb);
        double sinb = 2.0 * sb * cb;
        double c2 = 1.0 - 2.0 * sinb * sinb;
        double prev = -sinb, cur = sinb, s = 0.0;
#pragma unroll
        for (int k = 0; k < 16; ++k) {
            s += cur * (1.0 / (2.0 * k + 1.0));
            double nx = 2.0 * c2 * cur - prev;
            prev = cur; cur = nx;
        }
        g_w1[t] = (2.0 / 16.0) * sinb * s;
    }
    if (t < 16) {
        double beta = PI_D * (2.0 * t + 1.0) / 32.0;
        double sb, cb;
        sincos(beta * 0.5, &sb, &cb);
        g_cb2[t] = cb; g_sb2[t] = sb;
        g_ts2[t] = (sb * sb) / (cb * cb);
    }
}

// ------------------------- merged table kernel -----------------------------
// D1I: 4-fold symmetry (canonical wedge nt >= |mt|).
// D1F: mirror symmetry d_{-m,0} = (-1)^m d_{m,0} (compute mt >= 0 only).
__global__ void t_tables() {
    int idx = blockIdx.x * blockDim.x + threadIdx.x;
    if (idx < 31744) {
        int l = idx / (64 * 31);
        int j = (idx / 31) % 64;
        int m = idx % 31;
        int mt = m - 15;
        float* base = g_D1F + (size_t)l * 64 * 31 + (size_t)j * 31;
        if (abs(mt) > l) { base[m] = 0.f; return; }
        if (mt < 0) return;   // written by the mt >= 0 partner
        float v = (float)(g_w0[j] * wig_fast(l, mt, 0, g_cb0[j], g_sb0[j], g_ts0[j]));
        base[m] = v;
        base[30 - m] = (mt & 1) ? -v : v;
        return;
    }
    idx -= 31744;
    if (idx < 507904) {
        int l = idx / 31744;
        int r = idx % 31744;
        int j = r / 992;
        int m = (r / 32) % 31;
        int n = r % 32;
        float* base = g_D1I + (size_t)l * 31744 + (size_t)j * 992;
        if (n == 31) { base[m * 32 + 31] = 0.f; return; }
        int mt = m - 15, nt = n - 15;
        if (abs(mt) > l || abs(nt) > l) { base[m * 32 + n] = 0.f; return; }
        if (nt < abs(mt)) return;   // non-canonical valid: written by partner
        float vf = (float)((2.0 * l + 1.0) *
                           wig_fast(l, mt, nt, g_cb1[j], g_sb1[j], g_ts1[j]));
        float sv = ((m - n) & 1) ? -vf : vf;
        base[m * 32 + n] = vf;
        base[n * 32 + m] = sv;
        base[(30 - m) * 32 + (30 - n)] = sv;
        base[(30 - n) * 32 + (30 - m)] = vf;
        return;
    }
    idx -= 507904;
    if (idx < 57600) {
        int l = idx / (32 * 225);
        int j = (idx / 225) % 32;
        int m = (idx / 15) % 15;
        int n = idx % 15;
        int mt = m - 7, nt = n - 7;
        float v = 0.f;
        if (abs(mt) <= l && abs(nt) <= l)
            v = (float)(g_w1[j] * wig_fast(l, mt, nt, g_cb1[j], g_sb1[j], g_ts1[j]));
        g_D2F[idx] = v;
        return;
    }
    idx -= 57600;
    if (idx < 1800) {
        int l = idx / 225;
        int m = (idx / 15) % 15;
        int n = idx % 15;
        int mt = m - 7, nt = n - 7;
        float v = 0.f;
        if (abs(mt) <= l && abs(nt) <= l)
            v = (float)((2.0 * l + 1.0) * wig_fast(l, mt, nt, g_cb2[0], g_sb2[0], g_ts2[0]));
        g_D2I0[idx] = v;
    }
}

// ------------------------- stage A: x -> xh --------------------------------
__global__ void k_xh(const float* __restrict__ x) {
    __shared__ float2 s_tw[64];
    __shared__ float2 s_xm[64];
    int b = blockIdx.x / 31;
    int m = blockIdx.x % 31;
    int mt = m - 15;
    int j = threadIdx.x;   // 64

    float sj, cj;
    __sincosf((float)j * (6.2831853071795864769f / 64.f), &sj, &cj);
    s_tw[j] = make_float2(cj, sj);
    __syncthreads();

    const float* xr = x + (size_t)(b * 64 + j) * 64;
    float accx = 0.f, accy = 0.f;
#pragma unroll 8
    for (int t = 0; t < 64; ++t) {
        unsigned r = ((unsigned)(mt * t)) & 63u;
        float2 e = s_tw[r];
        float v = xr[t];
        accx += v * e.x;
        accy -= v * e.y;
    }
    s_xm[j] = make_float2(accx, accy);
    __syncthreads();

    if (j < 16) {
        int l = j;
        float ax = 0.f, ay = 0.f;
        const float* dp = g_D1F + (size_t)l * 64 * 31 + m;
#pragma unroll 8
        for (int jj = 0; jj < 64; ++jj) {
            float d = dp[jj * 31];
            float2 v = s_xm[jj];
            ax += d * v.x;
            ay += d * v.y;
        }
        g_xh[(b * 16 + l) * 31 + m] = make_float2(ax, ay);
    }
}

// ------------------------- stage B+C fused plane kernel (b-paired) ---------
// One block handles TWO batch planes (2bp, 2bp+1) for fixed (f,j): D1I LDG
// and w1 LDS amortized across both; steps 2-5 looped per plane.
__global__ __launch_bounds__(256, 3) void k_main(const float* __restrict__ w1r,
                                                 const float* __restrict__ w1i) {
    __shared__ float2 s_xh2[2 * 496];                  // 7.9 KB
    __shared__ __align__(16) float2 s_w1[16 * 32];     // 4 KB
    __shared__ __align__(16) float2 s_f2[2 * 1056];    // 16.9 KB (f OR sp4+u per bb)
    __shared__ float2 s_g[31 * 32];                    // 7.9 KB
    __shared__ __align__(16) float4 s_p4[31 * 16];     // 7.9 KB pairing scratch
    __shared__ float  s_r016[64];

    float2* sp3 = (float2*)s_p4;         // [mt-1][q]  15x32

    int bx = blockIdx.x;
    int bp = bx >> 10;          // 0..7
    int f = (bx >> 5) & 31;
    int j = bx & 31;
    int tid = threadIdx.x;

    for (int i = tid; i < 992; i += 256)
        s_xh2[i] = g_xh[(2 * bp) * 496 + i];    // covers both planes (contiguous)
    for (int i = tid; i < 496; i += 256) {
        int l = i / 31, n = i % 31;
        s_w1[l * 32 + n] = make_float2(w1r[f * 496 + i], w1i[f * 496 + i]);
    }
    if (tid < 16) s_w1[tid * 32 + 31] = make_float2(0.f, 0.f);
    __syncthreads();

    // step 1 (both planes): f[bb][m,n] = sum_l D1I * xh[bb] * conj(w1)
    if (tid < 248) {
        int m = tid >> 3, ng = tid & 7, n0 = ng * 4;
        int am = abs(m - 15);
        int nhi = n0 + 3;
        int anmin = (nhi < 15) ? (15 - nhi) : ((n0 > 15) ? (n0 - 15) : 0);
        int l0 = max(am, anmin);
        float ax[2][4] = {{0.f, 0.f, 0.f, 0.f}, {0.f, 0.f, 0.f, 0.f}};
        float ay[2][4] = {{0.f, 0.f, 0.f, 0.f}, {0.f, 0.f, 0.f, 0.f}};
        const float4* dp4 = (const float4*)(g_D1I + (size_t)j * 992 + m * 32 + n0);
        for (int l = l0; l < 16; ++l) {
            float4 d = dp4[l * 7936];
            float2 aA = s_xh2[l * 31 + m];
            float2 aB = s_xh2[496 + l * 31 + m];
            float4 wA = *(const float4*)(s_w1 + l * 32 + n0);
            float4 wB = *(const float4*)(s_w1 + l * 32 + n0 + 2);
            float wx[4] = {wA.x, wA.z, wB.x, wB.z};
            float wy[4] = {wA.y, wA.w, wB.y, wB.w};
            float dv[4] = {d.x, d.y, d.z, d.w};
#pragma unroll
            for (int k = 0; k < 4; ++k) {
                float tr = aA.x * wx[k] + aA.y * wy[k];
                float ti = aA.y * wx[k] - aA.x * wy[k];
                ax[0][k] += dv[k] * tr; ay[0][k] += dv[k] * ti;
                tr = aB.x * wx[k] + aB.y * wy[k];
                ti = aB.y * wx[k] - aB.x * wy[k];
                ax[1][k] += dv[k] * tr; ay[1][k] += dv[k] * ti;
            }
        }
#pragma unroll
        for (int bb = 0; bb < 2; ++bb) {
            float2* sf = s_f2 + bb * 1056;
            *(float4*)(sf + m * 34 + n0)     = make_float4(ax[bb][0], ay[bb][0], ax[bb][1], ay[bb][1]);
            *(float4*)(sf + m * 34 + n0 + 2) = make_float4(ax[bb][2], ay[bb][2], ax[bb][3], ay[bb][3]);
        }
    }
    __syncthreads();

    for (int bb = 0; bb < 2; ++bb) {
        float2* s_f = s_f2 + bb * 1056;
        float2* sp4 = s_f;              // overlay after pass A consumes s_f
        float2* s_u = s_f + 560;

        // pass A: pair f over nt
        for (int i = tid; i < 496; i += 256) {
            int m = i >> 4, nt = i & 15;
            float4 v;
            if (nt == 0) {
                float2 c = s_f[m * 34 + 15];
                v = make_float4(c.x, c.y, 0.f, 0.f);
            } else {
                float2 fp = s_f[m * 34 + 15 + nt];
                float2 fm = s_f[m * 34 + 15 - nt];
                v = make_float4(fp.x + fm.x, fp.y + fm.y, fp.x - fm.x, fp.y - fm.y);
            }
            s_p4[m * 16 + nt] = v;
        }
        __syncthreads();

        // step 2: g[m,q], 4-way q blocking
        if (tid < 248) {
            int m = tid >> 3, q0 = tid & 7;
            float2 S, E;
            __sincosf((float)q0 * TWOPI_32F, &S.y, &S.x);
            E = S;
            const float4* prow = s_p4 + m * 16;
            float4 c0 = prow[0];
            float a0x = c0.x, a0y = c0.y, a1x = c0.x, a1y = c0.y;
            float a2x = c0.x, a2y = c0.y, a3x = c0.x, a3y = c0.y;
            int nt = 1;
#define S2P(PP)                                                              \
            {                                                                \
                float4 pr = prow[nt];                                        \
                float p1 = E.x * pr.x, p2 = E.y * pr.w;                      \
                float p3 = E.x * pr.y, p4 = E.y * pr.z;                      \
                float tx = p1 - p2, ty = p3 + p4;                            \
                a0x += tx; a0y += ty;                                        \
                if (PP == 0) { a1x += tx; a1y += ty; a2x += tx; a2y += ty;   \
                               a3x += tx; a3y += ty; }                       \
                if (PP == 2) { a1x -= tx; a1y -= ty; a2x += tx; a2y += ty;   \
                               a3x -= tx; a3y -= ty; }                       \
                if (PP == 1 || PP == 3) {                                    \
                    float r1 = E.y * pr.x, r2 = E.x * pr.w;                  \
                    float r3 = E.y * pr.y, r4 = E.x * pr.z;                  \
                    float ux = r1 + r2, uy = r3 - r4;                        \
                    if (PP == 1) { a1x -= ux; a1y -= uy; a2x -= tx;          \
                                   a2y -= ty; a3x += ux; a3y += uy; }        \
                    if (PP == 3) { a1x += ux; a1y += uy; a2x -= tx;          \
                                   a2y -= ty; a3x -= ux; a3y -= uy; }        \
                }                                                            \
                float ex = E.x * S.x - E.y * S.y;                            \
                E.y = E.x * S.y + E.y * S.x;                                 \
                E.x = ex;                                                    \
                ++nt;                                                        \
            }
#pragma unroll
            for (int g4 = 0; g4 < 3; ++g4) {
                S2P(1) S2P(2) S2P(3) S2P(0)
            }
            S2P(1) S2P(2) S2P(3)
#undef S2P
            s_g[m * 32 + q0]      = make_float2(a0x, a0y);
            s_g[m * 32 + q0 + 8]  = make_float2(a1x, a1y);
            s_g[m * 32 + q0 + 16] = make_float2(a2x, a2y);
            s_g[m * 32 + q0 + 24] = make_float2(a3x, a3y);
        }
        __syncthreads();

        // pass B: pair g over mt
        for (int i = tid; i < 480; i += 256) {
            int mt = 1 + (i >> 5), q = i & 31;
            float2 gp = s_g[(15 + mt) * 32 + q];
            float2 gm = s_g[(15 - mt) * 32 + q];
            sp3[(mt - 1) * 32 + q] = make_float2(gp.x + gm.x, gp.y - gm.y);
        }
        __syncthreads();

        // step 3 + in-warp pass C
        {
            int q = tid & 31, p0 = tid >> 5;
            float2 S, E;
            __sincosf((float)p0 * TWOPI_32F, &S.y, &S.x);
            E = S;
            float c = s_g[15 * 32 + q].x;
            float a0 = c, a1 = c, a2 = c, a3 = c;
            const float2* pcol = sp3 + q;
            int mt = 1;
#define S3P(PP)                                                              \
            {                                                                \
                float2 v = pcol[(mt - 1) * 32];                              \
                float u1 = E.x * v.x, u2 = E.y * v.y;                        \
                float tx = u1 - u2;                                          \
                a0 += tx;                                                    \
                if (PP == 0) { a1 += tx; a2 += tx; a3 += tx; }               \
                if (PP == 2) { a1 -= tx; a2 += tx; a3 -= tx; }               \
                if (PP == 1 || PP == 3) {                                    \
                    float v1 = E.y * v.x, v2 = E.x * v.y;                    \
                    float ux = v1 + v2;                                      \
                    if (PP == 1) { a1 -= ux; a2 -= tx; a3 += ux; }           \
                    if (PP == 3) { a1 += ux; a2 -= tx; a3 -= ux; }           \
                }                                                            \
                float ex = E.x * S.x - E.y * S.y;                            \
                E.y = E.x * S.y + E.y * S.x;                                 \
                E.x = ex;                                                    \
                ++mt;                                                        \
            }
#pragma unroll
            for (int g4 = 0; g4 < 3; ++g4) {
                S3P(1) S3P(2) S3P(3) S3P(0)
            }
            S3P(1) S3P(2) S3P(3)
#undef S3P
            a0 = fmaxf(a0, 0.f);
            a1 = fmaxf(a1, 0.f);
            a2 = fmaxf(a2, 0.f);
            a3 = fmaxf(a3, 0.f);
            int src = (32 - q) & 31;
            float b0 = __shfl_sync(0xffffffffu, a0, src);
            float b1 = __shfl_sync(0xffffffffu, a1, src);
            float b2 = __shfl_sync(0xffffffffu, a2, src);
            float b3 = __shfl_sync(0xffffffffu, a3, src);
            __syncthreads();   // s_f(bb) reads (pass A) and sp3 reads done
            if (q >= 1 && q <= 15) {
                int qm1 = q - 1;
                sp4[p0 * 17 + qm1]        = make_float2(a0 + b0, a0 - b0);
                sp4[(p0 + 8) * 17 + qm1]  = make_float2(a1 + b1, a1 - b1);
                sp4[(p0 + 16) * 17 + qm1] = make_float2(a2 + b2, a2 - b2);
                sp4[(p0 + 24) * 17 + qm1] = make_float2(a3 + b3, a3 - b3);
            } else if (q == 0) {
                s_r016[p0]      = a0;
                s_r016[p0 + 8]  = a1;
                s_r016[p0 + 16] = a2;
                s_r016[p0 + 24] = a3;
            } else if (q == 16) {
                s_r016[32 + p0]      = a0;
                s_r016[32 + p0 + 8]  = a1;
                s_r016[32 + p0 + 16] = a2;
                s_r016[32 + p0 + 24] = a3;
            }
        }
        __syncthreads();

        // step 4
        {
            int p = tid >> 3, d = tid & 7;
            float2 W1;
            __sincosf((float)d * TWOPI_32F, &W1.y, &W1.x);
            W1.y = -W1.y;
            float2 W = W1;
            float r0 = s_r016[p];
            float r16 = s_r016[32 + p];
            float axv = r0 + ((d & 1) ? -r16 : r16);
            float ayv = 0.f;
            const float2* sd = sp4 + p * 17;
#pragma unroll
            for (int q = 1; q <= 15; ++q) {
                float2 v = sd[q - 1];
                axv += v.x * W.x;
                ayv += v.y * W.y;
                float wx = W.x * W1.x - W.y * W1.y;
                W.y = W.x * W1.y + W.y * W1.x;
                W.x = wx;
            }
            s_u[p * 8 + d] = make_float2(axv, ayv);
        }
        __syncthreads();

        // step 5 (Hermitian half)
        if (tid < 120) {
            int m2 = tid >> 3, d = tid & 7;
            int n2 = 7 + d;
            int mt = m2 - 7;
            float2 W = make_float2(1.f, 0.f), S5;
            {
                float ss, cc;
                __sincosf((float)mt * TWOPI_32F, &ss, &cc);
                S5 = make_float2(cc, -ss);
            }
            float axv = 0.f, ayv = 0.f;
            const float2* ucol = s_u + d;
#pragma unroll
            for (int p = 0; p < 32; ++p) {
                float2 u = ucol[p * 8];
                axv += u.x * W.x - u.y * W.y;
                ayv += u.x * W.y + u.y * W.x;
                float wx = W.x * S5.x - W.y * S5.y;
                W.y = W.x * S5.y + W.y * S5.x;
                W.x = wx;
            }
            size_t plane = (size_t)(2 * bp + bb) * 1024 + f * 32 + j;
            float2* outp = g_xmn + plane * 225;
            outp[m2 * 15 + n2] = make_float2(axv, ayv);
            if (d > 0)
                outp[(14 - m2) * 15 + (14 - n2)] = make_float2(axv, -ayv);
        }
        __syncthreads();   // s_u/s_p4/s_g safe before next iteration
    }
}

// ------------------------- k_G: xmn -> xh2 -> G (per (b,c)) ----------------
__global__ __launch_bounds__(512) void k_G() {
    __shared__ float2 s_xh2[2 * 8 * 225];
    __shared__ float  s_d2i0[1800];
    int bc = blockIdx.x;    // b*32 + c
    int tid = threadIdx.x;  // 512

    for (int i = tid; i < 1800; i += 512) s_d2i0[i] = g_D2I0[i];

    if (tid < 450) {
        int jh = tid / 225, mk = tid % 225;
        float2 acc[8];
#pragma unroll
        for (int l = 0; l < 8; ++l) acc[l] = make_float2(0.f, 0.f);
        const float2* xp = g_xmn + (size_t)bc * 7200 + jh * 16 * 225 + mk;
        const float* dp = g_D2F + jh * 16 * 225 + mk;
#pragma unroll 4
        for (int j = 0; j < 16; ++j) {
            float2 xv = xp[j * 225];
#pragma unroll
            for (int l = 0; l < 8; ++l) {
                float d = dp[l * 7200 + j * 225];
                acc[l].x += d * xv.x;
                acc[l].y += d * xv.y;
            }
        }
#pragma unroll
        for (int l = 0; l < 8; ++l)
            s_xh2[jh * 1800 + l * 225 + mk] = acc[l];
    }
    __syncthreads();

    for (int i = tid; i < 1800; i += 512) {
        float2 a = s_xh2[i], b = s_xh2[1800 + i];
        s_xh2[i] = make_float2(a.x + b.x, a.y + b.y);
    }
    __syncthreads();

    float2* gout = g_G + (size_t)bc * 1800;
    for (int idx = tid; idx < 1800; idx += 512) {
        int l = idx / 225, nk = idx % 225;
        int n = nk / 15, k = nk % 15;
        float ax = 0.f, ay = 0.f;
        if (abs(n - 7) <= l) {
            const float* dp = s_d2i0 + l * 225 + n;
            const float2* xp = s_xh2 + l * 225 + k;
            for (int m = 7 - l; m <= 7 + l; ++m) {
                float d = dp[m * 15];
                float2 v = xp[m * 15];
                ax += d * v.x;
                ay += d * v.y;
            }
        }
        gout[idx] = make_float2(ax, ay);
    }
}

// ------------------------- k_dot: coalesced warp-per-(b,f) -----------------
__global__ __launch_bounds__(256) void k_dot(const float* __restrict__ w2r,
                                             const float* __restrict__ w2i) {
    int c  = blockIdx.x;      // 32
    int ft = blockIdx.y;      // 8
    int tid = threadIdx.x;    // 256
    int w = tid >> 5;         // warp 0..7
    int lane = tid & 31;

    for (int fl = 0; fl < 8; ++fl) {
        int f = ft * 8 + fl;
        const float4* Wr4 = (const float4*)(w2r + ((size_t)c * 64 + f) * 1800);
        const float4* Wi4 = (const float4*)(w2i + ((size_t)c * 64 + f) * 1800);
#pragma unroll
        for (int b2 = 0; b2 < 2; ++b2) {
            int b = 2 * w + b2;
            const float4* X4 = (const float4*)(g_G + ((size_t)b * 32 + c) * 1800);
            float acc = 0.f;
            for (int i = lane; i < 450; i += 32) {
                float4 g0 = X4[2 * i], g1 = X4[2 * i + 1];
                float4 wr = Wr4[i], wi = Wi4[i];
                acc += g0.x * wr.x + g0.y * wi.x + g0.z * wr.y + g0.w * wi.y
                     + g1.x * wr.z + g1.y * wi.z + g1.z * wr.w + g1.w * wi.w;
            }
#pragma unroll
            for (int o = 16; o > 0; o >>= 1)
                acc += __shfl_xor_sync(0xffffffffu, acc, o);
            if (lane == 0)
                g_partial[(c * 8 + ft) * 128 + b * 8 + fl] = acc;
        }
    }
}

// ------------------------- head: reduce + conv1d + BN + FC -----------------
__global__ void k_head(const float* __restrict__ w3, const float* __restrict__ b3,
                       const float* __restrict__ gam, const float* __restrict__ bet,
                       const float* __restrict__ fcw, const float* __restrict__ fcb,
                       float* __restrict__ out) {
    __shared__ float s_feat[16 * 64];
    __shared__ float s_r3[16 * 570];
    __shared__ float s_mu[10], s_rstd[10];
    __shared__ float s_ps[160], s_ps2[160];
    int tid = threadIdx.x;    // 256

    for (int idx = tid; idx < 1024; idx += 256) {
        int b = idx >> 6;
        int f = idx & 63;
        int ft = f >> 3, fl = f & 7;
        float s = 0.f;
#pragma unroll
        for (int c = 0; c < 32; ++c)
            s += g_partial[(c * 8 + ft) * 128 + (b << 3) + fl];
        s_feat[b * 64 + f] = fmaxf(s, 0.f);
    }
    __syncthreads();

    for (int idx = tid; idx < 9120; idx += 256) {
        int b = idx / 570;
        int r = idx % 570;
        int o = r / 57, t = r % 57;
        float s = b3[o];
#pragma unroll
        for (int k = 0; k < 8; ++k)
            s += w3[o * 8 + k] * s_feat[b * 64 + t + k];
        s_r3[idx] = fmaxf(s, 0.f);
    }
    __syncthreads();

    if (tid < 160) {
        int o = tid >> 4, i = tid & 15;
        float s = 0.f, s2 = 0.f;
        for (int idx2 = i; idx2 < 912; idx2 += 16) {
            int b = idx2 / 57, t = idx2 % 57;
            float v = s_r3[b * 570 + o * 57 + t];
            s += v;
            s2 += v * v;
        }
        s_ps[tid] = s;
        s_ps2[tid] = s2;
    }
    __syncthreads();

    if (tid < 10) {
        float s = 0.f, s2 = 0.f;
#pragma unroll
        for (int i = 0; i < 16; ++i) {
            s += s_ps[tid * 16 + i];
            s2 += s_ps2[tid * 16 + i];
        }
        float mu = s / 912.f;
        float var = s2 / 912.f - mu * mu;
        s_mu[tid] = mu;
        s_rstd[tid] = rsqrtf(var + 1e-5f);
    }
    __syncthreads();

    for (int idx = tid; idx < 9120; idx += 256) {
        int o = (idx % 570) / 57;
        s_r3[idx] = gam[o] * (s_r3[idx] - s_mu[o]) * s_rstd[o] + bet[o];
    }
    __syncthreads();

    if (tid < 160) {
        int b = tid / 10, i = tid % 10;
        float s = fcb[i];
        const float* wr = fcw + i * 570;
        const float* xr = s_r3 + b * 570;
        for (int z = 0; z < 570; ++z) s += xr[z] * wr[z];
        out[b * 10 + i] = s;
    }
}

// ---------------------------------------------------------------------------
extern "C" void kernel_launch(void* const* d_in, const int* in_sizes, int n_in,
                              void* d_out, int out_size) {
    const float* x   = (const float*)d_in[0];
    const float* w1r = (const float*)d_in[1];
    const float* w1i = (const float*)d_in[2];
    const float* w2r = (const float*)d_in[3];
    const float* w2i = (const float*)d_in[4];
    const float* c3w = (const float*)d_in[5];
    const float* c3b = (const float*)d_in[6];
    const float* bng = (const float*)d_in[7];
    const float* bnb = (const float*)d_in[8];
    const float* fcw = (const float*)d_in[9];
    const float* fcb = (const float*)d_in[10];
    float* out = (float*)d_out;

    t_setup<<<1, 64>>>();
    t_tables<<<(599048 + 127) / 128, 128>>>();

    k_xh<<<16 * 31, 64>>>(x);
    k_main<<<8 * 32 * 32, 256>>>(w1r, w1i);
    k_G<<<512, 512>>>();
    k_dot<<<dim3(32, 8), 256>>>(w2r, w2i);
    k_head<<<1, 256>>>(c3w, c3b, bng, bnb, fcw, fcb, out);
}

// round 11
// speedup vs baseline: 4.7089x; 1.0089x over previous
#include <cuda_runtime.h>
#include <math.h>

// ---------------------------------------------------------------------------
// S2ConvNet forward pass, sm_103a.
// Shapes: B=16, F1=32, F2=64, B0=32, B1=16, B2=8, M1=31, M2=15.
// ---------------------------------------------------------------------------

#define PI_D 3.141592653589793238462643383279502884
#define TWOPI_32F 0.19634954084936207f   // 2*pi/32

// ------------------------- static device scratch ---------------------------
__device__ float  g_D1F[16 * 64 * 31];                       // [l][j][m]
__device__ __align__(16) float g_D1I[16 * 32 * 31 * 32];     // [l][j][m][n] n padded
__device__ float  g_D2F[8 * 32 * 15 * 15];                   // [l][j][m][k]
__device__ float  g_D2I0[8 * 15 * 15];                       // [l][m][n]
__device__ float2 g_xh[16 * 16 * 31];                        // [b][l][m]
__device__ __align__(16) float2 g_xmn[16 * 32 * 32 * 225];   // [b][c][j][m][k]
__device__ __align__(16) float2 g_G[16 * 32 * 1800];         // [b][c][l][n][k]
__device__ float  g_partial[32 * 8 * 128];

// beta-grid precompute (incl. tan^2(beta/2))
__device__ double g_cb0[64], g_sb0[64], g_w0[64], g_ts0[64];
__device__ double g_cb1[32], g_sb1[32], g_w1[32], g_ts1[32];
__device__ double g_cb2[16], g_sb2[16], g_ts2[16];

__device__ static const double c_F[32] = {
    1.0, 1.0, 2.0, 6.0, 24.0, 120.0, 720.0, 5040.0, 40320.0, 362880.0,
    3628800.0, 39916800.0, 479001600.0, 6227020800.0, 87178291200.0,
    1307674368000.0, 20922789888000.0, 355687428096000.0, 6402373705728000.0,
    121645100408832000.0, 2432902008176640000.0, 51090942171709440000.0,
    1124000727777607680000.0, 25852016738884976640000.0,
    620448401733239439360000.0, 15511210043330985984000000.0,
    403291461126605635584000000.0, 10888869450418352160768000000.0,
    304888344611713860501504000000.0, 8841761993739701954543616000000.0,
    265252859812191058636308480000000.0, 8222838654177922817725562880000000.0
};

__device__ static const double c_R[32] = {
    0.0, 1.0, 1.0/2.0, 1.0/3.0, 1.0/4.0, 1.0/5.0, 1.0/6.0, 1.0/7.0,
    1.0/8.0, 1.0/9.0, 1.0/10.0, 1.0/11.0, 1.0/12.0, 1.0/13.0, 1.0/14.0,
    1.0/15.0, 1.0/16.0, 1.0/17.0, 1.0/18.0, 1.0/19.0, 1.0/20.0, 1.0/21.0,
    1.0/22.0, 1.0/23.0, 1.0/24.0, 1.0/25.0, 1.0/26.0, 1.0/27.0, 1.0/28.0,
    1.0/29.0, 1.0/30.0, 1.0/31.0
};

__device__ __forceinline__ double ipow_d(double x, int e) {
    double r = 1.0;
    while (e) { if (e & 1) r *= x; x *= x; e >>= 1; }
    return r;
}

__device__ double wig_fast(int l, int m, int n, double cb, double sb, double ts) {
    int kmin = max(0, m - n);
    int kmax = min(l + m, l - n);
    if (kmax < kmin) return 0.0;
    double t = sqrt(c_F[l + m] * c_F[l - m] * c_F[l + n] * c_F[l - n])
             / (c_F[kmin] * c_F[l + m - kmin] * c_F[l - n - kmin] * c_F[n - m + kmin]);
    t *= ipow_d(cb, 2 * l + m - n - 2 * kmin) * ipow_d(sb, n - m + 2 * kmin);
    if (kmin & 1) t = -t;
    double s = t;
    for (int k = kmin; k < kmax; ++k) {
        t *= -((double)((l + m - k) * (l - n - k)) *
               c_R[k + 1] * c_R[n - m + k + 1]) * ts;
        s += t;
    }
    return s;
}

// ------------------------- setup kernel ------------------------------------
__global__ void t_setup() {
    int t = threadIdx.x;   // 64
    if (t < 64) {
        double beta = PI_D * (2.0 * t + 1.0) / 128.0;
        double sb, cb;
        sincos(beta * 0.5, &sb, &cb);
        g_cb0[t] = cb; g_sb0[t] = sb;
        g_ts0[t] = (sb * sb) / (cb * cb);
        double sinb = 2.0 * sb * cb;
        double c2 = 1.0 - 2.0 * sinb * sinb;
        double prev = -sinb, cur = sinb, s = 0.0;
#pragma unroll
        for (int k = 0; k < 32; ++k) {
            s += cur * (1.0 / (2.0 * k + 1.0));
            double nx = 2.0 * c2 * cur - prev;
            prev = cur; cur = nx;
        }
        g_w0[t] = (2.0 / 32.0) * sinb * s;
    }
    if (t < 32) {
        double beta = PI_D * (2.0 * t + 1.0) / 64.0;
        double sb, cb;
        sincos(beta * 0.5, &sb, &cb);
        g_cb1[t] = cb; g_sb1[t] = sb;
        g_ts1[t] = (sb * sb) / (cb * cb);
        double sinb = 2.0 * sb * cb;
        double c2 = 1.0 - 2.0 * sinb * sinb;
        double prev = -sinb, cur = sinb, s = 0.0;
#pragma unroll
        for (int k = 0; k < 16; ++k) {
            s += cur * (1.0 / (2.0 * k + 1.0));
            double nx = 2.0 * c2 * cur - prev;
            prev = cur; cur = nx;
        }
        g_w1[t] = (2.0 / 16.0) * sinb * s;
    }
    if (t < 16) {
        double beta = PI_D * (2.0 * t + 1.0) / 32.0;
        double sb, cb;
        sincos(beta * 0.5, &sb, &cb);
        g_cb2[t] = cb; g_sb2[t] = sb;
        g_ts2[t] = (sb * sb) / (cb * cb);
    }
}

// ------------------------- merged table kernel -----------------------------
__global__ void t_tables() {
    int idx = blockIdx.x * blockDim.x + threadIdx.x;
    if (idx < 31744) {
        int l = idx / (64 * 31);
        int j = (idx / 31) % 64;
        int m = idx % 31;
        int mt = m - 15;
        float* base = g_D1F + (size_t)l * 64 * 31 + (size_t)j * 31;
        if (abs(mt) > l) { base[m] = 0.f; return; }
        if (mt < 0) return;
        float v = (float)(g_w0[j] * wig_fast(l, mt, 0, g_cb0[j], g_sb0[j], g_ts0[j]));
        base[m] = v;
        base[30 - m] = (mt & 1) ? -v : v;
        return;
    }
    idx -= 31744;
    if (idx < 507904) {
        int l = idx / 31744;
        int r = idx % 31744;
        int j = r / 992;
        int m = (r / 32) % 31;
        int n = r % 32;
        float* base = g_D1I + (size_t)l * 31744 + (size_t)j * 992;
        if (n == 31) { base[m * 32 + 31] = 0.f; return; }
        int mt = m - 15, nt = n - 15;
        if (abs(mt) > l || abs(nt) > l) { base[m * 32 + n] = 0.f; return; }
        if (nt < abs(mt)) return;
        float vf = (float)((2.0 * l + 1.0) *
                           wig_fast(l, mt, nt, g_cb1[j], g_sb1[j], g_ts1[j]));
        float sv = ((m - n) & 1) ? -vf : vf;
        base[m * 32 + n] = vf;
        base[n * 32 + m] = sv;
        base[(30 - m) * 32 + (30 - n)] = sv;
        base[(30 - n) * 32 + (30 - m)] = vf;
        return;
    }
    idx -= 507904;
    if (idx < 57600) {
        int l = idx / (32 * 225);
        int j = (idx / 225) % 32;
        int m = (idx / 15) % 15;
        int n = idx % 15;
        int mt = m - 7, nt = n - 7;
        float v = 0.f;
        if (abs(mt) <= l && abs(nt) <= l)
            v = (float)(g_w1[j] * wig_fast(l, mt, nt, g_cb1[j], g_sb1[j], g_ts1[j]));
        g_D2F[idx] = v;
        return;
    }
    idx -= 57600;
    if (idx < 1800) {
        int l = idx / 225;
        int m = (idx / 15) % 15;
        int n = idx % 15;
        int mt = m - 7, nt = n - 7;
        float v = 0.f;
        if (abs(mt) <= l && abs(nt) <= l)
            v = (float)((2.0 * l + 1.0) * wig_fast(l, mt, nt, g_cb2[0], g_sb2[0], g_ts2[0]));
        g_D2I0[idx] = v;
    }
}

// ------------------------- stage A: x -> xh --------------------------------
__global__ void k_xh(const float* __restrict__ x) {
    __shared__ float2 s_tw[64];
    __shared__ float2 s_xm[64];
    int b = blockIdx.x / 31;
    int m = blockIdx.x % 31;
    int mt = m - 15;
    int j = threadIdx.x;   // 64

    float sj, cj;
    __sincosf((float)j * (6.2831853071795864769f / 64.f), &sj, &cj);
    s_tw[j] = make_float2(cj, sj);
    __syncthreads();

    const float* xr = x + (size_t)(b * 64 + j) * 64;
    float accx = 0.f, accy = 0.f;
#pragma unroll 8
    for (int t = 0; t < 64; ++t) {
        unsigned r = ((unsigned)(mt * t)) & 63u;
        float2 e = s_tw[r];
        float v = xr[t];
        accx += v * e.x;
        accy -= v * e.y;
    }
    s_xm[j] = make_float2(accx, accy);
    __syncthreads();

    if (j < 16) {
        int l = j;
        float ax = 0.f, ay = 0.f;
        const float* dp = g_D1F + (size_t)l * 64 * 31 + m;
#pragma unroll 8
        for (int jj = 0; jj < 64; ++jj) {
            float d = dp[jj * 31];
            float2 v = s_xm[jj];
            ax += d * v.x;
            ay += d * v.y;
        }
        g_xh[(b * 16 + l) * 31 + m] = make_float2(ax, ay);
    }
}

// ------------------------- stage B+C fused plane kernel (4-plane) ----------
// One block handles FOUR batch planes (4bp..4bp+3) for fixed (f,j): D1I LDG
// and w1 LDS amortized across all four; steps 2-5 looped per plane.
// f-buffer (4 x 1056 float2) lives in dynamic shared memory.
__global__ __launch_bounds__(256, 2) void k_main(const float* __restrict__ w1r,
                                                 const float* __restrict__ w1i) {
    extern __shared__ __align__(16) float2 s_f4[];     // 4 * 1056 f2 = 33.8 KB
    __shared__ float2 s_xh4[4 * 496];                  // 15.9 KB
    __shared__ __align__(16) float2 s_w1[16 * 32];     // 4 KB
    __shared__ float2 s_g[31 * 32];                    // 7.9 KB
    __shared__ __align__(16) float4 s_p4[31 * 16];     // 7.9 KB
    __shared__ float  s_r016[64];

    float2* sp3 = (float2*)s_p4;         // [mt-1][q]  15x32

    int bx = blockIdx.x;
    int bp = bx >> 10;          // 0..3
    int f = (bx >> 5) & 31;
    int j = bx & 31;
    int tid = threadIdx.x;

    for (int i = tid; i < 1984; i += 256)
        s_xh4[i] = g_xh[(4 * bp) * 496 + i];    // 4 contiguous planes
    for (int i = tid; i < 496; i += 256) {
        int l = i / 31, n = i % 31;
        s_w1[l * 32 + n] = make_float2(w1r[f * 496 + i], w1i[f * 496 + i]);
    }
    if (tid < 16) s_w1[tid * 32 + 31] = make_float2(0.f, 0.f);
    __syncthreads();

    // step 1 (all four planes): f[bb][m,n] = sum_l D1I * xh[bb] * conj(w1)
    if (tid < 248) {
        int m = tid >> 3, ng = tid & 7, n0 = ng * 4;
        int am = abs(m - 15);
        int nhi = n0 + 3;
        int anmin = (nhi < 15) ? (15 - nhi) : ((n0 > 15) ? (n0 - 15) : 0);
        int l0 = max(am, anmin);
        float ax[4][4] = {};
        float ay[4][4] = {};
        const float4* dp4 = (const float4*)(g_D1I + (size_t)j * 992 + m * 32 + n0);
        for (int l = l0; l < 16; ++l) {
            float4 d = dp4[l * 7936];
            float4 wA = *(const float4*)(s_w1 + l * 32 + n0);
            float4 wB = *(const float4*)(s_w1 + l * 32 + n0 + 2);
            float wx[4] = {wA.x, wA.z, wB.x, wB.z};
            float wy[4] = {wA.y, wA.w, wB.y, wB.w};
            float dv[4] = {d.x, d.y, d.z, d.w};
            float2 aP[4];
#pragma unroll
            for (int bb = 0; bb < 4; ++bb)
                aP[bb] = s_xh4[bb * 496 + l * 31 + m];
#pragma unroll
            for (int bb = 0; bb < 4; ++bb) {
#pragma unroll
                for (int k = 0; k < 4; ++k) {
                    float tr = aP[bb].x * wx[k] + aP[bb].y * wy[k];
                    float ti = aP[bb].y * wx[k] - aP[bb].x * wy[k];
                    ax[bb][k] += dv[k] * tr;
                    ay[bb][k] += dv[k] * ti;
                }
            }
        }
#pragma unroll
        for (int bb = 0; bb < 4; ++bb) {
            float2* sf = s_f4 + bb * 1056;
            *(float4*)(sf + m * 34 + n0)     = make_float4(ax[bb][0], ay[bb][0], ax[bb][1], ay[bb][1]);
            *(float4*)(sf + m * 34 + n0 + 2) = make_float4(ax[bb][2], ay[bb][2], ax[bb][3], ay[bb][3]);
        }
    }
    __syncthreads();

    for (int bb = 0; bb < 4; ++bb) {
        float2* s_f = s_f4 + bb * 1056;
        float2* sp4 = s_f;              // overlay after pass A consumes s_f
        float2* s_u = s_f + 560;

        // pass A: pair f over nt
        for (int i = tid; i < 496; i += 256) {
            int m = i >> 4, nt = i & 15;
            float4 v;
            if (nt == 0) {
                float2 c = s_f[m * 34 + 15];
                v = make_float4(c.x, c.y, 0.f, 0.f);
            } else {
                float2 fp = s_f[m * 34 + 15 + nt];
                float2 fm = s_f[m * 34 + 15 - nt];
                v = make_float4(fp.x + fm.x, fp.y + fm.y, fp.x - fm.x, fp.y - fm.y);
            }
            s_p4[m * 16 + nt] = v;
        }
        __syncthreads();

        // step 2: g[m,q], 4-way q blocking
        if (tid < 248) {
            int m = tid >> 3, q0 = tid & 7;
            float2 S, E;
            __sincosf((float)q0 * TWOPI_32F, &S.y, &S.x);
            E = S;
            const float4* prow = s_p4 + m * 16;
            float4 c0 = prow[0];
            float a0x = c0.x, a0y = c0.y, a1x = c0.x, a1y = c0.y;
            float a2x = c0.x, a2y = c0.y, a3x = c0.x, a3y = c0.y;
            int nt = 1;
#define S2P(PP)                                                              \
            {                                                                \
                float4 pr = prow[nt];                                        \
                float p1 = E.x * pr.x, p2 = E.y * pr.w;                      \
                float p3 = E.x * pr.y, p4 = E.y * pr.z;                      \
                float tx = p1 - p2, ty = p3 + p4;                            \
                a0x += tx; a0y += ty;                                        \
                if (PP == 0) { a1x += tx; a1y += ty; a2x += tx; a2y += ty;   \
                               a3x += tx; a3y += ty; }                       \
                if (PP == 2) { a1x -= tx; a1y -= ty; a2x += tx; a2y += ty;   \
                               a3x -= tx; a3y -= ty; }                       \
                if (PP == 1 || PP == 3) {                                    \
                    float r1 = E.y * pr.x, r2 = E.x * pr.w;                  \
                    float r3 = E.y * pr.y, r4 = E.x * pr.z;                  \
                    float ux = r1 + r2, uy = r3 - r4;                        \
                    if (PP == 1) { a1x -= ux; a1y -= uy; a2x -= tx;          \
                                   a2y -= ty; a3x += ux; a3y += uy; }        \
                    if (PP == 3) { a1x += ux; a1y += uy; a2x -= tx;          \
                                   a2y -= ty; a3x -= ux; a3y -= uy; }        \
                }                                                            \
                float ex = E.x * S.x - E.y * S.y;                            \
                E.y = E.x * S.y + E.y * S.x;                                 \
                E.x = ex;                                                    \
                ++nt;                                                        \
            }
#pragma unroll
            for (int g4 = 0; g4 < 3; ++g4) {
                S2P(1) S2P(2) S2P(3) S2P(0)
            }
            S2P(1) S2P(2) S2P(3)
#undef S2P
            s_g[m * 32 + q0]      = make_float2(a0x, a0y);
            s_g[m * 32 + q0 + 8]  = make_float2(a1x, a1y);
            s_g[m * 32 + q0 + 16] = make_float2(a2x, a2y);
            s_g[m * 32 + q0 + 24] = make_float2(a3x, a3y);
        }
        __syncthreads();

        // pass B: pair g over mt
        for (int i = tid; i < 480; i += 256) {
            int mt = 1 + (i >> 5), q = i & 31;
            float2 gp = s_g[(15 + mt) * 32 + q];
            float2 gm = s_g[(15 - mt) * 32 + q];
            sp3[(mt - 1) * 32 + q] = make_float2(gp.x + gm.x, gp.y - gm.y);
        }
        __syncthreads();

        // step 3 + in-warp pass C
        {
            int q = tid & 31, p0 = tid >> 5;
            float2 S, E;
            __sincosf((float)p0 * TWOPI_32F, &S.y, &S.x);
            E = S;
            float c = s_g[15 * 32 + q].x;
            float a0 = c, a1 = c, a2 = c, a3 = c;
            const float2* pcol = sp3 + q;
            int mt = 1;
#define S3P(PP)                                                              \
            {                                                                \
                float2 v = pcol[(mt - 1) * 32];                              \
                float u1 = E.x * v.x, u2 = E.y * v.y;                        \
                float tx = u1 - u2;                                          \
                a0 += tx;                                                    \
                if (PP == 0) { a1 += tx; a2 += tx; a3 += tx; }               \
                if (PP == 2) { a1 -= tx; a2 += tx; a3 -= tx; }               \
                if (PP == 1 || PP == 3) {                                    \
                    float v1 = E.y * v.x, v2 = E.x * v.y;                    \
                    float ux = v1 + v2;                                      \
                    if (PP == 1) { a1 -= ux; a2 -= tx; a3 += ux; }           \
                    if (PP == 3) { a1 += ux; a2 -= tx; a3 -= ux; }           \
                }                                                            \
                float ex = E.x * S.x - E.y * S.y;                            \
                E.y = E.x * S.y + E.y * S.x;                                 \
                E.x = ex;                                                    \
                ++mt;                                                        \
            }
#pragma unroll
            for (int g4 = 0; g4 < 3; ++g4) {
                S3P(1) S3P(2) S3P(3) S3P(0)
            }
            S3P(1) S3P(2) S3P(3)
#undef S3P
            a0 = fmaxf(a0, 0.f);
            a1 = fmaxf(a1, 0.f);
            a2 = fmaxf(a2, 0.f);
            a3 = fmaxf(a3, 0.f);
            int src = (32 - q) & 31;
            float b0 = __shfl_sync(0xffffffffu, a0, src);
            float b1 = __shfl_sync(0xffffffffu, a1, src);
            float b2 = __shfl_sync(0xffffffffu, a2, src);
            float b3 = __shfl_sync(0xffffffffu, a3, src);
            __syncthreads();   // pass-A reads of s_f done before sp4 overlay
            if (q >= 1 && q <= 15) {
                int qm1 = q - 1;
                sp4[p0 * 17 + qm1]        = make_float2(a0 + b0, a0 - b0);
                sp4[(p0 + 8) * 17 + qm1]  = make_float2(a1 + b1, a1 - b1);
                sp4[(p0 + 16) * 17 + qm1] = make_float2(a2 + b2, a2 - b2);
                sp4[(p0 + 24) * 17 + qm1] = make_float2(a3 + b3, a3 - b3);
            } else if (q == 0) {
                s_r016[p0]      = a0;
                s_r016[p0 + 8]  = a1;
                s_r016[p0 + 16] = a2;
                s_r016[p0 + 24] = a3;
            } else if (q == 16) {
                s_r016[32 + p0]      = a0;
                s_r016[32 + p0 + 8]  = a1;
                s_r016[32 + p0 + 16] = a2;
                s_r016[32 + p0 + 24] = a3;
            }
        }
        __syncthreads();

        // step 4
        {
            int p = tid >> 3, d = tid & 7;
            float2 W1;
            __sincosf((float)d * TWOPI_32F, &W1.y, &W1.x);
            W1.y = -W1.y;
            float2 W = W1;
            float r0 = s_r016[p];
            float r16 = s_r016[32 + p];
            float axv = r0 + ((d & 1) ? -r16 : r16);
            float ayv = 0.f;
            const float2* sd = sp4 + p * 17;
#pragma unroll
            for (int q = 1; q <= 15; ++q) {
                float2 v = sd[q - 1];
                axv += v.x * W.x;
                ayv += v.y * W.y;
                float wx = W.x * W1.x - W.y * W1.y;
                W.y = W.x * W1.y + W.y * W1.x;
                W.x = wx;
            }
            s_u[p * 8 + d] = make_float2(axv, ayv);
        }
        __syncthreads();

        // step 5 (Hermitian half)
        if (tid < 120) {
            int m2 = tid >> 3, d = tid & 7;
            int n2 = 7 + d;
            int mt = m2 - 7;
            float2 W = make_float2(1.f, 0.f), S5;
            {
                float ss, cc;
                __sincosf((float)mt * TWOPI_32F, &ss, &cc);
                S5 = make_float2(cc, -ss);
            }
            float axv = 0.f, ayv = 0.f;
            const float2* ucol = s_u + d;
#pragma unroll
            for (int p = 0; p < 32; ++p) {
                float2 u = ucol[p * 8];
                axv += u.x * W.x - u.y * W.y;
                ayv += u.x * W.y + u.y * W.x;
                float wx = W.x * S5.x - W.y * S5.y;
                W.y = W.x * S5.y + W.y * S5.x;
                W.x = wx;
            }
            size_t plane = (size_t)(4 * bp + bb) * 1024 + f * 32 + j;
            float2* outp = g_xmn + plane * 225;
            outp[m2 * 15 + n2] = make_float2(axv, ayv);
            if (d > 0)
                outp[(14 - m2) * 15 + (14 - n2)] = make_float2(axv, -ayv);
        }
        __syncthreads();
    }
}

// ------------------------- k_G: xmn -> xh2 -> G (per (b,c)) ----------------
__global__ __launch_bounds__(512) void k_G() {
    __shared__ float2 s_xh2[2 * 8 * 225];
    __shared__ float  s_d2i0[1800];
    int bc = blockIdx.x;    // b*32 + c
    int tid = threadIdx.x;  // 512

    for (int i = tid; i < 1800; i += 512) s_d2i0[i] = g_D2I0[i];

    if (tid < 450) {
        int jh = tid / 225, mk = tid % 225;
        float2 acc[8];
#pragma unroll
        for (int l = 0; l < 8; ++l) acc[l] = make_float2(0.f, 0.f);
        const float2* xp = g_xmn + (size_t)bc * 7200 + jh * 16 * 225 + mk;
        const float* dp = g_D2F + jh * 16 * 225 + mk;
#pragma unroll 4
        for (int j = 0; j < 16; ++j) {
            float2 xv = xp[j * 225];
#pragma unroll
            for (int l = 0; l < 8; ++l) {
                float d = dp[l * 7200 + j * 225];
                acc[l].x += d * xv.x;
                acc[l].y += d * xv.y;
            }
        }
#pragma unroll
        for (int l = 0; l < 8; ++l)
            s_xh2[jh * 1800 + l * 225 + mk] = acc[l];
    }
    __syncthreads();

    for (int i = tid; i < 1800; i += 512) {
        float2 a = s_xh2[i], b = s_xh2[1800 + i];
        s_xh2[i] = make_float2(a.x + b.x, a.y + b.y);
    }
    __syncthreads();

    float2* gout = g_G + (size_t)bc * 1800;
    for (int idx = tid; idx < 1800; idx += 512) {
        int l = idx / 225, nk = idx % 225;
        int n = nk / 15, k = nk % 15;
        float ax = 0.f, ay = 0.f;
        if (abs(n - 7) <= l) {
            const float* dp = s_d2i0 + l * 225 + n;
            const float2* xp = s_xh2 + l * 225 + k;
            for (int m = 7 - l; m <= 7 + l; ++m) {
                float d = dp[m * 15];
                float2 v = xp[m * 15];
                ax += d * v.x;
                ay += d * v.y;
            }
        }
        gout[idx] = make_float2(ax, ay);
    }
}

// ------------------------- k_dot: coalesced warp-per-(b,f), z-split --------
__global__ __launch_bounds__(256) void k_dot(const float* __restrict__ w2r,
                                             const float* __restrict__ w2i) {
    int c  = blockIdx.x;      // 32
    int ft = blockIdx.y;      // 8
    int fz = blockIdx.z;      // 4 (each handles 2 fl values)
    int tid = threadIdx.x;    // 256
    int w = tid >> 5;
    int lane = tid & 31;

#pragma unroll
    for (int fi = 0; fi < 2; ++fi) {
        int fl = fz * 2 + fi;
        int f = ft * 8 + fl;
        const float4* Wr4 = (const float4*)(w2r + ((size_t)c * 64 + f) * 1800);
        const float4* Wi4 = (const float4*)(w2i + ((size_t)c * 64 + f) * 1800);
#pragma unroll
        for (int b2 = 0; b2 < 2; ++b2) {
            int b = 2 * w + b2;
            const float4* X4 = (const float4*)(g_G + ((size_t)b * 32 + c) * 1800);
            float acc = 0.f;
            for (int i = lane; i < 450; i += 32) {
                float4 g0 = X4[2 * i], g1 = X4[2 * i + 1];
                float4 wr = Wr4[i], wi = Wi4[i];
                acc += g0.x * wr.x + g0.y * wi.x + g0.z * wr.y + g0.w * wi.y
                     + g1.x * wr.z + g1.y * wi.z + g1.z * wr.w + g1.w * wi.w;
            }
#pragma unroll
            for (int o = 16; o > 0; o >>= 1)
                acc += __shfl_xor_sync(0xffffffffu, acc, o);
            if (lane == 0)
                g_partial[(c * 8 + ft) * 128 + b * 8 + fl] = acc;
        }
    }
}

// ------------------------- head: reduce + conv1d + BN + FC -----------------
__global__ void k_head(const float* __restrict__ w3, const float* __restrict__ b3,
                       const float* __restrict__ gam, const float* __restrict__ bet,
                       const float* __restrict__ fcw, const float* __restrict__ fcb,
                       float* __restrict__ out) {
    __shared__ float s_feat[16 * 64];
    __shared__ float s_r3[16 * 570];
    __shared__ float s_mu[10], s_rstd[10];
    __shared__ float s_ps[160], s_ps2[160];
    int tid = threadIdx.x;    // 256

    for (int idx = tid; idx < 1024; idx += 256) {
        int b = idx >> 6;
        int f = idx & 63;
        int ft = f >> 3, fl = f & 7;
        float s = 0.f;
#pragma unroll
        for (int c = 0; c < 32; ++c)
            s += g_partial[(c * 8 + ft) * 128 + (b << 3) + fl];
        s_feat[b * 64 + f] = fmaxf(s, 0.f);
    }
    __syncthreads();

    for (int idx = tid; idx < 9120; idx += 256) {
        int b = idx / 570;
        int r = idx % 570;
        int o = r / 57, t = r % 57;
        float s = b3[o];
#pragma unroll
        for (int k = 0; k < 8; ++k)
            s += w3[o * 8 + k] * s_feat[b * 64 + t + k];
        s_r3[idx] = fmaxf(s, 0.f);
    }
    __syncthreads();

    if (tid < 160) {
        int o = tid >> 4, i = tid & 15;
        float s = 0.f, s2 = 0.f;
        for (int idx2 = i; idx2 < 912; idx2 += 16) {
            int b = idx2 / 57, t = idx2 % 57;
            float v = s_r3[b * 570 + o * 57 + t];
            s += v;
            s2 += v * v;
        }
        s_ps[tid] = s;
        s_ps2[tid] = s2;
    }
    __syncthreads();

    if (tid < 10) {
        float s = 0.f, s2 = 0.f;
#pragma unroll
        for (int i = 0; i < 16; ++i) {
            s += s_ps[tid * 16 + i];
            s2 += s_ps2[tid * 16 + i];
        }
        float mu = s / 912.f;
        float var = s2 / 912.f - mu * mu;
        s_mu[tid] = mu;
        s_rstd[tid] = rsqrtf(var + 1e-5f);
    }
    __syncthreads();

    for (int idx = tid; idx < 9120; idx += 256) {
        int o = (idx % 570) / 57;
        s_r3[idx] = gam[o] * (s_r3[idx] - s_mu[o]) * s_rstd[o] + bet[o];
    }
    __syncthreads();

    if (tid < 160) {
        int b = tid / 10, i = tid % 10;
        float s = fcb[i];
        const float* wr = fcw + i * 570;
        const float* xr = s_r3 + b * 570;
        for (int z = 0; z < 570; ++z) s += xr[z] * wr[z];
        out[b * 10 + i] = s;
    }
}

// ---------------------------------------------------------------------------
extern "C" void kernel_launch(void* const* d_in, const int* in_sizes, int n_in,
                              void* d_out, int out_size) {
    const float* x   = (const float*)d_in[0];
    const float* w1r = (const float*)d_in[1];
    const float* w1i = (const float*)d_in[2];
    const float* w2r = (const float*)d_in[3];
    const float* w2i = (const float*)d_in[4];
    const float* c3w = (const float*)d_in[5];
    const float* c3b = (const float*)d_in[6];
    const float* bng = (const float*)d_in[7];
    const float* bnb = (const float*)d_in[8];
    const float* fcw = (const float*)d_in[9];
    const float* fcb = (const float*)d_in[10];
    float* out = (float*)d_out;

    static const int kMainDynSmem = 4 * 1056 * (int)sizeof(float2);   // 33792
    cudaFuncSetAttribute(k_main, cudaFuncAttributeMaxDynamicSharedMemorySize,
                         kMainDynSmem);

    t_setup<<<1, 64>>>();
    t_tables<<<(599048 + 127) / 128, 128>>>();

    k_xh<<<16 * 31, 64>>>(x);
    k_main<<<4 * 32 * 32, 256, kMainDynSmem>>>(w1r, w1i);
    k_G<<<512, 512>>>();
    k_dot<<<dim3(32, 8, 4), 256>>>(w2r, w2i);
    k_head<<<1, 256>>>(c3w, c3b, bng, bnb, fcw, fcb, out);
}

// round 12
// speedup vs baseline: 4.7152x; 1.0013x over previous
#include <cuda_runtime.h>
#include <math.h>

// ---------------------------------------------------------------------------
// S2ConvNet forward pass, sm_103a.
// Shapes: B=16, F1=32, F2=64, B0=32, B1=16, B2=8, M1=31, M2=15.
// ---------------------------------------------------------------------------

#define PI_D 3.141592653589793238462643383279502884
#define TWOPI_32F 0.19634954084936207f   // 2*pi/32

// ------------------------- static device scratch ---------------------------
__device__ float  g_D1F[16 * 64 * 31];                       // [l][j][m]
__device__ __align__(16) float g_D1I[16 * 32 * 31 * 32];     // [l][j][m][n] n padded
__device__ float  g_D2F[8 * 32 * 15 * 15];                   // [l][j][m][k]
__device__ float  g_D2I0[8 * 15 * 15];                       // [l][m][n]
__device__ float2 g_xh[16 * 16 * 31];                        // [b][l][m]
__device__ __align__(16) float2 g_xmn[16 * 32 * 32 * 225];   // [b][c][j][m][k]
__device__ __align__(16) float2 g_G[16 * 32 * 1800];         // [b][c][l][n][k]
__device__ float  g_partial[32 * 8 * 128];

// beta-grid precompute (incl. tan^2(beta/2))
__device__ double g_cb0[64], g_sb0[64], g_w0[64], g_ts0[64];
__device__ double g_cb1[32], g_sb1[32], g_w1[32], g_ts1[32];
__device__ double g_cb2[16], g_sb2[16], g_ts2[16];

__device__ static const double c_F[32] = {
    1.0, 1.0, 2.0, 6.0, 24.0, 120.0, 720.0, 5040.0, 40320.0, 362880.0,
    3628800.0, 39916800.0, 479001600.0, 6227020800.0, 87178291200.0,
    1307674368000.0, 20922789888000.0, 355687428096000.0, 6402373705728000.0,
    121645100408832000.0, 2432902008176640000.0, 51090942171709440000.0,
    1124000727777607680000.0, 25852016738884976640000.0,
    620448401733239439360000.0, 15511210043330985984000000.0,
    403291461126605635584000000.0, 10888869450418352160768000000.0,
    304888344611713860501504000000.0, 8841761993739701954543616000000.0,
    265252859812191058636308480000000.0, 8222838654177922817725562880000000.0
};

__device__ static const double c_R[32] = {
    0.0, 1.0, 1.0/2.0, 1.0/3.0, 1.0/4.0, 1.0/5.0, 1.0/6.0, 1.0/7.0,
    1.0/8.0, 1.0/9.0, 1.0/10.0, 1.0/11.0, 1.0/12.0, 1.0/13.0, 1.0/14.0,
    1.0/15.0, 1.0/16.0, 1.0/17.0, 1.0/18.0, 1.0/19.0, 1.0/20.0, 1.0/21.0,
    1.0/22.0, 1.0/23.0, 1.0/24.0, 1.0/25.0, 1.0/26.0, 1.0/27.0, 1.0/28.0,
    1.0/29.0, 1.0/30.0, 1.0/31.0
};

__device__ __forceinline__ double ipow_d(double x, int e) {
    double r = 1.0;
    while (e) { if (e & 1) r *= x; x *= x; e >>= 1; }
    return r;
}

__device__ double wig_fast(int l, int m, int n, double cb, double sb, double ts) {
    int kmin = max(0, m - n);
    int kmax = min(l + m, l - n);
    if (kmax < kmin) return 0.0;
    double t = sqrt(c_F[l + m] * c_F[l - m] * c_F[l + n] * c_F[l - n])
             / (c_F[kmin] * c_F[l + m - kmin] * c_F[l - n - kmin] * c_F[n - m + kmin]);
    t *= ipow_d(cb, 2 * l + m - n - 2 * kmin) * ipow_d(sb, n - m + 2 * kmin);
    if (kmin & 1) t = -t;
    double s = t;
    for (int k = kmin; k < kmax; ++k) {
        t *= -((double)((l + m - k) * (l - n - k)) *
               c_R[k + 1] * c_R[n - m + k + 1]) * ts;
        s += t;
    }
    return s;
}

// ------------------------- setup kernel ------------------------------------
__global__ void t_setup() {
    int t = threadIdx.x;   // 64
    if (t < 64) {
        double beta = PI_D * (2.0 * t + 1.0) / 128.0;
        double sb, cb;
        sincos(beta * 0.5, &sb, &cb);
        g_cb0[t] = cb; g_sb0[t] = sb;
        g_ts0[t] = (sb * sb) / (cb * cb);
        double sinb = 2.0 * sb * cb;
        double c2 = 1.0 - 2.0 * sinb * sinb;
        double prev = -sinb, cur = sinb, s = 0.0;
#pragma unroll
        for (int k = 0; k < 32; ++k) {
            s += cur * (1.0 / (2.0 * k + 1.0));
            double nx = 2.0 * c2 * cur - prev;
            prev = cur; cur = nx;
        }
        g_w0[t] = (2.0 / 32.0) * sinb * s;
    }
    if (t < 32) {
        double beta = PI_D * (2.0 * t + 1.0) / 64.0;
        double sb, cb;
        sincos(beta * 0.5, &sb, &cb);
        g_cb1[t] = cb; g_sb1[t] = sb;
        g_ts1[t] = (sb * sb) / (cb * cb);
        double sinb = 2.0 * sb * cb;
        double c2 = 1.0 - 2.0 * sinb * sinb;
        double prev = -sinb, cur = sinb, s = 0.0;
#pragma unroll
        for (int k = 0; k < 16; ++k) {
            s += cur * (1.0 / (2.0 * k + 1.0));
            double nx = 2.0 * c2 * cur - prev;
            prev = cur; cur = nx;
        }
        g_w1[t] = (2.0 / 16.0) * sinb * s;
    }
    if (t < 16) {
        double beta = PI_D * (2.0 * t + 1.0) / 32.0;
        double sb, cb;
        sincos(beta * 0.5, &sb, &cb);
        g_cb2[t] = cb; g_sb2[t] = sb;
        g_ts2[t] = (sb * sb) / (cb * cb);
    }
}

// ------------------------- merged table kernel -----------------------------
__global__ void t_tables() {
    int idx = blockIdx.x * blockDim.x + threadIdx.x;
    if (idx < 31744) {
        int l = idx / (64 * 31);
        int j = (idx / 31) % 64;
        int m = idx % 31;
        int mt = m - 15;
        float* base = g_D1F + (size_t)l * 64 * 31 + (size_t)j * 31;
        if (abs(mt) > l) { base[m] = 0.f; return; }
        if (mt < 0) return;
        float v = (float)(g_w0[j] * wig_fast(l, mt, 0, g_cb0[j], g_sb0[j], g_ts0[j]));
        base[m] = v;
        base[30 - m] = (mt & 1) ? -v : v;
        return;
    }
    idx -= 31744;
    if (idx < 507904) {
        int l = idx / 31744;
        int r = idx % 31744;
        int j = r / 992;
        int m = (r / 32) % 31;
        int n = r % 32;
        float* base = g_D1I + (size_t)l * 31744 + (size_t)j * 992;
        if (n == 31) { base[m * 32 + 31] = 0.f; return; }
        int mt = m - 15, nt = n - 15;
        if (abs(mt) > l || abs(nt) > l) { base[m * 32 + n] = 0.f; return; }
        if (nt < abs(mt)) return;
        float vf = (float)((2.0 * l + 1.0) *
                           wig_fast(l, mt, nt, g_cb1[j], g_sb1[j], g_ts1[j]));
        float sv = ((m - n) & 1) ? -vf : vf;
        base[m * 32 + n] = vf;
        base[n * 32 + m] = sv;
        base[(30 - m) * 32 + (30 - n)] = sv;
        base[(30 - n) * 32 + (30 - m)] = vf;
        return;
    }
    idx -= 507904;
    if (idx < 57600) {
        int l = idx / (32 * 225);
        int j = (idx / 225) % 32;
        int m = (idx / 15) % 15;
        int n = idx % 15;
        int mt = m - 7, nt = n - 7;
        float v = 0.f;
        if (abs(mt) <= l && abs(nt) <= l)
            v = (float)(g_w1[j] * wig_fast(l, mt, nt, g_cb1[j], g_sb1[j], g_ts1[j]));
        g_D2F[idx] = v;
        return;
    }
    idx -= 57600;
    if (idx < 1800) {
        int l = idx / 225;
        int m = (idx / 15) % 15;
        int n = idx % 15;
        int mt = m - 7, nt = n - 7;
        float v = 0.f;
        if (abs(mt) <= l && abs(nt) <= l)
            v = (float)((2.0 * l + 1.0) * wig_fast(l, mt, nt, g_cb2[0], g_sb2[0], g_ts2[0]));
        g_D2I0[idx] = v;
    }
}

// ------------------------- stage A: x -> xh --------------------------------
__global__ void k_xh(const float* __restrict__ x) {
    __shared__ float2 s_tw[64];
    __shared__ float2 s_xm[64];
    int b = blockIdx.x / 31;
    int m = blockIdx.x % 31;
    int mt = m - 15;
    int j = threadIdx.x;   // 64

    float sj, cj;
    __sincosf((float)j * (6.2831853071795864769f / 64.f), &sj, &cj);
    s_tw[j] = make_float2(cj, sj);
    __syncthreads();

    const float* xr = x + (size_t)(b * 64 + j) * 64;
    float accx = 0.f, accy = 0.f;
#pragma unroll 8
    for (int t = 0; t < 64; ++t) {
        unsigned r = ((unsigned)(mt * t)) & 63u;
        float2 e = s_tw[r];
        float v = xr[t];
        accx += v * e.x;
        accy -= v * e.y;
    }
    s_xm[j] = make_float2(accx, accy);
    __syncthreads();

    if (j < 16) {
        int l = j;
        float ax = 0.f, ay = 0.f;
        const float* dp = g_D1F + (size_t)l * 64 * 31 + m;
#pragma unroll 8
        for (int jj = 0; jj < 64; ++jj) {
            float d = dp[jj * 31];
            float2 v = s_xm[jj];
            ax += d * v.x;
            ay += d * v.y;
        }
        g_xh[(b * 16 + l) * 31 + m] = make_float2(ax, ay);
    }
}

// ------------------------- stage B+C fused plane kernel (b-paired) ---------
// One block handles TWO batch planes (2bp, 2bp+1) for fixed (f,j).
__global__ __launch_bounds__(256, 3) void k_main(const float* __restrict__ w1r,
                                                 const float* __restrict__ w1i) {
    __shared__ float2 s_xh2[2 * 496];                  // 7.9 KB
    __shared__ __align__(16) float2 s_w1[16 * 32];     // 4 KB
    __shared__ __align__(16) float2 s_f2[2 * 1056];    // 16.9 KB (f OR sp4+u per bb)
    __shared__ float2 s_g[31 * 32];                    // 7.9 KB
    __shared__ __align__(16) float4 s_p4[31 * 16];     // 7.9 KB pairing scratch
    __shared__ float  s_r016[64];

    float2* sp3 = (float2*)s_p4;         // [mt-1][q]  15x32

    int bx = blockIdx.x;
    int bp = bx >> 10;          // 0..7
    int f = (bx >> 5) & 31;
    int j = bx & 31;
    int tid = threadIdx.x;

    for (int i = tid; i < 992; i += 256)
        s_xh2[i] = g_xh[(2 * bp) * 496 + i];
    for (int i = tid; i < 496; i += 256) {
        int l = i / 31, n = i % 31;
        s_w1[l * 32 + n] = make_float2(w1r[f * 496 + i], w1i[f * 496 + i]);
    }
    if (tid < 16) s_w1[tid * 32 + 31] = make_float2(0.f, 0.f);
    __syncthreads();

    // step 1 (both planes)
    if (tid < 248) {
        int m = tid >> 3, ng = tid & 7, n0 = ng * 4;
        int am = abs(m - 15);
        int nhi = n0 + 3;
        int anmin = (nhi < 15) ? (15 - nhi) : ((n0 > 15) ? (n0 - 15) : 0);
        int l0 = max(am, anmin);
        float ax[2][4] = {{0.f, 0.f, 0.f, 0.f}, {0.f, 0.f, 0.f, 0.f}};
        float ay[2][4] = {{0.f, 0.f, 0.f, 0.f}, {0.f, 0.f, 0.f, 0.f}};
        const float4* dp4 = (const float4*)(g_D1I + (size_t)j * 992 + m * 32 + n0);
        for (int l = l0; l < 16; ++l) {
            float4 d = dp4[l * 7936];
            float2 aA = s_xh2[l * 31 + m];
            float2 aB = s_xh2[496 + l * 31 + m];
            float4 wA = *(const float4*)(s_w1 + l * 32 + n0);
            float4 wB = *(const float4*)(s_w1 + l * 32 + n0 + 2);
            float wx[4] = {wA.x, wA.z, wB.x, wB.z};
            float wy[4] = {wA.y, wA.w, wB.y, wB.w};
            float dv[4] = {d.x, d.y, d.z, d.w};
#pragma unroll
            for (int k = 0; k < 4; ++k) {
                float tr = aA.x * wx[k] + aA.y * wy[k];
                float ti = aA.y * wx[k] - aA.x * wy[k];
                ax[0][k] += dv[k] * tr; ay[0][k] += dv[k] * ti;
                tr = aB.x * wx[k] + aB.y * wy[k];
                ti = aB.y * wx[k] - aB.x * wy[k];
                ax[1][k] += dv[k] * tr; ay[1][k] += dv[k] * ti;
            }
        }
#pragma unroll
        for (int bb = 0; bb < 2; ++bb) {
            float2* sf = s_f2 + bb * 1056;
            *(float4*)(sf + m * 34 + n0)     = make_float4(ax[bb][0], ay[bb][0], ax[bb][1], ay[bb][1]);
            *(float4*)(sf + m * 34 + n0 + 2) = make_float4(ax[bb][2], ay[bb][2], ax[bb][3], ay[bb][3]);
        }
    }
    __syncthreads();

    for (int bb = 0; bb < 2; ++bb) {
        float2* s_f = s_f2 + bb * 1056;
        float2* sp4 = s_f;
        float2* s_u = s_f + 560;

        // pass A: pair f over nt
        for (int i = tid; i < 496; i += 256) {
            int m = i >> 4, nt = i & 15;
            float4 v;
            if (nt == 0) {
                float2 c = s_f[m * 34 + 15];
                v = make_float4(c.x, c.y, 0.f, 0.f);
            } else {
                float2 fp = s_f[m * 34 + 15 + nt];
                float2 fm = s_f[m * 34 + 15 - nt];
                v = make_float4(fp.x + fm.x, fp.y + fm.y, fp.x - fm.x, fp.y - fm.y);
            }
            s_p4[m * 16 + nt] = v;
        }
        __syncthreads();

        // step 2: g[m,q], 4-way q blocking
        if (tid < 248) {
            int m = tid >> 3, q0 = tid & 7;
            float2 S, E;
            __sincosf((float)q0 * TWOPI_32F, &S.y, &S.x);
            E = S;
            const float4* prow = s_p4 + m * 16;
            float4 c0 = prow[0];
            float a0x = c0.x, a0y = c0.y, a1x = c0.x, a1y = c0.y;
            float a2x = c0.x, a2y = c0.y, a3x = c0.x, a3y = c0.y;
            int nt = 1;
#define S2P(PP)                                                              \
            {                                                                \
                float4 pr = prow[nt];                                        \
                float p1 = E.x * pr.x, p2 = E.y * pr.w;                      \
                float p3 = E.x * pr.y, p4 = E.y * pr.z;                      \
                float tx = p1 - p2, ty = p3 + p4;                            \
                a0x += tx; a0y += ty;                                        \
                if (PP == 0) { a1x += tx; a1y += ty; a2x += tx; a2y += ty;   \
                               a3x += tx; a3y += ty; }                       \
                if (PP == 2) { a1x -= tx; a1y -= ty; a2x += tx; a2y += ty;   \
                               a3x -= tx; a3y -= ty; }                       \
                if (PP == 1 || PP == 3) {                                    \
                    float r1 = E.y * pr.x, r2 = E.x * pr.w;                  \
                    float r3 = E.y * pr.y, r4 = E.x * pr.z;                  \
                    float ux = r1 + r2, uy = r3 - r4;                        \
                    if (PP == 1) { a1x -= ux; a1y -= uy; a2x -= tx;          \
                                   a2y -= ty; a3x += ux; a3y += uy; }        \
                    if (PP == 3) { a1x += ux; a1y += uy; a2x -= tx;          \
                                   a2y -= ty; a3x -= ux; a3y -= uy; }        \
                }                                                            \
                float ex = E.x * S.x - E.y * S.y;                            \
                E.y = E.x * S.y + E.y * S.x;                                 \
                E.x = ex;                                                    \
                ++nt;                                                        \
            }
#pragma unroll
            for (int g4 = 0; g4 < 3; ++g4) {
                S2P(1) S2P(2) S2P(3) S2P(0)
            }
            S2P(1) S2P(2) S2P(3)
#undef S2P
            s_g[m * 32 + q0]      = make_float2(a0x, a0y);
            s_g[m * 32 + q0 + 8]  = make_float2(a1x, a1y);
            s_g[m * 32 + q0 + 16] = make_float2(a2x, a2y);
            s_g[m * 32 + q0 + 24] = make_float2(a3x, a3y);
        }
        __syncthreads();

        // pass B: pair g over mt
        for (int i = tid; i < 480; i += 256) {
            int mt = 1 + (i >> 5), q = i & 31;
            float2 gp = s_g[(15 + mt) * 32 + q];
            float2 gm = s_g[(15 - mt) * 32 + q];
            sp3[(mt - 1) * 32 + q] = make_float2(gp.x + gm.x, gp.y - gm.y);
        }
        __syncthreads();

        // step 3 + in-warp pass C
        {
            int q = tid & 31, p0 = tid >> 5;
            float2 S, E;
            __sincosf((float)p0 * TWOPI_32F, &S.y, &S.x);
            E = S;
            float c = s_g[15 * 32 + q].x;
            float a0 = c, a1 = c, a2 = c, a3 = c;
            const float2* pcol = sp3 + q;
            int mt = 1;
#define S3P(PP)                                                              \
            {                                                                \
                float2 v = pcol[(mt - 1) * 32];                              \
                float u1 = E.x * v.x, u2 = E.y * v.y;                        \
                float tx = u1 - u2;                                          \
                a0 += tx;                                                    \
                if (PP == 0) { a1 += tx; a2 += tx; a3 += tx; }               \
                if (PP == 2) { a1 -= tx; a2 += tx; a3 -= tx; }               \
                if (PP == 1 || PP == 3) {                                    \
                    float v1 = E.y * v.x, v2 = E.x * v.y;                    \
                    float ux = v1 + v2;                                      \
                    if (PP == 1) { a1 -= ux; a2 -= tx; a3 += ux; }           \
                    if (PP == 3) { a1 += ux; a2 -= tx; a3 -= ux; }           \
                }                                                            \
                float ex = E.x * S.x - E.y * S.y;                            \
                E.y = E.x * S.y + E.y * S.x;                                 \
                E.x = ex;                                                    \
                ++mt;                                                        \
            }
#pragma unroll
            for (int g4 = 0; g4 < 3; ++g4) {
                S3P(1) S3P(2) S3P(3) S3P(0)
            }
            S3P(1) S3P(2) S3P(3)
#undef S3P
            a0 = fmaxf(a0, 0.f);
            a1 = fmaxf(a1, 0.f);
            a2 = fmaxf(a2, 0.f);
            a3 = fmaxf(a3, 0.f);
            int src = (32 - q) & 31;
            float b0 = __shfl_sync(0xffffffffu, a0, src);
            float b1 = __shfl_sync(0xffffffffu, a1, src);
            float b2 = __shfl_sync(0xffffffffu, a2, src);
            float b3 = __shfl_sync(0xffffffffu, a3, src);
            __syncthreads();
            if (q >= 1 && q <= 15) {
                int qm1 = q - 1;
                sp4[p0 * 17 + qm1]        = make_float2(a0 + b0, a0 - b0);
                sp4[(p0 + 8) * 17 + qm1]  = make_float2(a1 + b1, a1 - b1);
                sp4[(p0 + 16) * 17 + qm1] = make_float2(a2 + b2, a2 - b2);
                sp4[(p0 + 24) * 17 + qm1] = make_float2(a3 + b3, a3 - b3);
            } else if (q == 0) {
                s_r016[p0]      = a0;
                s_r016[p0 + 8]  = a1;
                s_r016[p0 + 16] = a2;
                s_r016[p0 + 24] = a3;
            } else if (q == 16) {
                s_r016[32 + p0]      = a0;
                s_r016[32 + p0 + 8]  = a1;
                s_r016[32 + p0 + 16] = a2;
                s_r016[32 + p0 + 24] = a3;
            }
        }
        __syncthreads();

        // step 4
        {
            int p = tid >> 3, d = tid & 7;
            float2 W1;
            __sincosf((float)d * TWOPI_32F, &W1.y, &W1.x);
            W1.y = -W1.y;
            float2 W = W1;
            float r0 = s_r016[p];
            float r16 = s_r016[32 + p];
            float axv = r0 + ((d & 1) ? -r16 : r16);
            float ayv = 0.f;
            const float2* sd = sp4 + p * 17;
#pragma unroll
            for (int q = 1; q <= 15; ++q) {
                float2 v = sd[q - 1];
                axv += v.x * W.x;
                ayv += v.y * W.y;
                float wx = W.x * W1.x - W.y * W1.y;
                W.y = W.x * W1.y + W.y * W1.x;
                W.x = wx;
            }
            s_u[p * 8 + d] = make_float2(axv, ayv);
        }
        __syncthreads();

        // step 5 (Hermitian half)
        if (tid < 120) {
            int m2 = tid >> 3, d = tid & 7;
            int n2 = 7 + d;
            int mt = m2 - 7;
            float2 W = make_float2(1.f, 0.f), S5;
            {
                float ss, cc;
                __sincosf((float)mt * TWOPI_32F, &ss, &cc);
                S5 = make_float2(cc, -ss);
            }
            float axv = 0.f, ayv = 0.f;
            const float2* ucol = s_u + d;
#pragma unroll
            for (int p = 0; p < 32; ++p) {
                float2 u = ucol[p * 8];
                axv += u.x * W.x - u.y * W.y;
                ayv += u.x * W.y + u.y * W.x;
                float wx = W.x * S5.x - W.y * S5.y;
                W.y = W.x * S5.y + W.y * S5.x;
                W.x = wx;
            }
            size_t plane = (size_t)(2 * bp + bb) * 1024 + f * 32 + j;
            float2* outp = g_xmn + plane * 225;
            outp[m2 * 15 + n2] = make_float2(axv, ayv);
            if (d > 0)
                outp[(14 - m2) * 15 + (14 - n2)] = make_float2(axv, -ayv);
        }
        __syncthreads();
    }
}

// ------------------------- k_G: xmn -> xh2 -> G (per (b,c)) ----------------
__global__ __launch_bounds__(512) void k_G() {
    __shared__ float2 s_xh2[2 * 8 * 225];
    __shared__ float  s_d2i0[1800];
    int bc = blockIdx.x;    // b*32 + c
    int tid = threadIdx.x;  // 512

    for (int i = tid; i < 1800; i += 512) s_d2i0[i] = g_D2I0[i];

    if (tid < 450) {
        int jh = tid / 225, mk = tid % 225;
        float2 acc[8];
#pragma unroll
        for (int l = 0; l < 8; ++l) acc[l] = make_float2(0.f, 0.f);
        const float2* xp = g_xmn + (size_t)bc * 7200 + jh * 16 * 225 + mk;
        const float* dp = g_D2F + jh * 16 * 225 + mk;
#pragma unroll 4
        for (int j = 0; j < 16; ++j) {
            float2 xv = xp[j * 225];
#pragma unroll
            for (int l = 0; l < 8; ++l) {
                float d = dp[l * 7200 + j * 225];
                acc[l].x += d * xv.x;
                acc[l].y += d * xv.y;
            }
        }
#pragma unroll
        for (int l = 0; l < 8; ++l)
            s_xh2[jh * 1800 + l * 225 + mk] = acc[l];
    }
    __syncthreads();

    for (int i = tid; i < 1800; i += 512) {
        float2 a = s_xh2[i], b = s_xh2[1800 + i];
        s_xh2[i] = make_float2(a.x + b.x, a.y + b.y);
    }
    __syncthreads();

    float2* gout = g_G + (size_t)bc * 1800;
    for (int idx = tid; idx < 1800; idx += 512) {
        int l = idx / 225, nk = idx % 225;
        int n = nk / 15, k = nk % 15;
        float ax = 0.f, ay = 0.f;
        if (abs(n - 7) <= l) {
            const float* dp = s_d2i0 + l * 225 + n;
            const float2* xp = s_xh2 + l * 225 + k;
            for (int m = 7 - l; m <= 7 + l; ++m) {
                float d = dp[m * 15];
                float2 v = xp[m * 15];
                ax += d * v.x;
                ay += d * v.y;
            }
        }
        gout[idx] = make_float2(ax, ay);
    }
}

// ------------------------- k_dot: warp-per-b, fl-loop (G L2 reuse) ---------
// Block (c, ft) = 256 blocks x 512 threads. Warp w = batch b = w (16 warps).
// All warps share each w2 slice (L1 broadcast); G chunk re-read 8x total.
__global__ __launch_bounds__(512) void k_dot(const float* __restrict__ w2r,
                                             const float* __restrict__ w2i) {
    int c  = blockIdx.x;      // 32
    int ft = blockIdx.y;      // 8
    int tid = threadIdx.x;    // 512
    int b = tid >> 5;         // warp = batch 0..15
    int lane = tid & 31;

    const float4* X4 = (const float4*)(g_G + ((size_t)b * 32 + c) * 1800);
#pragma unroll 2
    for (int fl = 0; fl < 8; ++fl) {
        int f = ft * 8 + fl;
        const float4* Wr4 = (const float4*)(w2r + ((size_t)c * 64 + f) * 1800);
        const float4* Wi4 = (const float4*)(w2i + ((size_t)c * 64 + f) * 1800);
        float acc = 0.f;
        for (int i = lane; i < 450; i += 32) {
            float4 g0 = X4[2 * i], g1 = X4[2 * i + 1];
            float4 wr = Wr4[i], wi = Wi4[i];
            acc += g0.x * wr.x + g0.y * wi.x + g0.z * wr.y + g0.w * wi.y
                 + g1.x * wr.z + g1.y * wi.z + g1.z * wr.w + g1.w * wi.w;
        }
#pragma unroll
        for (int o = 16; o > 0; o >>= 1)
            acc += __shfl_xor_sync(0xffffffffu, acc, o);
        if (lane == 0)
            g_partial[(c * 8 + ft) * 128 + b * 8 + fl] = acc;
    }
}

// ------------------------- head: reduce + conv1d + BN + FC -----------------
__global__ void k_head(const float* __restrict__ w3, const float* __restrict__ b3,
                       const float* __restrict__ gam, const float* __restrict__ bet,
                       const float* __restrict__ fcw, const float* __restrict__ fcb,
                       float* __restrict__ out) {
    __shared__ float s_feat[16 * 64];
    __shared__ float s_r3[16 * 570];
    __shared__ float s_mu[10], s_rstd[10];
    __shared__ float s_ps[160], s_ps2[160];
    int tid = threadIdx.x;    // 256

    for (int idx = tid; idx < 1024; idx += 256) {
        int b = idx >> 6;
        int f = idx & 63;
        int ft = f >> 3, fl = f & 7;
        float s = 0.f;
#pragma unroll
        for (int c = 0; c < 32; ++c)
            s += g_partial[(c * 8 + ft) * 128 + (b << 3) + fl];
        s_feat[b * 64 + f] = fmaxf(s, 0.f);
    }
    __syncthreads();

    for (int idx = tid; idx < 9120; idx += 256) {
        int b = idx / 570;
        int r = idx % 570;
        int o = r / 57, t = r % 57;
        float s = b3[o];
#pragma unroll
        for (int k = 0; k < 8; ++k)
            s += w3[o * 8 + k] * s_feat[b * 64 + t + k];
        s_r3[idx] = fmaxf(s, 0.f);
    }
    __syncthreads();

    if (tid < 160) {
        int o = tid >> 4, i = tid & 15;
        float s = 0.f, s2 = 0.f;
        for (int idx2 = i; idx2 < 912; idx2 += 16) {
            int b = idx2 / 57, t = idx2 % 57;
            float v = s_r3[b * 570 + o * 57 + t];
            s += v;
            s2 += v * v;
        }
        s_ps[tid] = s;
        s_ps2[tid] = s2;
    }
    __syncthreads();

    if (tid < 10) {
        float s = 0.f, s2 = 0.f;
#pragma unroll
        for (int i = 0; i < 16; ++i) {
            s += s_ps[tid * 16 + i];
            s2 += s_ps2[tid * 16 + i];
        }
        float mu = s / 912.f;
        float var = s2 / 912.f - mu * mu;
        s_mu[tid] = mu;
        s_rstd[tid] = rsqrtf(var + 1e-5f);
    }
    __syncthreads();

    for (int idx = tid; idx < 9120; idx += 256) {
        int o = (idx % 570) / 57;
        s_r3[idx] = gam[o] * (s_r3[idx] - s_mu[o]) * s_rstd[o] + bet[o];
    }
    __syncthreads();

    if (tid < 160) {
        int b = tid / 10, i = tid % 10;
        float s = fcb[i];
        const float* wr = fcw + i * 570;
        const float* xr = s_r3 + b * 570;
        for (int z = 0; z < 570; ++z) s += xr[z] * wr[z];
        out[b * 10 + i] = s;
    }
}

// ---------------------------------------------------------------------------
extern "C" void kernel_launch(void* const* d_in, const int* in_sizes, int n_in,
                              void* d_out, int out_size) {
    const float* x   = (const float*)d_in[0];
    const float* w1r = (const float*)d_in[1];
    const float* w1i = (const float*)d_in[2];
    const float* w2r = (const float*)d_in[3];
    const float* w2i = (const float*)d_in[4];
    const float* c3w = (const float*)d_in[5];
    const float* c3b = (const float*)d_in[6];
    const float* bng = (const float*)d_in[7];
    const float* bnb = (const float*)d_in[8];
    const float* fcw = (const float*)d_in[9];
    const float* fcb = (const float*)d_in[10];
    float* out = (float*)d_out;

    t_setup<<<1, 64>>>();
    t_tables<<<(599048 + 127) / 128, 128>>>();

    k_xh<<<16 * 31, 64>>>(x);
    k_main<<<8 * 32 * 32, 256>>>(w1r, w1i);
    k_G<<<512, 512>>>();
    k_dot<<<dim3(32, 8), 512>>>(w2r, w2i);
    k_head<<<1, 256>>>(c3w, c3b, bng, bnb, fcw, fcb, out);
}